// round 7
// baseline (speedup 1.0000x reference)
#include <cuda_runtime.h>
#include <cuda_bf16.h>
#include <math.h>
#include <cstdint>

#define BB 2
#define SS 4096
#define DM 768
#define NH 12
#define FF 3072
#define WIN 64
#define HD 64
#define NC (SS / WIN)
#define MROWS (BB * SS)    // 8192
#define QKVN (3 * DM)      // 2304
#define KVW (2 * DM)       // 1536 packed k|v width

// ================= helpers =================
__device__ __forceinline__ uint32_t smem_to_u32(const void* p) {
    uint32_t a;
    asm("{ .reg .u64 t; cvta.to.shared.u64 t, %1; cvt.u32.u64 %0, t; }" : "=r"(a) : "l"(p));
    return a;
}
#define SMEM_SWIZZLE_128B(o) ((o) ^ (((o) >> 3) & 0x70))

__device__ __forceinline__ void ldsm_x4(uint32_t r[4], uint32_t addr) {
    asm volatile("ldmatrix.sync.aligned.m8n8.x4.shared.b16 {%0,%1,%2,%3}, [%4];"
        : "=r"(r[0]), "=r"(r[1]), "=r"(r[2]), "=r"(r[3]) : "r"(addr));
}
__device__ __forceinline__ void ldsm_x4_trans(uint32_t r[4], uint32_t addr) {
    asm volatile("ldmatrix.sync.aligned.m8n8.x4.trans.shared.b16 {%0,%1,%2,%3}, [%4];"
        : "=r"(r[0]), "=r"(r[1]), "=r"(r[2]), "=r"(r[3]) : "r"(addr));
}
__device__ __forceinline__ void mma_bf16(float c[4], const uint32_t a[4],
                                         uint32_t b0, uint32_t b1) {
    asm volatile("mma.sync.aligned.m16n8k16.row.col.f32.bf16.bf16.f32 "
        "{%0,%1,%2,%3}, {%4,%5,%6,%7}, {%8,%9}, {%0,%1,%2,%3};"
        : "+f"(c[0]), "+f"(c[1]), "+f"(c[2]), "+f"(c[3])
        : "r"(a[0]), "r"(a[1]), "r"(a[2]), "r"(a[3]), "r"(b0), "r"(b1));
}
__device__ __forceinline__ void split_bf16(float v, __nv_bfloat16& h, __nv_bfloat16& l) {
    h = __float2bfloat16(v);
    l = __float2bfloat16(v - __bfloat162float(h));
}
__device__ __forceinline__ uint32_t pack_hi(float x, float y) {
    __nv_bfloat162 t(__float2bfloat16(x), __float2bfloat16(y));
    return *reinterpret_cast<uint32_t*>(&t);
}
__device__ __forceinline__ uint32_t pack_lo(float x, float y) {
    __nv_bfloat16 hx = __float2bfloat16(x), hy = __float2bfloat16(y);
    __nv_bfloat162 t(__float2bfloat16(x - __bfloat162float(hx)),
                     __float2bfloat16(y - __bfloat162float(hy)));
    return *reinterpret_cast<uint32_t*>(&t);
}
__device__ __forceinline__ float gelu_tanh(float x) {
    const float c = 0.7978845608028654f;
    float x3 = x * x * x;
    return 0.5f * x * (1.0f + tanhf(c * (x + 0.044715f * x3)));
}

// ================= scratch =================
__device__ float g_qf[MROWS * DM];
__device__ float g_attn[MROWS * DM];
__device__ float g_x1[MROWS * DM];
__device__ float g_ff[MROWS * DM];
__device__ float g_bqkv[QKVN];
__device__ __nv_bfloat16 g_kvh[MROWS * KVW], g_kvl[MROWS * KVW];
__device__ __nv_bfloat16 g_xh[MROWS * DM],  g_xl[MROWS * DM];
__device__ __nv_bfloat16 g_x1h[MROWS * DM], g_x1l[MROWS * DM];
__device__ __nv_bfloat16 g_hidh[MROWS * FF], g_hidl[MROWS * FF];
__device__ __nv_bfloat16 g_wqkvh[QKVN * DM], g_wqkvl[QKVN * DM];
__device__ __nv_bfloat16 g_w1h[FF * DM], g_w1l[FF * DM];
__device__ __nv_bfloat16 g_w2h[DM * FF], g_w2l[DM * FF];

// ========== elementwise fp32 -> bf16 hi/lo ==========
__global__ void split_convert(const float* __restrict__ in,
                              __nv_bfloat16* __restrict__ hi,
                              __nv_bfloat16* __restrict__ lo, int n4) {
    int i = blockIdx.x * blockDim.x + threadIdx.x;
    if (i >= n4) return;
    float4 v = reinterpret_cast<const float4*>(in)[i];
    __nv_bfloat16 h0,l0,h1,l1,h2,l2,h3,l3;
    split_bf16(v.x, h0, l0); split_bf16(v.y, h1, l1);
    split_bf16(v.z, h2, l2); split_bf16(v.w, h3, l3);
    reinterpret_cast<__nv_bfloat162*>(hi)[i*2+0] = __nv_bfloat162(h0, h1);
    reinterpret_cast<__nv_bfloat162*>(hi)[i*2+1] = __nv_bfloat162(h2, h3);
    reinterpret_cast<__nv_bfloat162*>(lo)[i*2+0] = __nv_bfloat162(l0, l1);
    reinterpret_cast<__nv_bfloat162*>(lo)[i*2+1] = __nv_bfloat162(l2, l3);
}

// ========== merged weight transpose+split + bias pack (one launch) ==========
// tiles: [0,576) Wq  [576,1152) Wk  [1152,1728) Wv  [1728,4032) W1  [4032,6336) W2
// [6336,6345): bias pack (9 blocks x 256 threads = 2304)
__global__ void prep_weights(const float* __restrict__ Wq, const float* __restrict__ Wk,
                             const float* __restrict__ Wv, const float* __restrict__ W1,
                             const float* __restrict__ W2,
                             const float* __restrict__ bq, const float* __restrict__ bk,
                             const float* __restrict__ bv,
                             __nv_bfloat16* __restrict__ wqkvh, __nv_bfloat16* __restrict__ wqkvl,
                             __nv_bfloat16* __restrict__ w1h, __nv_bfloat16* __restrict__ w1l,
                             __nv_bfloat16* __restrict__ w2h, __nv_bfloat16* __restrict__ w2l,
                             float* __restrict__ bqkv) {
    int id = blockIdx.x;
    if (id >= 6336) {
        int i = (id - 6336) * 256 + threadIdx.x;
        if (i < QKVN)
            bqkv[i] = (i < DM) ? bq[i] : (i < 2 * DM) ? bk[i - DM] : bv[i - 2 * DM];
        return;
    }
    const float* W; __nv_bfloat16 *Th, *Tl; int K, N, tix;
    if (id < 576)       { W = Wq; Th = wqkvh;              Tl = wqkvl;              K = DM; N = DM; tix = id; }
    else if (id < 1152) { W = Wk; Th = wqkvh + DM * DM;    Tl = wqkvl + DM * DM;    K = DM; N = DM; tix = id - 576; }
    else if (id < 1728) { W = Wv; Th = wqkvh + 2 * DM * DM; Tl = wqkvl + 2 * DM * DM; K = DM; N = DM; tix = id - 1152; }
    else if (id < 4032) { W = W1; Th = w1h;                Tl = w1l;                K = DM; N = FF; tix = id - 1728; }
    else                { W = W2; Th = w2h;                Tl = w2l;                K = FF; N = DM; tix = id - 4032; }
    int nt = N / 32;
    int n0 = (tix % nt) * 32, k0 = (tix / nt) * 32;
    __shared__ float t[32][33];
    int tx = threadIdx.x & 31, ty = threadIdx.x >> 5;   // 32 x 8
    #pragma unroll
    for (int i = 0; i < 4; i++)
        t[ty + i*8][tx] = W[(size_t)(k0 + ty + i*8) * N + n0 + tx];
    __syncthreads();
    #pragma unroll
    for (int i = 0; i < 4; i++) {
        float v = t[tx][ty + i*8];
        __nv_bfloat16 h, l; split_bf16(v, h, l);
        size_t o = (size_t)(n0 + ty + i*8) * K + k0 + tx;
        Th[o] = h; Tl[o] = l;
    }
}

// ========== HMMA GEMM: C[M,N] = A[M,K] @ Bt[N,K]^T + bias ==========
// 3xBF16 split, fp32 accumulate. CTA 128x128, 8 warps 32x64.
// K-block = 32; smem row = [32 hi | 32 lo] bf16 = 128B (SW128 swizzle intact).
// Stage = A(16KB) + B(16KB) = 32KB; 3 stages = 96KB -> 2 CTAs/SM.
// mode 0: fp32 out. mode 1: gelu + hi/lo out. mode 2: QKV (q fp32*0.125, k/v hi/lo).
#define STAGE_BYTES 32768
#define GEMM_SMEM (3 * STAGE_BYTES)
__global__ void __launch_bounds__(256, 2)
tc_gemm(const __nv_bfloat16* __restrict__ Ah, const __nv_bfloat16* __restrict__ Al,
        const __nv_bfloat16* __restrict__ Bh, const __nv_bfloat16* __restrict__ Bl,
        const float* __restrict__ bias,
        float* __restrict__ outF,
        __nv_bfloat16* __restrict__ outHi, __nv_bfloat16* __restrict__ outLo,
        int M, int N, int K, int mode) {
    extern __shared__ char smem[];
    const uint32_t tiles = smem_to_u32(smem);
    const int tid = threadIdx.x;
    const int wid = tid >> 5;
    const int lane = tid & 31;
    const int warpM = wid >> 1;
    const int warpN = wid & 1;
    const int bm = blockIdx.y * 128;
    const int bn = blockIdx.x * 128;
    const int NB = K >> 5;             // K-blocks of 32

    auto stage = [&](int kb, int s) {
        #pragma unroll
        for (int t = 0; t < 2; t++) {
            const __nv_bfloat16* shi = t ? Bh : Ah;
            const __nv_bfloat16* slo = t ? Bl : Al;
            const int rbase = t ? bn : bm;
            const uint32_t sb = tiles + (uint32_t)s * STAGE_BYTES + (uint32_t)t * 16384u;
            #pragma unroll
            for (int i = 0; i < 4; i++) {
                int chunk = tid + i * 256;        // 0..1023
                int row = chunk >> 3;
                int c = chunk & 7;                // 0..3 hi, 4..7 lo
                const __nv_bfloat16* src = (c < 4) ? shi : slo;
                uint32_t off = (uint32_t)(row * 128 + c * 16);
                uint32_t dst = sb + SMEM_SWIZZLE_128B(off);
                const void* g = src + (size_t)(rbase + row) * K + kb * 32 + (c & 3) * 8;
                asm volatile("cp.async.cg.shared.global [%0], [%1], 16;" :: "r"(dst), "l"(g));
            }
        }
        asm volatile("cp.async.commit_group;" ::: "memory");
    };

    float c[2][8][4] = {};

    stage(0, 0);
    if (NB > 1) stage(1, 1);

    const int lrow = lane & 15;
    const int lchunk = lane >> 4;

    for (int kb = 0; kb < NB; kb++) {
        const int s = kb % 3;
        if (kb + 1 < NB) asm volatile("cp.async.wait_group 1;" ::: "memory");
        else             asm volatile("cp.async.wait_group 0;" ::: "memory");
        __syncthreads();
        if (kb + 2 < NB) stage(kb + 2, (kb + 2) % 3);

        const uint32_t baseA = tiles + (uint32_t)s * STAGE_BYTES;
        const uint32_t baseB = baseA + 16384u;
        #pragma unroll
        for (int ks = 0; ks < 2; ks++) {
            const uint32_t colH = (uint32_t)(ks * 32 + lchunk * 16);
            uint32_t ah[2][4], al2[2][4];
            #pragma unroll
            for (int mt = 0; mt < 2; mt++) {
                uint32_t rowb = (uint32_t)((warpM * 32 + mt * 16 + lrow) * 128);
                ldsm_x4(ah[mt],  baseA + SMEM_SWIZZLE_128B(rowb + colH));
                ldsm_x4(al2[mt], baseA + SMEM_SWIZZLE_128B(rowb + 64u + colH));
            }
            #pragma unroll
            for (int np = 0; np < 4; np++) {
                uint32_t rowb = (uint32_t)((warpN * 64 + np * 16 + lrow) * 128);
                uint32_t bh[4], bl[4];
                ldsm_x4(bh, baseB + SMEM_SWIZZLE_128B(rowb + colH));
                ldsm_x4(bl, baseB + SMEM_SWIZZLE_128B(rowb + 64u + colH));
                #pragma unroll
                for (int mt = 0; mt < 2; mt++) {
                    mma_bf16(c[mt][2*np],   ah[mt],  bh[0], bh[2]);
                    mma_bf16(c[mt][2*np+1], ah[mt],  bh[1], bh[3]);
                    mma_bf16(c[mt][2*np],   ah[mt],  bl[0], bl[2]);
                    mma_bf16(c[mt][2*np+1], ah[mt],  bl[1], bl[3]);
                    mma_bf16(c[mt][2*np],   al2[mt], bh[0], bh[2]);
                    mma_bf16(c[mt][2*np+1], al2[mt], bh[1], bh[3]);
                }
            }
        }
    }
    __syncthreads();

    // epilogue: regs -> smem (padded) -> coalesced global (66KB < 96KB)
    float* sD = reinterpret_cast<float*>(smem);   // 128 x 129
    #pragma unroll
    for (int mt = 0; mt < 2; mt++) {
        #pragma unroll
        for (int nt = 0; nt < 8; nt++) {
            int r0 = warpM * 32 + mt * 16 + (lane >> 2);
            int col = warpN * 64 + nt * 8 + (lane & 3) * 2;
            sD[r0 * 129 + col]           = c[mt][nt][0];
            sD[r0 * 129 + col + 1]       = c[mt][nt][1];
            sD[(r0 + 8) * 129 + col]     = c[mt][nt][2];
            sD[(r0 + 8) * 129 + col + 1] = c[mt][nt][3];
        }
    }
    __syncthreads();

    for (int idx = tid; idx < 128 * 128; idx += 256) {
        int r = idx >> 7, cc = idx & 127;
        float v = sD[r * 129 + cc] + bias[bn + cc];
        size_t row = (size_t)(bm + r);
        int gc = bn + cc;
        if (mode == 0) {
            outF[row * N + gc] = v;
        } else if (mode == 1) {
            v = gelu_tanh(v);
            __nv_bfloat16 h, l; split_bf16(v, h, l);
            outHi[row * N + gc] = h;
            outLo[row * N + gc] = l;
        } else {
            if (gc < DM) {
                outF[row * DM + gc] = v * 0.125f;   // q, pre-scaled
            } else {
                __nv_bfloat16 h, l; split_bf16(v, h, l);
                size_t o = row * KVW + (gc - DM);
                outHi[o] = h; outLo[o] = l;
            }
        }
    }
}

// ================= HMMA sliding-window attention (unchanged from R6) =================
#define AQH 0
#define AQL 8192
#define AKH 16384
#define AKL 40960
#define AVH 65536
#define AVL 90112
#define ATTN_SMEM 114688
__global__ void __launch_bounds__(128, 1)
attn_kernel(const float* __restrict__ qf,
            const __nv_bfloat16* __restrict__ kvh,
            const __nv_bfloat16* __restrict__ kvl,
            float* __restrict__ out) {
    extern __shared__ char smem[];
    const uint32_t sb = smem_to_u32(smem);
    const int c = blockIdx.x, h = blockIdx.y, b = blockIdx.z;
    const int tid = threadIdx.x, warp = tid >> 5, lane = tid & 31;

    for (int idx = tid; idx < 64 * 16; idx += 128) {
        int r = idx >> 4, ch = idx & 15;
        float4 v = *reinterpret_cast<const float4*>(
            &qf[((size_t)b * SS + c * 64 + r) * DM + h * HD + ch * 4]);
        uint32_t off = SMEM_SWIZZLE_128B((uint32_t)(r * 128 + ch * 8));
        uint2 hh, ll;
        hh.x = pack_hi(v.x, v.y); hh.y = pack_hi(v.z, v.w);
        ll.x = pack_lo(v.x, v.y); ll.y = pack_lo(v.z, v.w);
        *reinterpret_cast<uint2*>(smem + AQH + off) = hh;
        *reinterpret_cast<uint2*>(smem + AQL + off) = ll;
    }
    for (int idx = tid; idx < 192 * 8; idx += 128) {
        int j = idx >> 3, ch = idx & 7;
        int g = c * 64 - 64 + j;
        uint4 z = {0, 0, 0, 0};
        uint4 kh4 = z, kl4 = z, vh4 = z, vl4 = z;
        if (g >= 0 && g < SS) {
            size_t rb = ((size_t)b * SS + g) * KVW + h * HD + ch * 8;
            kh4 = *reinterpret_cast<const uint4*>(&kvh[rb]);
            kl4 = *reinterpret_cast<const uint4*>(&kvl[rb]);
            vh4 = *reinterpret_cast<const uint4*>(&kvh[rb + DM]);
            vl4 = *reinterpret_cast<const uint4*>(&kvl[rb + DM]);
        }
        uint32_t off = SMEM_SWIZZLE_128B((uint32_t)(j * 128 + ch * 16));
        *reinterpret_cast<uint4*>(smem + AKH + off) = kh4;
        *reinterpret_cast<uint4*>(smem + AKL + off) = kl4;
        *reinterpret_cast<uint4*>(smem + AVH + off) = vh4;
        *reinterpret_cast<uint4*>(smem + AVL + off) = vl4;
    }
    __syncthreads();

    const int m0 = warp * 16;
    const int lrow = lane & 15;
    const int lch = lane >> 4;

    float s[24][4];
    #pragma unroll
    for (int nt = 0; nt < 24; nt++)
        #pragma unroll
        for (int u = 0; u < 4; u++) s[nt][u] = 0.f;

    #pragma unroll
    for (int ks = 0; ks < 4; ks++) {
        uint32_t aoff = SMEM_SWIZZLE_128B((uint32_t)((m0 + lrow) * 128 + ks * 32 + lch * 16));
        uint32_t ah[4], al[4];
        ldsm_x4(ah, sb + AQH + aoff);
        ldsm_x4(al, sb + AQL + aoff);
        #pragma unroll
        for (int n6 = 0; n6 < 12; n6++) {
            uint32_t boff = SMEM_SWIZZLE_128B((uint32_t)((n6 * 16 + lrow) * 128 + ks * 32 + lch * 16));
            uint32_t bh[4], bl[4];
            ldsm_x4(bh, sb + AKH + boff);
            ldsm_x4(bl, sb + AKL + boff);
            mma_bf16(s[2*n6],   ah, bh[0], bh[2]);
            mma_bf16(s[2*n6+1], ah, bh[1], bh[3]);
            mma_bf16(s[2*n6],   ah, bl[0], bl[2]);
            mma_bf16(s[2*n6+1], ah, bl[1], bl[3]);
            mma_bf16(s[2*n6],   al, bh[0], bh[2]);
            mma_bf16(s[2*n6+1], al, bh[1], bh[3]);
        }
    }

    const int rA = m0 + (lane >> 2);
    const int rB = rA + 8;
    const int jb = 2 * (lane & 3);
    const int gof = c * 64 - 64;
    float mA = -INFINITY, mB = -INFINITY;
    #pragma unroll
    for (int nt = 0; nt < 24; nt++) {
        int j0 = nt * 8 + jb, j1 = j0 + 1;
        int g0 = gof + j0, g1 = gof + j1;
        bool in0 = (g0 >= 0) && (g0 < SS);
        bool in1 = (g1 >= 0) && (g1 < SS);
        if (!((j0 >= rA) && (j0 <= rA + 128) && in0)) s[nt][0] = -INFINITY;
        if (!((j1 >= rA) && (j1 <= rA + 128) && in1)) s[nt][1] = -INFINITY;
        if (!((j0 >= rB) && (j0 <= rB + 128) && in0)) s[nt][2] = -INFINITY;
        if (!((j1 >= rB) && (j1 <= rB + 128) && in1)) s[nt][3] = -INFINITY;
        mA = fmaxf(mA, fmaxf(s[nt][0], s[nt][1]));
        mB = fmaxf(mB, fmaxf(s[nt][2], s[nt][3]));
    }
    mA = fmaxf(mA, __shfl_xor_sync(0xffffffffu, mA, 1));
    mA = fmaxf(mA, __shfl_xor_sync(0xffffffffu, mA, 2));
    mB = fmaxf(mB, __shfl_xor_sync(0xffffffffu, mB, 1));
    mB = fmaxf(mB, __shfl_xor_sync(0xffffffffu, mB, 2));
    float sA = 0.f, sB = 0.f;
    #pragma unroll
    for (int nt = 0; nt < 24; nt++) {
        s[nt][0] = __expf(s[nt][0] - mA);
        s[nt][1] = __expf(s[nt][1] - mA);
        s[nt][2] = __expf(s[nt][2] - mB);
        s[nt][3] = __expf(s[nt][3] - mB);
        sA += s[nt][0] + s[nt][1];
        sB += s[nt][2] + s[nt][3];
    }
    sA += __shfl_xor_sync(0xffffffffu, sA, 1);
    sA += __shfl_xor_sync(0xffffffffu, sA, 2);
    sB += __shfl_xor_sync(0xffffffffu, sB, 1);
    sB += __shfl_xor_sync(0xffffffffu, sB, 2);
    const float invA = 1.0f / sA, invB = 1.0f / sB;

    float o[8][4];
    #pragma unroll
    for (int nt = 0; nt < 8; nt++)
        #pragma unroll
        for (int u = 0; u < 4; u++) o[nt][u] = 0.f;

    #pragma unroll
    for (int t = 0; t < 12; t++) {
        uint32_t ph[4], pl[4];
        ph[0] = pack_hi(s[2*t][0],   s[2*t][1]);
        ph[1] = pack_hi(s[2*t][2],   s[2*t][3]);
        ph[2] = pack_hi(s[2*t+1][0], s[2*t+1][1]);
        ph[3] = pack_hi(s[2*t+1][2], s[2*t+1][3]);
        pl[0] = pack_lo(s[2*t][0],   s[2*t][1]);
        pl[1] = pack_lo(s[2*t][2],   s[2*t][3]);
        pl[2] = pack_lo(s[2*t+1][0], s[2*t+1][1]);
        pl[3] = pack_lo(s[2*t+1][2], s[2*t+1][3]);
        #pragma unroll
        for (int nn = 0; nn < 4; nn++) {
            uint32_t voff = SMEM_SWIZZLE_128B(
                (uint32_t)((t * 16 + (lane & 15)) * 128 + (nn * 16 + (lane >> 4) * 8) * 2));
            uint32_t vh[4], vl[4];
            ldsm_x4_trans(vh, sb + AVH + voff);
            ldsm_x4_trans(vl, sb + AVL + voff);
            mma_bf16(o[2*nn],   ph, vh[0], vh[1]);
            mma_bf16(o[2*nn+1], ph, vh[2], vh[3]);
            mma_bf16(o[2*nn],   ph, vl[0], vl[1]);
            mma_bf16(o[2*nn+1], ph, vl[2], vl[3]);
            mma_bf16(o[2*nn],   pl, vh[0], vh[1]);
            mma_bf16(o[2*nn+1], pl, vh[2], vh[3]);
        }
    }

    const size_t rowg = (size_t)b * SS + c * 64;
    #pragma unroll
    for (int nt = 0; nt < 8; nt++) {
        int col = h * HD + nt * 8 + jb;
        float2 v0 = make_float2(o[nt][0] * invA, o[nt][1] * invA);
        float2 v1 = make_float2(o[nt][2] * invB, o[nt][3] * invB);
        *reinterpret_cast<float2*>(&out[(rowg + rA) * DM + col]) = v0;
        *reinterpret_cast<float2*>(&out[(rowg + rB) * DM + col]) = v1;
    }
}

// ================= warp-per-row residual + LayerNorm =================
__global__ void __launch_bounds__(256)
add_ln_kernel(const float* __restrict__ a,
              const float* __restrict__ r,
              const float* __restrict__ g,
              const float* __restrict__ beta,
              float* __restrict__ out,
              __nv_bfloat16* __restrict__ outHi,
              __nv_bfloat16* __restrict__ outLo) {
    const int warp = threadIdx.x >> 5, lane = threadIdx.x & 31;
    const int row = blockIdx.x * 8 + warp;
    const float4* pa = reinterpret_cast<const float4*>(a + (size_t)row * DM);
    const float4* pr = reinterpret_cast<const float4*>(r + (size_t)row * DM);
    const float4* pg = reinterpret_cast<const float4*>(g);
    const float4* pb = reinterpret_cast<const float4*>(beta);

    float4 v[6];
    float sum = 0.f;
    #pragma unroll
    for (int ch = 0; ch < 6; ch++) {
        float4 va = pa[lane + 32 * ch];
        float4 vr = pr[lane + 32 * ch];
        v[ch] = make_float4(va.x + vr.x, va.y + vr.y, va.z + vr.z, va.w + vr.w);
        sum += v[ch].x + v[ch].y + v[ch].z + v[ch].w;
    }
    #pragma unroll
    for (int o = 16; o > 0; o >>= 1) sum += __shfl_xor_sync(0xffffffffu, sum, o);
    float mu = sum * (1.0f / DM);

    float var = 0.f;
    #pragma unroll
    for (int ch = 0; ch < 6; ch++) {
        float dx = v[ch].x - mu, dy = v[ch].y - mu, dz = v[ch].z - mu, dw = v[ch].w - mu;
        var += dx * dx + dy * dy + dz * dz + dw * dw;
    }
    #pragma unroll
    for (int o = 16; o > 0; o >>= 1) var += __shfl_xor_sync(0xffffffffu, var, o);
    float rstd = rsqrtf(var * (1.0f / DM) + 1e-5f);

    float4* po = reinterpret_cast<float4*>(out + (size_t)row * DM);
    #pragma unroll
    for (int ch = 0; ch < 6; ch++) {
        float4 gg = pg[lane + 32 * ch];
        float4 bb = pb[lane + 32 * ch];
        float4 y;
        y.x = (v[ch].x - mu) * rstd * gg.x + bb.x;
        y.y = (v[ch].y - mu) * rstd * gg.y + bb.y;
        y.z = (v[ch].z - mu) * rstd * gg.z + bb.z;
        y.w = (v[ch].w - mu) * rstd * gg.w + bb.w;
        po[lane + 32 * ch] = y;
        if (outHi) {
            size_t o4 = (size_t)row * DM + (lane + 32 * ch) * 4;
            __nv_bfloat16 h0,l0,h1,l1,h2,l2,h3,l3;
            split_bf16(y.x, h0, l0); split_bf16(y.y, h1, l1);
            split_bf16(y.z, h2, l2); split_bf16(y.w, h3, l3);
            reinterpret_cast<__nv_bfloat162*>(outHi + o4)[0] = __nv_bfloat162(h0, h1);
            reinterpret_cast<__nv_bfloat162*>(outHi + o4)[1] = __nv_bfloat162(h2, h3);
            reinterpret_cast<__nv_bfloat162*>(outLo + o4)[0] = __nv_bfloat162(l0, l1);
            reinterpret_cast<__nv_bfloat162*>(outLo + o4)[1] = __nv_bfloat162(l2, l3);
        }
    }
}

// ================= launch =================
extern "C" void kernel_launch(void* const* d_in, const int* in_sizes, int n_in,
                              void* d_out, int out_size) {
    const float* x     = (const float*)d_in[0];
    const float* Wq    = (const float*)d_in[1];
    const float* bq    = (const float*)d_in[2];
    const float* Wk    = (const float*)d_in[3];
    const float* bk    = (const float*)d_in[4];
    const float* Wv    = (const float*)d_in[5];
    const float* bv    = (const float*)d_in[6];
    const float* ln1_g = (const float*)d_in[7];
    const float* ln1_b = (const float*)d_in[8];
    const float* W1    = (const float*)d_in[9];
    const float* b1    = (const float*)d_in[10];
    const float* W2    = (const float*)d_in[11];
    const float* b2    = (const float*)d_in[12];
    const float* ln2_g = (const float*)d_in[13];
    const float* ln2_b = (const float*)d_in[14];
    float* out = (float*)d_out;

    float *qf, *attn, *x1, *ff, *bqkv;
    __nv_bfloat16 *kvh, *kvl, *xh, *xl, *x1h, *x1l, *hidh, *hidl;
    __nv_bfloat16 *wqkvh, *wqkvl, *w1h, *w1l, *w2h, *w2l;
    cudaGetSymbolAddress((void**)&qf, g_qf);     cudaGetSymbolAddress((void**)&attn, g_attn);
    cudaGetSymbolAddress((void**)&x1, g_x1);     cudaGetSymbolAddress((void**)&ff, g_ff);
    cudaGetSymbolAddress((void**)&bqkv, g_bqkv);
    cudaGetSymbolAddress((void**)&kvh, g_kvh);   cudaGetSymbolAddress((void**)&kvl, g_kvl);
    cudaGetSymbolAddress((void**)&xh, g_xh);     cudaGetSymbolAddress((void**)&xl, g_xl);
    cudaGetSymbolAddress((void**)&x1h, g_x1h);   cudaGetSymbolAddress((void**)&x1l, g_x1l);
    cudaGetSymbolAddress((void**)&hidh, g_hidh); cudaGetSymbolAddress((void**)&hidl, g_hidl);
    cudaGetSymbolAddress((void**)&wqkvh, g_wqkvh); cudaGetSymbolAddress((void**)&wqkvl, g_wqkvl);
    cudaGetSymbolAddress((void**)&w1h, g_w1h);   cudaGetSymbolAddress((void**)&w1l, g_w1l);
    cudaGetSymbolAddress((void**)&w2h, g_w2h);   cudaGetSymbolAddress((void**)&w2l, g_w2l);

    cudaFuncSetAttribute(tc_gemm, cudaFuncAttributeMaxDynamicSharedMemorySize, GEMM_SMEM);
    cudaFuncSetAttribute(attn_kernel, cudaFuncAttributeMaxDynamicSharedMemorySize, ATTN_SMEM);

    // ---- convert inputs (merged weight prep) ----
    {
        int n4 = MROWS * DM / 4;
        split_convert<<<(n4 + 255) / 256, 256>>>(x, xh, xl, n4);
        prep_weights<<<6345, 256>>>(Wq, Wk, Wv, W1, W2, bq, bk, bv,
                                    wqkvh, wqkvl, w1h, w1l, w2h, w2l, bqkv);
    }

    // ---- fused QKV projection: q fp32 (scaled), k/v bf16 hi/lo ----
    {
        dim3 grid(QKVN / 128, MROWS / 128);
        tc_gemm<<<grid, 256, GEMM_SMEM>>>(xh, xl, wqkvh, wqkvl, bqkv, qf,
                                          kvh, kvl, MROWS, QKVN, DM, 2);
    }

    // ---- attention (HMMA) ----
    {
        dim3 grid(NC, NH, BB);
        attn_kernel<<<grid, 128, ATTN_SMEM>>>(qf, kvh, kvl, attn);
    }

    // ---- x1 = LN(attn + x), emit bf16 hi/lo ----
    add_ln_kernel<<<MROWS / 8, 256>>>(attn, x, ln1_g, ln1_b, x1, x1h, x1l);

    // ---- FFN ----
    {
        dim3 grid1(FF / 128, MROWS / 128);
        tc_gemm<<<grid1, 256, GEMM_SMEM>>>(x1h, x1l, w1h, w1l, b1, nullptr,
                                           hidh, hidl, MROWS, FF, DM, 1);
        dim3 grid2(DM / 128, MROWS / 128);
        tc_gemm<<<grid2, 256, GEMM_SMEM>>>(hidh, hidl, w2h, w2l, b2, ff,
                                           nullptr, nullptr, MROWS, DM, FF, 0);
    }

    // ---- out = LN(ff + x1) ----
    add_ln_kernel<<<MROWS / 8, 256>>>(ff, x1, ln2_g, ln2_b, out, nullptr, nullptr);
}

// round 8
// speedup vs baseline: 1.0118x; 1.0118x over previous
#include <cuda_runtime.h>
#include <cuda_bf16.h>
#include <math.h>
#include <cstdint>

#define BB 2
#define SS 4096
#define DM 768
#define NH 12
#define FF 3072
#define WIN 64
#define HD 64
#define NC (SS / WIN)
#define MROWS (BB * SS)    // 8192
#define QKVN (3 * DM)      // 2304
#define KVW (2 * DM)       // 1536 packed k|v width

// ================= helpers =================
__device__ __forceinline__ uint32_t smem_to_u32(const void* p) {
    uint32_t a;
    asm("{ .reg .u64 t; cvta.to.shared.u64 t, %1; cvt.u32.u64 %0, t; }" : "=r"(a) : "l"(p));
    return a;
}
#define SMEM_SWIZZLE_128B(o) ((o) ^ (((o) >> 3) & 0x70))

__device__ __forceinline__ void ldsm_x4(uint32_t r[4], uint32_t addr) {
    asm volatile("ldmatrix.sync.aligned.m8n8.x4.shared.b16 {%0,%1,%2,%3}, [%4];"
        : "=r"(r[0]), "=r"(r[1]), "=r"(r[2]), "=r"(r[3]) : "r"(addr));
}
__device__ __forceinline__ void ldsm_x4_trans(uint32_t r[4], uint32_t addr) {
    asm volatile("ldmatrix.sync.aligned.m8n8.x4.trans.shared.b16 {%0,%1,%2,%3}, [%4];"
        : "=r"(r[0]), "=r"(r[1]), "=r"(r[2]), "=r"(r[3]) : "r"(addr));
}
__device__ __forceinline__ void mma_bf16(float c[4], const uint32_t a[4],
                                         uint32_t b0, uint32_t b1) {
    asm volatile("mma.sync.aligned.m16n8k16.row.col.f32.bf16.bf16.f32 "
        "{%0,%1,%2,%3}, {%4,%5,%6,%7}, {%8,%9}, {%0,%1,%2,%3};"
        : "+f"(c[0]), "+f"(c[1]), "+f"(c[2]), "+f"(c[3])
        : "r"(a[0]), "r"(a[1]), "r"(a[2]), "r"(a[3]), "r"(b0), "r"(b1));
}
__device__ __forceinline__ void split_bf16(float v, __nv_bfloat16& h, __nv_bfloat16& l) {
    h = __float2bfloat16(v);
    l = __float2bfloat16(v - __bfloat162float(h));
}
__device__ __forceinline__ uint32_t pack_hi(float x, float y) {
    __nv_bfloat162 t(__float2bfloat16(x), __float2bfloat16(y));
    return *reinterpret_cast<uint32_t*>(&t);
}
__device__ __forceinline__ uint32_t pack_lo(float x, float y) {
    __nv_bfloat16 hx = __float2bfloat16(x), hy = __float2bfloat16(y);
    __nv_bfloat162 t(__float2bfloat16(x - __bfloat162float(hx)),
                     __float2bfloat16(y - __bfloat162float(hy)));
    return *reinterpret_cast<uint32_t*>(&t);
}
__device__ __forceinline__ float gelu_tanh(float x) {
    const float c = 0.7978845608028654f;
    float x3 = x * x * x;
    return 0.5f * x * (1.0f + tanhf(c * (x + 0.044715f * x3)));
}

// ================= scratch =================
__device__ float g_qf[MROWS * DM];
__device__ float g_attn[MROWS * DM];
__device__ float g_x1[MROWS * DM];
__device__ float g_ff[MROWS * DM];
__device__ float g_bqkv[QKVN];
__device__ __nv_bfloat16 g_kvh[MROWS * KVW], g_kvl[MROWS * KVW];
__device__ __nv_bfloat16 g_xh[MROWS * DM],  g_xl[MROWS * DM];
__device__ __nv_bfloat16 g_x1h[MROWS * DM], g_x1l[MROWS * DM];
__device__ __nv_bfloat16 g_hidh[MROWS * FF], g_hidl[MROWS * FF];
__device__ __nv_bfloat16 g_wqkvh[QKVN * DM], g_wqkvl[QKVN * DM];
__device__ __nv_bfloat16 g_w1h[FF * DM], g_w1l[FF * DM];
__device__ __nv_bfloat16 g_w2h[DM * FF], g_w2l[DM * FF];

// ========== elementwise fp32 -> bf16 hi/lo ==========
__global__ void split_convert(const float* __restrict__ in,
                              __nv_bfloat16* __restrict__ hi,
                              __nv_bfloat16* __restrict__ lo, int n4) {
    int i = blockIdx.x * blockDim.x + threadIdx.x;
    if (i >= n4) return;
    float4 v = reinterpret_cast<const float4*>(in)[i];
    __nv_bfloat16 h0,l0,h1,l1,h2,l2,h3,l3;
    split_bf16(v.x, h0, l0); split_bf16(v.y, h1, l1);
    split_bf16(v.z, h2, l2); split_bf16(v.w, h3, l3);
    reinterpret_cast<__nv_bfloat162*>(hi)[i*2+0] = __nv_bfloat162(h0, h1);
    reinterpret_cast<__nv_bfloat162*>(hi)[i*2+1] = __nv_bfloat162(h2, h3);
    reinterpret_cast<__nv_bfloat162*>(lo)[i*2+0] = __nv_bfloat162(l0, l1);
    reinterpret_cast<__nv_bfloat162*>(lo)[i*2+1] = __nv_bfloat162(l2, l3);
}

// ========== merged weight transpose+split + bias pack (one launch) ==========
__global__ void prep_weights(const float* __restrict__ Wq, const float* __restrict__ Wk,
                             const float* __restrict__ Wv, const float* __restrict__ W1,
                             const float* __restrict__ W2,
                             const float* __restrict__ bq, const float* __restrict__ bk,
                             const float* __restrict__ bv,
                             __nv_bfloat16* __restrict__ wqkvh, __nv_bfloat16* __restrict__ wqkvl,
                             __nv_bfloat16* __restrict__ w1h, __nv_bfloat16* __restrict__ w1l,
                             __nv_bfloat16* __restrict__ w2h, __nv_bfloat16* __restrict__ w2l,
                             float* __restrict__ bqkv) {
    int id = blockIdx.x;
    if (id >= 6336) {
        int i = (id - 6336) * 256 + threadIdx.x;
        if (i < QKVN)
            bqkv[i] = (i < DM) ? bq[i] : (i < 2 * DM) ? bk[i - DM] : bv[i - 2 * DM];
        return;
    }
    const float* W; __nv_bfloat16 *Th, *Tl; int K, N, tix;
    if (id < 576)       { W = Wq; Th = wqkvh;               Tl = wqkvl;               K = DM; N = DM; tix = id; }
    else if (id < 1152) { W = Wk; Th = wqkvh + DM * DM;     Tl = wqkvl + DM * DM;     K = DM; N = DM; tix = id - 576; }
    else if (id < 1728) { W = Wv; Th = wqkvh + 2 * DM * DM; Tl = wqkvl + 2 * DM * DM; K = DM; N = DM; tix = id - 1152; }
    else if (id < 4032) { W = W1; Th = w1h;                 Tl = w1l;                 K = DM; N = FF; tix = id - 1728; }
    else                { W = W2; Th = w2h;                 Tl = w2l;                 K = FF; N = DM; tix = id - 4032; }
    int nt = N / 32;
    int n0 = (tix % nt) * 32, k0 = (tix / nt) * 32;
    __shared__ float t[32][33];
    int tx = threadIdx.x & 31, ty = threadIdx.x >> 5;   // 32 x 8
    #pragma unroll
    for (int i = 0; i < 4; i++)
        t[ty + i*8][tx] = W[(size_t)(k0 + ty + i*8) * N + n0 + tx];
    __syncthreads();
    #pragma unroll
    for (int i = 0; i < 4; i++) {
        float v = t[tx][ty + i*8];
        __nv_bfloat16 h, l; split_bf16(v, h, l);
        size_t o = (size_t)(n0 + ty + i*8) * K + k0 + tx;
        Th[o] = h; Tl[o] = l;
    }
}

// ========== HMMA GEMM (R6 config: K-block 64, 3x64KB stages, 1 CTA/SM) ==========
#define STAGE_BYTES 65536
#define GEMM_SMEM (3 * STAGE_BYTES)
__global__ void __launch_bounds__(256, 1)
tc_gemm(const __nv_bfloat16* __restrict__ Ah, const __nv_bfloat16* __restrict__ Al,
        const __nv_bfloat16* __restrict__ Bh, const __nv_bfloat16* __restrict__ Bl,
        const float* __restrict__ bias,
        float* __restrict__ outF,
        __nv_bfloat16* __restrict__ outHi, __nv_bfloat16* __restrict__ outLo,
        int M, int N, int K, int mode) {
    extern __shared__ char smem[];
    const uint32_t tiles = smem_to_u32(smem);
    const int tid = threadIdx.x;
    const int wid = tid >> 5;
    const int lane = tid & 31;
    const int warpM = wid >> 1;
    const int warpN = wid & 1;
    const int bm = blockIdx.y * 128;
    const int bn = blockIdx.x * 128;
    const int NB = K >> 6;

    const __nv_bfloat16* srcs[4] = {Ah, Al, Bh, Bl};

    auto stage = [&](int kb, int s) {
        #pragma unroll
        for (int t = 0; t < 4; t++) {
            const __nv_bfloat16* src = srcs[t];
            const int rbase = (t < 2) ? bm : bn;
            const uint32_t sb = tiles + (uint32_t)s * STAGE_BYTES + (uint32_t)t * 16384u;
            #pragma unroll
            for (int i = 0; i < 4; i++) {
                int chunk = tid + i * 256;
                int row = chunk >> 3;
                int c16 = chunk & 7;
                uint32_t off = (uint32_t)(row * 128 + c16 * 16);
                uint32_t dst = sb + SMEM_SWIZZLE_128B(off);
                const void* g = src + (size_t)(rbase + row) * K + kb * 64 + c16 * 8;
                asm volatile("cp.async.cg.shared.global [%0], [%1], 16;" :: "r"(dst), "l"(g));
            }
        }
        asm volatile("cp.async.commit_group;" ::: "memory");
    };

    float c[2][8][4] = {};

    stage(0, 0);
    if (NB > 1) stage(1, 1);

    const int lrow = lane & 15;
    const int lchunk = lane >> 4;

    for (int kb = 0; kb < NB; kb++) {
        const int s = kb % 3;
        if (kb + 1 < NB) asm volatile("cp.async.wait_group 1;" ::: "memory");
        else             asm volatile("cp.async.wait_group 0;" ::: "memory");
        __syncthreads();
        if (kb + 2 < NB) stage(kb + 2, (kb + 2) % 3);

        const uint32_t base_s = tiles + (uint32_t)s * STAGE_BYTES;
        #pragma unroll
        for (int ks = 0; ks < 4; ks++) {
            uint32_t ah[2][4], al2[2][4];
            #pragma unroll
            for (int mt = 0; mt < 2; mt++) {
                uint32_t off = (uint32_t)((warpM * 32 + mt * 16 + lrow) * 128 + ks * 32 + lchunk * 16);
                uint32_t sw = SMEM_SWIZZLE_128B(off);
                ldsm_x4(ah[mt],  base_s + sw);
                ldsm_x4(al2[mt], base_s + 16384u + sw);
            }
            #pragma unroll
            for (int np = 0; np < 4; np++) {
                uint32_t off = (uint32_t)((warpN * 64 + np * 16 + lrow) * 128 + ks * 32 + lchunk * 16);
                uint32_t sw = SMEM_SWIZZLE_128B(off);
                uint32_t bh[4], bl[4];
                ldsm_x4(bh, base_s + 32768u + sw);
                ldsm_x4(bl, base_s + 49152u + sw);
                #pragma unroll
                for (int mt = 0; mt < 2; mt++) {
                    mma_bf16(c[mt][2*np],   ah[mt],  bh[0], bh[2]);
                    mma_bf16(c[mt][2*np+1], ah[mt],  bh[1], bh[3]);
                    mma_bf16(c[mt][2*np],   ah[mt],  bl[0], bl[2]);
                    mma_bf16(c[mt][2*np+1], ah[mt],  bl[1], bl[3]);
                    mma_bf16(c[mt][2*np],   al2[mt], bh[0], bh[2]);
                    mma_bf16(c[mt][2*np+1], al2[mt], bh[1], bh[3]);
                }
            }
        }
    }
    __syncthreads();

    float* sD = reinterpret_cast<float*>(smem);   // 128 x 129
    #pragma unroll
    for (int mt = 0; mt < 2; mt++) {
        #pragma unroll
        for (int nt = 0; nt < 8; nt++) {
            int r0 = warpM * 32 + mt * 16 + (lane >> 2);
            int col = warpN * 64 + nt * 8 + (lane & 3) * 2;
            sD[r0 * 129 + col]           = c[mt][nt][0];
            sD[r0 * 129 + col + 1]       = c[mt][nt][1];
            sD[(r0 + 8) * 129 + col]     = c[mt][nt][2];
            sD[(r0 + 8) * 129 + col + 1] = c[mt][nt][3];
        }
    }
    __syncthreads();

    for (int idx = tid; idx < 128 * 128; idx += 256) {
        int r = idx >> 7, cc = idx & 127;
        float v = sD[r * 129 + cc] + bias[bn + cc];
        size_t row = (size_t)(bm + r);
        int gc = bn + cc;
        if (mode == 0) {
            outF[row * N + gc] = v;
        } else if (mode == 1) {
            v = gelu_tanh(v);
            __nv_bfloat16 h, l; split_bf16(v, h, l);
            outHi[row * N + gc] = h;
            outLo[row * N + gc] = l;
        } else {
            if (gc < DM) {
                outF[row * DM + gc] = v * 0.125f;
            } else {
                __nv_bfloat16 h, l; split_bf16(v, h, l);
                size_t o = row * KVW + (gc - DM);
                outHi[o] = h; outLo[o] = l;
            }
        }
    }
}

// ================= HMMA sliding-window attention, 8 warps =================
// block = (c, h, b), 256 threads. warpM = wid>>1 (16-row tile), warpN = wid&1
// (96-col half of the 192-col kv window). Softmax max/sum combined across the
// warpN pair via smem; PV partial-O pair-summed through the dead q region.
#define AQH 0
#define AQL 8192
#define AKH 16384
#define AKL 40960
#define AVH 65536
#define AVL 90112
#define ARED 114688            // maxbuf[128] floats, sumbuf[128] floats
#define OEX 0                  // aliases q region after QK
#define ATTN_SMEM (114688 + 1024)
__global__ void __launch_bounds__(256, 1)
attn_kernel(const float* __restrict__ qf,
            const __nv_bfloat16* __restrict__ kvh,
            const __nv_bfloat16* __restrict__ kvl,
            float* __restrict__ out) {
    extern __shared__ char smem[];
    const uint32_t sb = smem_to_u32(smem);
    const int c = blockIdx.x, h = blockIdx.y, b = blockIdx.z;
    const int tid = threadIdx.x, wid = tid >> 5, lane = tid & 31;
    const int warpM = wid >> 1, warpN = wid & 1;

    // ---- load q (fp32, pre-scaled) -> split hi/lo ----
    for (int idx = tid; idx < 64 * 16; idx += 256) {
        int r = idx >> 4, ch = idx & 15;
        float4 v = *reinterpret_cast<const float4*>(
            &qf[((size_t)b * SS + c * 64 + r) * DM + h * HD + ch * 4]);
        uint32_t off = SMEM_SWIZZLE_128B((uint32_t)(r * 128 + ch * 8));
        uint2 hh, ll;
        hh.x = pack_hi(v.x, v.y); hh.y = pack_hi(v.z, v.w);
        ll.x = pack_lo(v.x, v.y); ll.y = pack_lo(v.z, v.w);
        *reinterpret_cast<uint2*>(smem + AQH + off) = hh;
        *reinterpret_cast<uint2*>(smem + AQL + off) = ll;
    }
    // ---- load k/v hi/lo window (192 rows, zero-padded) ----
    for (int idx = tid; idx < 192 * 8; idx += 256) {
        int j = idx >> 3, ch = idx & 7;
        int g = c * 64 - 64 + j;
        uint4 z = {0, 0, 0, 0};
        uint4 kh4 = z, kl4 = z, vh4 = z, vl4 = z;
        if (g >= 0 && g < SS) {
            size_t rb = ((size_t)b * SS + g) * KVW + h * HD + ch * 8;
            kh4 = *reinterpret_cast<const uint4*>(&kvh[rb]);
            kl4 = *reinterpret_cast<const uint4*>(&kvl[rb]);
            vh4 = *reinterpret_cast<const uint4*>(&kvh[rb + DM]);
            vl4 = *reinterpret_cast<const uint4*>(&kvl[rb + DM]);
        }
        uint32_t off = SMEM_SWIZZLE_128B((uint32_t)(j * 128 + ch * 16));
        *reinterpret_cast<uint4*>(smem + AKH + off) = kh4;
        *reinterpret_cast<uint4*>(smem + AKL + off) = kl4;
        *reinterpret_cast<uint4*>(smem + AVH + off) = vh4;
        *reinterpret_cast<uint4*>(smem + AVL + off) = vl4;
    }
    __syncthreads();

    const int m0 = warpM * 16;
    const int jbase = warpN * 96;      // this warp's kv column base
    const int lrow = lane & 15;
    const int lch = lane >> 4;

    // ---- QK^T: 16 x 96 per warp ----
    float s[12][4];
    #pragma unroll
    for (int nt = 0; nt < 12; nt++)
        #pragma unroll
        for (int u = 0; u < 4; u++) s[nt][u] = 0.f;

    #pragma unroll
    for (int ks = 0; ks < 4; ks++) {
        uint32_t aoff = SMEM_SWIZZLE_128B((uint32_t)((m0 + lrow) * 128 + ks * 32 + lch * 16));
        uint32_t ah[4], al[4];
        ldsm_x4(ah, sb + AQH + aoff);
        ldsm_x4(al, sb + AQL + aoff);
        #pragma unroll
        for (int n6 = 0; n6 < 6; n6++) {
            uint32_t boff = SMEM_SWIZZLE_128B(
                (uint32_t)((jbase + n6 * 16 + lrow) * 128 + ks * 32 + lch * 16));
            uint32_t bh[4], bl[4];
            ldsm_x4(bh, sb + AKH + boff);
            ldsm_x4(bl, sb + AKL + boff);
            mma_bf16(s[2*n6],   ah, bh[0], bh[2]);
            mma_bf16(s[2*n6+1], ah, bh[1], bh[3]);
            mma_bf16(s[2*n6],   ah, bl[0], bl[2]);
            mma_bf16(s[2*n6+1], ah, bl[1], bl[3]);
            mma_bf16(s[2*n6],   al, bh[0], bh[2]);
            mma_bf16(s[2*n6+1], al, bh[1], bh[3]);
        }
    }

    // ---- mask + cross-warp softmax ----
    const int rA = m0 + (lane >> 2);
    const int rB = rA + 8;
    const int jb = 2 * (lane & 3);
    const int gof = c * 64 - 64;
    float mA = -INFINITY, mB = -INFINITY;
    #pragma unroll
    for (int nt = 0; nt < 12; nt++) {
        int j0 = jbase + nt * 8 + jb, j1 = j0 + 1;
        int g0 = gof + j0, g1 = gof + j1;
        bool in0 = (g0 >= 0) && (g0 < SS);
        bool in1 = (g1 >= 0) && (g1 < SS);
        if (!((j0 >= rA) && (j0 <= rA + 128) && in0)) s[nt][0] = -INFINITY;
        if (!((j1 >= rA) && (j1 <= rA + 128) && in1)) s[nt][1] = -INFINITY;
        if (!((j0 >= rB) && (j0 <= rB + 128) && in0)) s[nt][2] = -INFINITY;
        if (!((j1 >= rB) && (j1 <= rB + 128) && in1)) s[nt][3] = -INFINITY;
        mA = fmaxf(mA, fmaxf(s[nt][0], s[nt][1]));
        mB = fmaxf(mB, fmaxf(s[nt][2], s[nt][3]));
    }
    mA = fmaxf(mA, __shfl_xor_sync(0xffffffffu, mA, 1));
    mA = fmaxf(mA, __shfl_xor_sync(0xffffffffu, mA, 2));
    mB = fmaxf(mB, __shfl_xor_sync(0xffffffffu, mB, 1));
    mB = fmaxf(mB, __shfl_xor_sync(0xffffffffu, mB, 2));

    float* redbuf = reinterpret_cast<float*>(smem + ARED);   // [0:128) max, [128:256) sum
    if ((lane & 3) == 0) {
        redbuf[warpN * 64 + rA] = mA;
        redbuf[warpN * 64 + rB] = mB;
    }
    __syncthreads();
    mA = fmaxf(mA, redbuf[(warpN ^ 1) * 64 + rA]);
    mB = fmaxf(mB, redbuf[(warpN ^ 1) * 64 + rB]);

    float sA = 0.f, sB = 0.f;
    #pragma unroll
    for (int nt = 0; nt < 12; nt++) {
        s[nt][0] = __expf(s[nt][0] - mA);
        s[nt][1] = __expf(s[nt][1] - mA);
        s[nt][2] = __expf(s[nt][2] - mB);
        s[nt][3] = __expf(s[nt][3] - mB);
        sA += s[nt][0] + s[nt][1];
        sB += s[nt][2] + s[nt][3];
    }
    sA += __shfl_xor_sync(0xffffffffu, sA, 1);
    sA += __shfl_xor_sync(0xffffffffu, sA, 2);
    sB += __shfl_xor_sync(0xffffffffu, sB, 1);
    sB += __shfl_xor_sync(0xffffffffu, sB, 2);
    if ((lane & 3) == 0) {
        redbuf[128 + warpN * 64 + rA] = sA;
        redbuf[128 + warpN * 64 + rB] = sB;
    }
    __syncthreads();
    sA += redbuf[128 + (warpN ^ 1) * 64 + rA];
    sB += redbuf[128 + (warpN ^ 1) * 64 + rB];
    const float invA = 1.0f / sA, invB = 1.0f / sB;

    // ---- PV over this warp's 96 kv rows ----
    float o[8][4];
    #pragma unroll
    for (int nt = 0; nt < 8; nt++)
        #pragma unroll
        for (int u = 0; u < 4; u++) o[nt][u] = 0.f;

    #pragma unroll
    for (int t = 0; t < 6; t++) {
        uint32_t ph[4], pl[4];
        ph[0] = pack_hi(s[2*t][0],   s[2*t][1]);
        ph[1] = pack_hi(s[2*t][2],   s[2*t][3]);
        ph[2] = pack_hi(s[2*t+1][0], s[2*t+1][1]);
        ph[3] = pack_hi(s[2*t+1][2], s[2*t+1][3]);
        pl[0] = pack_lo(s[2*t][0],   s[2*t][1]);
        pl[1] = pack_lo(s[2*t][2],   s[2*t][3]);
        pl[2] = pack_lo(s[2*t+1][0], s[2*t+1][1]);
        pl[3] = pack_lo(s[2*t+1][2], s[2*t+1][3]);
        #pragma unroll
        for (int nn = 0; nn < 4; nn++) {
            uint32_t voff = SMEM_SWIZZLE_128B(
                (uint32_t)((jbase + t * 16 + (lane & 15)) * 128 + (nn * 16 + (lane >> 4) * 8) * 2));
            uint32_t vh[4], vl[4];
            ldsm_x4_trans(vh, sb + AVH + voff);
            ldsm_x4_trans(vl, sb + AVL + voff);
            mma_bf16(o[2*nn],   ph, vh[0], vh[1]);
            mma_bf16(o[2*nn+1], ph, vh[2], vh[3]);
            mma_bf16(o[2*nn],   ph, vl[0], vl[1]);
            mma_bf16(o[2*nn+1], ph, vl[2], vl[3]);
            mma_bf16(o[2*nn],   pl, vh[0], vh[1]);
            mma_bf16(o[2*nn+1], pl, vh[2], vh[3]);
        }
    }

    // ---- pair-sum partial O through smem (q region is dead) ----
    float* obuf = reinterpret_cast<float*>(smem + OEX);   // 4 x (16x64) floats
    __syncthreads();                                       // all QK reads of q done (long ago)
    if (warpN == 1) {
        const int base = warpM * 1024;
        #pragma unroll
        for (int nt = 0; nt < 8; nt++) {
            int col = nt * 8 + jb;
            *reinterpret_cast<float2*>(&obuf[base + (rA - m0) * 64 + col]) =
                make_float2(o[nt][0], o[nt][1]);
            *reinterpret_cast<float2*>(&obuf[base + (rB - m0) * 64 + col]) =
                make_float2(o[nt][2], o[nt][3]);
        }
    }
    __syncthreads();
    if (warpN == 0) {
        const int base = warpM * 1024;
        const size_t rowg = (size_t)b * SS + c * 64;
        #pragma unroll
        for (int nt = 0; nt < 8; nt++) {
            int col = nt * 8 + jb;
            float2 pA = *reinterpret_cast<const float2*>(&obuf[base + (rA - m0) * 64 + col]);
            float2 pB = *reinterpret_cast<const float2*>(&obuf[base + (rB - m0) * 64 + col]);
            float2 v0 = make_float2((o[nt][0] + pA.x) * invA, (o[nt][1] + pA.y) * invA);
            float2 v1 = make_float2((o[nt][2] + pB.x) * invB, (o[nt][3] + pB.y) * invB);
            *reinterpret_cast<float2*>(&out[(rowg + rA) * DM + h * HD + col]) = v0;
            *reinterpret_cast<float2*>(&out[(rowg + rB) * DM + h * HD + col]) = v1;
        }
    }
}

// ================= warp-per-row residual + LayerNorm =================
__global__ void __launch_bounds__(256)
add_ln_kernel(const float* __restrict__ a,
              const float* __restrict__ r,
              const float* __restrict__ g,
              const float* __restrict__ beta,
              float* __restrict__ out,
              __nv_bfloat16* __restrict__ outHi,
              __nv_bfloat16* __restrict__ outLo) {
    const int warp = threadIdx.x >> 5, lane = threadIdx.x & 31;
    const int row = blockIdx.x * 8 + warp;
    const float4* pa = reinterpret_cast<const float4*>(a + (size_t)row * DM);
    const float4* pr = reinterpret_cast<const float4*>(r + (size_t)row * DM);
    const float4* pg = reinterpret_cast<const float4*>(g);
    const float4* pb = reinterpret_cast<const float4*>(beta);

    float4 v[6];
    float sum = 0.f;
    #pragma unroll
    for (int ch = 0; ch < 6; ch++) {
        float4 va = pa[lane + 32 * ch];
        float4 vr = pr[lane + 32 * ch];
        v[ch] = make_float4(va.x + vr.x, va.y + vr.y, va.z + vr.z, va.w + vr.w);
        sum += v[ch].x + v[ch].y + v[ch].z + v[ch].w;
    }
    #pragma unroll
    for (int o = 16; o > 0; o >>= 1) sum += __shfl_xor_sync(0xffffffffu, sum, o);
    float mu = sum * (1.0f / DM);

    float var = 0.f;
    #pragma unroll
    for (int ch = 0; ch < 6; ch++) {
        float dx = v[ch].x - mu, dy = v[ch].y - mu, dz = v[ch].z - mu, dw = v[ch].w - mu;
        var += dx * dx + dy * dy + dz * dz + dw * dw;
    }
    #pragma unroll
    for (int o = 16; o > 0; o >>= 1) var += __shfl_xor_sync(0xffffffffu, var, o);
    float rstd = rsqrtf(var * (1.0f / DM) + 1e-5f);

    float4* po = reinterpret_cast<float4*>(out + (size_t)row * DM);
    #pragma unroll
    for (int ch = 0; ch < 6; ch++) {
        float4 gg = pg[lane + 32 * ch];
        float4 bb = pb[lane + 32 * ch];
        float4 y;
        y.x = (v[ch].x - mu) * rstd * gg.x + bb.x;
        y.y = (v[ch].y - mu) * rstd * gg.y + bb.y;
        y.z = (v[ch].z - mu) * rstd * gg.z + bb.z;
        y.w = (v[ch].w - mu) * rstd * gg.w + bb.w;
        po[lane + 32 * ch] = y;
        if (outHi) {
            size_t o4 = (size_t)row * DM + (lane + 32 * ch) * 4;
            __nv_bfloat16 h0,l0,h1,l1,h2,l2,h3,l3;
            split_bf16(y.x, h0, l0); split_bf16(y.y, h1, l1);
            split_bf16(y.z, h2, l2); split_bf16(y.w, h3, l3);
            reinterpret_cast<__nv_bfloat162*>(outHi + o4)[0] = __nv_bfloat162(h0, h1);
            reinterpret_cast<__nv_bfloat162*>(outHi + o4)[1] = __nv_bfloat162(h2, h3);
            reinterpret_cast<__nv_bfloat162*>(outLo + o4)[0] = __nv_bfloat162(l0, l1);
            reinterpret_cast<__nv_bfloat162*>(outLo + o4)[1] = __nv_bfloat162(l2, l3);
        }
    }
}

// ================= launch =================
extern "C" void kernel_launch(void* const* d_in, const int* in_sizes, int n_in,
                              void* d_out, int out_size) {
    const float* x     = (const float*)d_in[0];
    const float* Wq    = (const float*)d_in[1];
    const float* bq    = (const float*)d_in[2];
    const float* Wk    = (const float*)d_in[3];
    const float* bk    = (const float*)d_in[4];
    const float* Wv    = (const float*)d_in[5];
    const float* bv    = (const float*)d_in[6];
    const float* ln1_g = (const float*)d_in[7];
    const float* ln1_b = (const float*)d_in[8];
    const float* W1    = (const float*)d_in[9];
    const float* b1    = (const float*)d_in[10];
    const float* W2    = (const float*)d_in[11];
    const float* b2    = (const float*)d_in[12];
    const float* ln2_g = (const float*)d_in[13];
    const float* ln2_b = (const float*)d_in[14];
    float* out = (float*)d_out;

    float *qf, *attn, *x1, *ff, *bqkv;
    __nv_bfloat16 *kvh, *kvl, *xh, *xl, *x1h, *x1l, *hidh, *hidl;
    __nv_bfloat16 *wqkvh, *wqkvl, *w1h, *w1l, *w2h, *w2l;
    cudaGetSymbolAddress((void**)&qf, g_qf);     cudaGetSymbolAddress((void**)&attn, g_attn);
    cudaGetSymbolAddress((void**)&x1, g_x1);     cudaGetSymbolAddress((void**)&ff, g_ff);
    cudaGetSymbolAddress((void**)&bqkv, g_bqkv);
    cudaGetSymbolAddress((void**)&kvh, g_kvh);   cudaGetSymbolAddress((void**)&kvl, g_kvl);
    cudaGetSymbolAddress((void**)&xh, g_xh);     cudaGetSymbolAddress((void**)&xl, g_xl);
    cudaGetSymbolAddress((void**)&x1h, g_x1h);   cudaGetSymbolAddress((void**)&x1l, g_x1l);
    cudaGetSymbolAddress((void**)&hidh, g_hidh); cudaGetSymbolAddress((void**)&hidl, g_hidl);
    cudaGetSymbolAddress((void**)&wqkvh, g_wqkvh); cudaGetSymbolAddress((void**)&wqkvl, g_wqkvl);
    cudaGetSymbolAddress((void**)&w1h, g_w1h);   cudaGetSymbolAddress((void**)&w1l, g_w1l);
    cudaGetSymbolAddress((void**)&w2h, g_w2h);   cudaGetSymbolAddress((void**)&w2l, g_w2l);

    cudaFuncSetAttribute(tc_gemm, cudaFuncAttributeMaxDynamicSharedMemorySize, GEMM_SMEM);
    cudaFuncSetAttribute(attn_kernel, cudaFuncAttributeMaxDynamicSharedMemorySize, ATTN_SMEM);

    // ---- convert inputs ----
    {
        int n4 = MROWS * DM / 4;
        split_convert<<<(n4 + 255) / 256, 256>>>(x, xh, xl, n4);
        prep_weights<<<6345, 256>>>(Wq, Wk, Wv, W1, W2, bq, bk, bv,
                                    wqkvh, wqkvl, w1h, w1l, w2h, w2l, bqkv);
    }

    // ---- fused QKV projection: q fp32 (scaled), k/v bf16 hi/lo ----
    {
        dim3 grid(QKVN / 128, MROWS / 128);
        tc_gemm<<<grid, 256, GEMM_SMEM>>>(xh, xl, wqkvh, wqkvl, bqkv, qf,
                                          kvh, kvl, MROWS, QKVN, DM, 2);
    }

    // ---- attention (HMMA, 8 warps) ----
    {
        dim3 grid(NC, NH, BB);
        attn_kernel<<<grid, 256, ATTN_SMEM>>>(qf, kvh, kvl, attn);
    }

    // ---- x1 = LN(attn + x), emit bf16 hi/lo ----
    add_ln_kernel<<<MROWS / 8, 256>>>(attn, x, ln1_g, ln1_b, x1, x1h, x1l);

    // ---- FFN ----
    {
        dim3 grid1(FF / 128, MROWS / 128);
        tc_gemm<<<grid1, 256, GEMM_SMEM>>>(x1h, x1l, w1h, w1l, b1, nullptr,
                                           hidh, hidl, MROWS, FF, DM, 1);
        dim3 grid2(DM / 128, MROWS / 128);
        tc_gemm<<<grid2, 256, GEMM_SMEM>>>(hidh, hidl, w2h, w2l, b2, ff,
                                           nullptr, nullptr, MROWS, DM, FF, 0);
    }

    // ---- out = LN(ff + x1) ----
    add_ln_kernel<<<MROWS / 8, 256>>>(ff, x1, ln2_g, ln2_b, out, nullptr, nullptr);
}

// round 9
// speedup vs baseline: 1.0401x; 1.0279x over previous
#include <cuda_runtime.h>
#include <cuda_bf16.h>
#include <math.h>
#include <cstdint>

#define BB 2
#define SS 4096
#define DM 768
#define NH 12
#define FF 3072
#define WIN 64
#define HD 64
#define NC (SS / WIN)
#define MROWS (BB * SS)    // 8192
#define QKVN (3 * DM)      // 2304
#define KVW (2 * DM)       // 1536 packed k|v width
#define MD (MROWS * DM)

// ================= helpers =================
__device__ __forceinline__ uint32_t smem_to_u32(const void* p) {
    uint32_t a;
    asm("{ .reg .u64 t; cvta.to.shared.u64 t, %1; cvt.u32.u64 %0, t; }" : "=r"(a) : "l"(p));
    return a;
}
#define SMEM_SWIZZLE_128B(o) ((o) ^ (((o) >> 3) & 0x70))

__device__ __forceinline__ void ldsm_x4(uint32_t r[4], uint32_t addr) {
    asm volatile("ldmatrix.sync.aligned.m8n8.x4.shared.b16 {%0,%1,%2,%3}, [%4];"
        : "=r"(r[0]), "=r"(r[1]), "=r"(r[2]), "=r"(r[3]) : "r"(addr));
}
__device__ __forceinline__ void ldsm_x4_trans(uint32_t r[4], uint32_t addr) {
    asm volatile("ldmatrix.sync.aligned.m8n8.x4.trans.shared.b16 {%0,%1,%2,%3}, [%4];"
        : "=r"(r[0]), "=r"(r[1]), "=r"(r[2]), "=r"(r[3]) : "r"(addr));
}
__device__ __forceinline__ void mma_bf16(float c[4], const uint32_t a[4],
                                         uint32_t b0, uint32_t b1) {
    asm volatile("mma.sync.aligned.m16n8k16.row.col.f32.bf16.bf16.f32 "
        "{%0,%1,%2,%3}, {%4,%5,%6,%7}, {%8,%9}, {%0,%1,%2,%3};"
        : "+f"(c[0]), "+f"(c[1]), "+f"(c[2]), "+f"(c[3])
        : "r"(a[0]), "r"(a[1]), "r"(a[2]), "r"(a[3]), "r"(b0), "r"(b1));
}
__device__ __forceinline__ void split_bf16(float v, __nv_bfloat16& h, __nv_bfloat16& l) {
    h = __float2bfloat16(v);
    l = __float2bfloat16(v - __bfloat162float(h));
}
__device__ __forceinline__ uint32_t pack_hi(float x, float y) {
    __nv_bfloat162 t(__float2bfloat16(x), __float2bfloat16(y));
    return *reinterpret_cast<uint32_t*>(&t);
}
__device__ __forceinline__ uint32_t pack_lo(float x, float y) {
    __nv_bfloat16 hx = __float2bfloat16(x), hy = __float2bfloat16(y);
    __nv_bfloat162 t(__float2bfloat16(x - __bfloat162float(hx)),
                     __float2bfloat16(y - __bfloat162float(hy)));
    return *reinterpret_cast<uint32_t*>(&t);
}
__device__ __forceinline__ float gelu_tanh(float x) {
    const float c = 0.7978845608028654f;
    float x3 = x * x * x;
    return 0.5f * x * (1.0f + tanhf(c * (x + 0.044715f * x3)));
}

// ================= scratch =================
__device__ float g_qf[MD];
__device__ float g_attn[MD];
__device__ float g_x1[MD];
__device__ float g_ffp[3 * MD];     // FFN2 split-K partials
__device__ float g_bqkv[QKVN];
__device__ __nv_bfloat16 g_kvh[MROWS * KVW], g_kvl[MROWS * KVW];
__device__ __nv_bfloat16 g_xh[MD],  g_xl[MD];
__device__ __nv_bfloat16 g_x1h[MD], g_x1l[MD];
__device__ __nv_bfloat16 g_hidh[MROWS * FF], g_hidl[MROWS * FF];
__device__ __nv_bfloat16 g_wqkvh[QKVN * DM], g_wqkvl[QKVN * DM];
__device__ __nv_bfloat16 g_w1h[FF * DM], g_w1l[FF * DM];
__device__ __nv_bfloat16 g_w2h[DM * FF], g_w2l[DM * FF];

// ========== elementwise fp32 -> bf16 hi/lo ==========
__global__ void split_convert(const float* __restrict__ in,
                              __nv_bfloat16* __restrict__ hi,
                              __nv_bfloat16* __restrict__ lo, int n4) {
    int i = blockIdx.x * blockDim.x + threadIdx.x;
    if (i >= n4) return;
    float4 v = reinterpret_cast<const float4*>(in)[i];
    __nv_bfloat16 h0,l0,h1,l1,h2,l2,h3,l3;
    split_bf16(v.x, h0, l0); split_bf16(v.y, h1, l1);
    split_bf16(v.z, h2, l2); split_bf16(v.w, h3, l3);
    reinterpret_cast<__nv_bfloat162*>(hi)[i*2+0] = __nv_bfloat162(h0, h1);
    reinterpret_cast<__nv_bfloat162*>(hi)[i*2+1] = __nv_bfloat162(h2, h3);
    reinterpret_cast<__nv_bfloat162*>(lo)[i*2+0] = __nv_bfloat162(l0, l1);
    reinterpret_cast<__nv_bfloat162*>(lo)[i*2+1] = __nv_bfloat162(l2, l3);
}

// ========== merged weight transpose+split + bias pack ==========
__global__ void prep_weights(const float* __restrict__ Wq, const float* __restrict__ Wk,
                             const float* __restrict__ Wv, const float* __restrict__ W1,
                             const float* __restrict__ W2,
                             const float* __restrict__ bq, const float* __restrict__ bk,
                             const float* __restrict__ bv,
                             __nv_bfloat16* __restrict__ wqkvh, __nv_bfloat16* __restrict__ wqkvl,
                             __nv_bfloat16* __restrict__ w1h, __nv_bfloat16* __restrict__ w1l,
                             __nv_bfloat16* __restrict__ w2h, __nv_bfloat16* __restrict__ w2l,
                             float* __restrict__ bqkv) {
    int id = blockIdx.x;
    if (id >= 6336) {
        int i = (id - 6336) * 256 + threadIdx.x;
        if (i < QKVN)
            bqkv[i] = (i < DM) ? bq[i] : (i < 2 * DM) ? bk[i - DM] : bv[i - 2 * DM];
        return;
    }
    const float* W; __nv_bfloat16 *Th, *Tl; int K, N, tix;
    if (id < 576)       { W = Wq; Th = wqkvh;               Tl = wqkvl;               K = DM; N = DM; tix = id; }
    else if (id < 1152) { W = Wk; Th = wqkvh + DM * DM;     Tl = wqkvl + DM * DM;     K = DM; N = DM; tix = id - 576; }
    else if (id < 1728) { W = Wv; Th = wqkvh + 2 * DM * DM; Tl = wqkvl + 2 * DM * DM; K = DM; N = DM; tix = id - 1152; }
    else if (id < 4032) { W = W1; Th = w1h;                 Tl = w1l;                 K = DM; N = FF; tix = id - 1728; }
    else                { W = W2; Th = w2h;                 Tl = w2l;                 K = FF; N = DM; tix = id - 4032; }
    int nt = N / 32;
    int n0 = (tix % nt) * 32, k0 = (tix / nt) * 32;
    __shared__ float t[32][33];
    int tx = threadIdx.x & 31, ty = threadIdx.x >> 5;
    #pragma unroll
    for (int i = 0; i < 4; i++)
        t[ty + i*8][tx] = W[(size_t)(k0 + ty + i*8) * N + n0 + tx];
    __syncthreads();
    #pragma unroll
    for (int i = 0; i < 4; i++) {
        float v = t[tx][ty + i*8];
        __nv_bfloat16 h, l; split_bf16(v, h, l);
        size_t o = (size_t)(n0 + ty + i*8) * K + k0 + tx;
        Th[o] = h; Tl[o] = l;
    }
}

// ========== HMMA GEMM (R6 core + B double-buffer + split-K mode 3) ==========
// mode 0: fp32+bias. mode 1: gelu+hi/lo. mode 2: QKV. mode 3: split-K partial
// (blockIdx.z selects K third; fp32, no bias, out += z*M*N).
#define STAGE_BYTES 65536
#define GEMM_SMEM (3 * STAGE_BYTES)
__global__ void __launch_bounds__(256, 1)
tc_gemm(const __nv_bfloat16* __restrict__ Ah, const __nv_bfloat16* __restrict__ Al,
        const __nv_bfloat16* __restrict__ Bh, const __nv_bfloat16* __restrict__ Bl,
        const float* __restrict__ bias,
        float* __restrict__ outF,
        __nv_bfloat16* __restrict__ outHi, __nv_bfloat16* __restrict__ outLo,
        int M, int N, int K, int mode) {
    extern __shared__ char smem[];
    const uint32_t tiles = smem_to_u32(smem);
    const int tid = threadIdx.x;
    const int wid = tid >> 5;
    const int lane = tid & 31;
    const int warpM = wid >> 1;
    const int warpN = wid & 1;
    const int bm = blockIdx.y * 128;
    const int bn = blockIdx.x * 128;
    const int kb0 = (mode == 3) ? blockIdx.z * 16 : 0;
    const int NB  = (mode == 3) ? 16 : (K >> 6);
    if (mode == 3) outF += (size_t)blockIdx.z * M * N;

    const __nv_bfloat16* srcs[4] = {Ah, Al, Bh, Bl};

    auto stage = [&](int kb, int s) {
        #pragma unroll
        for (int t = 0; t < 4; t++) {
            const __nv_bfloat16* src = srcs[t];
            const int rbase = (t < 2) ? bm : bn;
            const uint32_t sb = tiles + (uint32_t)s * STAGE_BYTES + (uint32_t)t * 16384u;
            #pragma unroll
            for (int i = 0; i < 4; i++) {
                int chunk = tid + i * 256;
                int row = chunk >> 3;
                int c16 = chunk & 7;
                uint32_t off = (uint32_t)(row * 128 + c16 * 16);
                uint32_t dst = sb + SMEM_SWIZZLE_128B(off);
                const void* g = src + (size_t)(rbase + row) * K + kb * 64 + c16 * 8;
                asm volatile("cp.async.cg.shared.global [%0], [%1], 16;" :: "r"(dst), "l"(g));
            }
        }
        asm volatile("cp.async.commit_group;" ::: "memory");
    };

    float c[2][8][4] = {};

    stage(kb0, 0);
    if (NB > 1) stage(kb0 + 1, 1);

    const int lrow = lane & 15;
    const int lchunk = lane >> 4;

    for (int kb = 0; kb < NB; kb++) {
        const int s = kb % 3;
        if (kb + 1 < NB) asm volatile("cp.async.wait_group 1;" ::: "memory");
        else             asm volatile("cp.async.wait_group 0;" ::: "memory");
        __syncthreads();
        if (kb + 2 < NB) stage(kb0 + kb + 2, (kb + 2) % 3);

        const uint32_t base_s = tiles + (uint32_t)s * STAGE_BYTES;
        #pragma unroll
        for (int ks = 0; ks < 4; ks++) {
            uint32_t ah[2][4], al2[2][4];
            #pragma unroll
            for (int mt = 0; mt < 2; mt++) {
                uint32_t off = (uint32_t)((warpM * 32 + mt * 16 + lrow) * 128 + ks * 32 + lchunk * 16);
                uint32_t sw = SMEM_SWIZZLE_128B(off);
                ldsm_x4(ah[mt],  base_s + sw);
                ldsm_x4(al2[mt], base_s + 16384u + sw);
            }
            // B double-buffer: prefetch np+1 while issuing np's mma
            uint32_t bh[2][4], bl[2][4];
            {
                uint32_t off0 = (uint32_t)((warpN * 64 + lrow) * 128 + ks * 32 + lchunk * 16);
                uint32_t sw0 = SMEM_SWIZZLE_128B(off0);
                ldsm_x4(bh[0], base_s + 32768u + sw0);
                ldsm_x4(bl[0], base_s + 49152u + sw0);
            }
            #pragma unroll
            for (int np = 0; np < 4; np++) {
                const int cur = np & 1;
                if (np < 3) {
                    uint32_t off = (uint32_t)((warpN * 64 + (np + 1) * 16 + lrow) * 128 + ks * 32 + lchunk * 16);
                    uint32_t sw = SMEM_SWIZZLE_128B(off);
                    ldsm_x4(bh[cur ^ 1], base_s + 32768u + sw);
                    ldsm_x4(bl[cur ^ 1], base_s + 49152u + sw);
                }
                #pragma unroll
                for (int mt = 0; mt < 2; mt++) {
                    mma_bf16(c[mt][2*np],   ah[mt],  bh[cur][0], bh[cur][2]);
                    mma_bf16(c[mt][2*np+1], ah[mt],  bh[cur][1], bh[cur][3]);
                    mma_bf16(c[mt][2*np],   ah[mt],  bl[cur][0], bl[cur][2]);
                    mma_bf16(c[mt][2*np+1], ah[mt],  bl[cur][1], bl[cur][3]);
                    mma_bf16(c[mt][2*np],   al2[mt], bh[cur][0], bh[cur][2]);
                    mma_bf16(c[mt][2*np+1], al2[mt], bh[cur][1], bh[cur][3]);
                }
            }
        }
    }
    __syncthreads();

    float* sD = reinterpret_cast<float*>(smem);   // 128 x 129
    #pragma unroll
    for (int mt = 0; mt < 2; mt++) {
        #pragma unroll
        for (int nt = 0; nt < 8; nt++) {
            int r0 = warpM * 32 + mt * 16 + (lane >> 2);
            int col = warpN * 64 + nt * 8 + (lane & 3) * 2;
            sD[r0 * 129 + col]           = c[mt][nt][0];
            sD[r0 * 129 + col + 1]       = c[mt][nt][1];
            sD[(r0 + 8) * 129 + col]     = c[mt][nt][2];
            sD[(r0 + 8) * 129 + col + 1] = c[mt][nt][3];
        }
    }
    __syncthreads();

    for (int idx = tid; idx < 128 * 128; idx += 256) {
        int r = idx >> 7, cc = idx & 127;
        float v = sD[r * 129 + cc];
        size_t row = (size_t)(bm + r);
        int gc = bn + cc;
        if (mode == 3) {
            outF[row * N + gc] = v;
            continue;
        }
        v += bias[gc];
        if (mode == 0) {
            outF[row * N + gc] = v;
        } else if (mode == 1) {
            v = gelu_tanh(v);
            __nv_bfloat16 h, l; split_bf16(v, h, l);
            outHi[row * N + gc] = h;
            outLo[row * N + gc] = l;
        } else {
            if (gc < DM) {
                outF[row * DM + gc] = v * 0.125f;
            } else {
                __nv_bfloat16 h, l; split_bf16(v, h, l);
                size_t o = row * KVW + (gc - DM);
                outHi[o] = h; outLo[o] = l;
            }
        }
    }
}

// ================= HMMA sliding-window attention (R6 exact: 128 thr, 4 warps) ====
#define AQH 0
#define AQL 8192
#define AKH 16384
#define AKL 40960
#define AVH 65536
#define AVL 90112
#define ATTN_SMEM 114688
__global__ void __launch_bounds__(128, 1)
attn_kernel(const float* __restrict__ qf,
            const __nv_bfloat16* __restrict__ kvh,
            const __nv_bfloat16* __restrict__ kvl,
            float* __restrict__ out) {
    extern __shared__ char smem[];
    const uint32_t sb = smem_to_u32(smem);
    const int c = blockIdx.x, h = blockIdx.y, b = blockIdx.z;
    const int tid = threadIdx.x, warp = tid >> 5, lane = tid & 31;

    for (int idx = tid; idx < 64 * 16; idx += 128) {
        int r = idx >> 4, ch = idx & 15;
        float4 v = *reinterpret_cast<const float4*>(
            &qf[((size_t)b * SS + c * 64 + r) * DM + h * HD + ch * 4]);
        uint32_t off = SMEM_SWIZZLE_128B((uint32_t)(r * 128 + ch * 8));
        uint2 hh, ll;
        hh.x = pack_hi(v.x, v.y); hh.y = pack_hi(v.z, v.w);
        ll.x = pack_lo(v.x, v.y); ll.y = pack_lo(v.z, v.w);
        *reinterpret_cast<uint2*>(smem + AQH + off) = hh;
        *reinterpret_cast<uint2*>(smem + AQL + off) = ll;
    }
    for (int idx = tid; idx < 192 * 8; idx += 128) {
        int j = idx >> 3, ch = idx & 7;
        int g = c * 64 - 64 + j;
        uint4 z = {0, 0, 0, 0};
        uint4 kh4 = z, kl4 = z, vh4 = z, vl4 = z;
        if (g >= 0 && g < SS) {
            size_t rb = ((size_t)b * SS + g) * KVW + h * HD + ch * 8;
            kh4 = *reinterpret_cast<const uint4*>(&kvh[rb]);
            kl4 = *reinterpret_cast<const uint4*>(&kvl[rb]);
            vh4 = *reinterpret_cast<const uint4*>(&kvh[rb + DM]);
            vl4 = *reinterpret_cast<const uint4*>(&kvl[rb + DM]);
        }
        uint32_t off = SMEM_SWIZZLE_128B((uint32_t)(j * 128 + ch * 16));
        *reinterpret_cast<uint4*>(smem + AKH + off) = kh4;
        *reinterpret_cast<uint4*>(smem + AKL + off) = kl4;
        *reinterpret_cast<uint4*>(smem + AVH + off) = vh4;
        *reinterpret_cast<uint4*>(smem + AVL + off) = vl4;
    }
    __syncthreads();

    const int m0 = warp * 16;
    const int lrow = lane & 15;
    const int lch = lane >> 4;

    float s[24][4];
    #pragma unroll
    for (int nt = 0; nt < 24; nt++)
        #pragma unroll
        for (int u = 0; u < 4; u++) s[nt][u] = 0.f;

    #pragma unroll
    for (int ks = 0; ks < 4; ks++) {
        uint32_t aoff = SMEM_SWIZZLE_128B((uint32_t)((m0 + lrow) * 128 + ks * 32 + lch * 16));
        uint32_t ah[4], al[4];
        ldsm_x4(ah, sb + AQH + aoff);
        ldsm_x4(al, sb + AQL + aoff);
        #pragma unroll
        for (int n6 = 0; n6 < 12; n6++) {
            uint32_t boff = SMEM_SWIZZLE_128B((uint32_t)((n6 * 16 + lrow) * 128 + ks * 32 + lch * 16));
            uint32_t bh[4], bl[4];
            ldsm_x4(bh, sb + AKH + boff);
            ldsm_x4(bl, sb + AKL + boff);
            mma_bf16(s[2*n6],   ah, bh[0], bh[2]);
            mma_bf16(s[2*n6+1], ah, bh[1], bh[3]);
            mma_bf16(s[2*n6],   ah, bl[0], bl[2]);
            mma_bf16(s[2*n6+1], ah, bl[1], bl[3]);
            mma_bf16(s[2*n6],   al, bh[0], bh[2]);
            mma_bf16(s[2*n6+1], al, bh[1], bh[3]);
        }
    }

    const int rA = m0 + (lane >> 2);
    const int rB = rA + 8;
    const int jb = 2 * (lane & 3);
    const int gof = c * 64 - 64;
    float mA = -INFINITY, mB = -INFINITY;
    #pragma unroll
    for (int nt = 0; nt < 24; nt++) {
        int j0 = nt * 8 + jb, j1 = j0 + 1;
        int g0 = gof + j0, g1 = gof + j1;
        bool in0 = (g0 >= 0) && (g0 < SS);
        bool in1 = (g1 >= 0) && (g1 < SS);
        if (!((j0 >= rA) && (j0 <= rA + 128) && in0)) s[nt][0] = -INFINITY;
        if (!((j1 >= rA) && (j1 <= rA + 128) && in1)) s[nt][1] = -INFINITY;
        if (!((j0 >= rB) && (j0 <= rB + 128) && in0)) s[nt][2] = -INFINITY;
        if (!((j1 >= rB) && (j1 <= rB + 128) && in1)) s[nt][3] = -INFINITY;
        mA = fmaxf(mA, fmaxf(s[nt][0], s[nt][1]));
        mB = fmaxf(mB, fmaxf(s[nt][2], s[nt][3]));
    }
    mA = fmaxf(mA, __shfl_xor_sync(0xffffffffu, mA, 1));
    mA = fmaxf(mA, __shfl_xor_sync(0xffffffffu, mA, 2));
    mB = fmaxf(mB, __shfl_xor_sync(0xffffffffu, mB, 1));
    mB = fmaxf(mB, __shfl_xor_sync(0xffffffffu, mB, 2));
    float sA = 0.f, sB = 0.f;
    #pragma unroll
    for (int nt = 0; nt < 24; nt++) {
        s[nt][0] = __expf(s[nt][0] - mA);
        s[nt][1] = __expf(s[nt][1] - mA);
        s[nt][2] = __expf(s[nt][2] - mB);
        s[nt][3] = __expf(s[nt][3] - mB);
        sA += s[nt][0] + s[nt][1];
        sB += s[nt][2] + s[nt][3];
    }
    sA += __shfl_xor_sync(0xffffffffu, sA, 1);
    sA += __shfl_xor_sync(0xffffffffu, sA, 2);
    sB += __shfl_xor_sync(0xffffffffu, sB, 1);
    sB += __shfl_xor_sync(0xffffffffu, sB, 2);
    const float invA = 1.0f / sA, invB = 1.0f / sB;

    float o[8][4];
    #pragma unroll
    for (int nt = 0; nt < 8; nt++)
        #pragma unroll
        for (int u = 0; u < 4; u++) o[nt][u] = 0.f;

    #pragma unroll
    for (int t = 0; t < 12; t++) {
        uint32_t ph[4], pl[4];
        ph[0] = pack_hi(s[2*t][0],   s[2*t][1]);
        ph[1] = pack_hi(s[2*t][2],   s[2*t][3]);
        ph[2] = pack_hi(s[2*t+1][0], s[2*t+1][1]);
        ph[3] = pack_hi(s[2*t+1][2], s[2*t+1][3]);
        pl[0] = pack_lo(s[2*t][0],   s[2*t][1]);
        pl[1] = pack_lo(s[2*t][2],   s[2*t][3]);
        pl[2] = pack_lo(s[2*t+1][0], s[2*t+1][1]);
        pl[3] = pack_lo(s[2*t+1][2], s[2*t+1][3]);
        #pragma unroll
        for (int nn = 0; nn < 4; nn++) {
            uint32_t voff = SMEM_SWIZZLE_128B(
                (uint32_t)((t * 16 + (lane & 15)) * 128 + (nn * 16 + (lane >> 4) * 8) * 2));
            uint32_t vh[4], vl[4];
            ldsm_x4_trans(vh, sb + AVH + voff);
            ldsm_x4_trans(vl, sb + AVL + voff);
            mma_bf16(o[2*nn],   ph, vh[0], vh[1]);
            mma_bf16(o[2*nn+1], ph, vh[2], vh[3]);
            mma_bf16(o[2*nn],   ph, vl[0], vl[1]);
            mma_bf16(o[2*nn+1], ph, vl[2], vl[3]);
            mma_bf16(o[2*nn],   pl, vh[0], vh[1]);
            mma_bf16(o[2*nn+1], pl, vh[2], vh[3]);
        }
    }

    const size_t rowg = (size_t)b * SS + c * 64;
    #pragma unroll
    for (int nt = 0; nt < 8; nt++) {
        int col = h * HD + nt * 8 + jb;
        float2 v0 = make_float2(o[nt][0] * invA, o[nt][1] * invA);
        float2 v1 = make_float2(o[nt][2] * invB, o[nt][3] * invB);
        *reinterpret_cast<float2*>(&out[(rowg + rA) * DM + col]) = v0;
        *reinterpret_cast<float2*>(&out[(rowg + rB) * DM + col]) = v1;
    }
}

// ================= warp-per-row residual + LayerNorm =================
__global__ void __launch_bounds__(256)
add_ln_kernel(const float* __restrict__ a,
              const float* __restrict__ r,
              const float* __restrict__ g,
              const float* __restrict__ beta,
              float* __restrict__ out,
              __nv_bfloat16* __restrict__ outHi,
              __nv_bfloat16* __restrict__ outLo) {
    const int warp = threadIdx.x >> 5, lane = threadIdx.x & 31;
    const int row = blockIdx.x * 8 + warp;
    const float4* pa = reinterpret_cast<const float4*>(a + (size_t)row * DM);
    const float4* pr = reinterpret_cast<const float4*>(r + (size_t)row * DM);
    const float4* pg = reinterpret_cast<const float4*>(g);
    const float4* pb = reinterpret_cast<const float4*>(beta);

    float4 v[6];
    float sum = 0.f;
    #pragma unroll
    for (int ch = 0; ch < 6; ch++) {
        float4 va = pa[lane + 32 * ch];
        float4 vr = pr[lane + 32 * ch];
        v[ch] = make_float4(va.x + vr.x, va.y + vr.y, va.z + vr.z, va.w + vr.w);
        sum += v[ch].x + v[ch].y + v[ch].z + v[ch].w;
    }
    #pragma unroll
    for (int o = 16; o > 0; o >>= 1) sum += __shfl_xor_sync(0xffffffffu, sum, o);
    float mu = sum * (1.0f / DM);

    float var = 0.f;
    #pragma unroll
    for (int ch = 0; ch < 6; ch++) {
        float dx = v[ch].x - mu, dy = v[ch].y - mu, dz = v[ch].z - mu, dw = v[ch].w - mu;
        var += dx * dx + dy * dy + dz * dz + dw * dw;
    }
    #pragma unroll
    for (int o = 16; o > 0; o >>= 1) var += __shfl_xor_sync(0xffffffffu, var, o);
    float rstd = rsqrtf(var * (1.0f / DM) + 1e-5f);

    float4* po = reinterpret_cast<float4*>(out + (size_t)row * DM);
    #pragma unroll
    for (int ch = 0; ch < 6; ch++) {
        float4 gg = pg[lane + 32 * ch];
        float4 bb = pb[lane + 32 * ch];
        float4 y;
        y.x = (v[ch].x - mu) * rstd * gg.x + bb.x;
        y.y = (v[ch].y - mu) * rstd * gg.y + bb.y;
        y.z = (v[ch].z - mu) * rstd * gg.z + bb.z;
        y.w = (v[ch].w - mu) * rstd * gg.w + bb.w;
        po[lane + 32 * ch] = y;
        if (outHi) {
            size_t o4 = (size_t)row * DM + (lane + 32 * ch) * 4;
            __nv_bfloat16 h0,l0,h1,l1,h2,l2,h3,l3;
            split_bf16(y.x, h0, l0); split_bf16(y.y, h1, l1);
            split_bf16(y.z, h2, l2); split_bf16(y.w, h3, l3);
            reinterpret_cast<__nv_bfloat162*>(outHi + o4)[0] = __nv_bfloat162(h0, h1);
            reinterpret_cast<__nv_bfloat162*>(outHi + o4)[1] = __nv_bfloat162(h2, h3);
            reinterpret_cast<__nv_bfloat162*>(outLo + o4)[0] = __nv_bfloat162(l0, l1);
            reinterpret_cast<__nv_bfloat162*>(outLo + o4)[1] = __nv_bfloat162(l2, l3);
        }
    }
}

// ===== final LN: out = LN(p0+p1+p2 + bias2 + x1) (sums FFN2 split-K partials) ===
__global__ void __launch_bounds__(256)
add_ln3_kernel(const float* __restrict__ p,
               const float* __restrict__ r,
               const float* __restrict__ bias2,
               const float* __restrict__ g,
               const float* __restrict__ beta,
               float* __restrict__ out) {
    const int warp = threadIdx.x >> 5, lane = threadIdx.x & 31;
    const int row = blockIdx.x * 8 + warp;
    const float4* p0 = reinterpret_cast<const float4*>(p + (size_t)row * DM);
    const float4* p1 = reinterpret_cast<const float4*>(p + (size_t)row * DM + MD);
    const float4* p2 = reinterpret_cast<const float4*>(p + (size_t)row * DM + 2 * (size_t)MD);
    const float4* pr = reinterpret_cast<const float4*>(r + (size_t)row * DM);
    const float4* pb2 = reinterpret_cast<const float4*>(bias2);
    const float4* pg = reinterpret_cast<const float4*>(g);
    const float4* pb = reinterpret_cast<const float4*>(beta);

    float4 v[6];
    float sum = 0.f;
    #pragma unroll
    for (int ch = 0; ch < 6; ch++) {
        float4 a0 = p0[lane + 32 * ch];
        float4 a1 = p1[lane + 32 * ch];
        float4 a2 = p2[lane + 32 * ch];
        float4 vr = pr[lane + 32 * ch];
        float4 b2 = pb2[lane + 32 * ch];
        v[ch] = make_float4(a0.x + a1.x + a2.x + b2.x + vr.x,
                            a0.y + a1.y + a2.y + b2.y + vr.y,
                            a0.z + a1.z + a2.z + b2.z + vr.z,
                            a0.w + a1.w + a2.w + b2.w + vr.w);
        sum += v[ch].x + v[ch].y + v[ch].z + v[ch].w;
    }
    #pragma unroll
    for (int o = 16; o > 0; o >>= 1) sum += __shfl_xor_sync(0xffffffffu, sum, o);
    float mu = sum * (1.0f / DM);

    float var = 0.f;
    #pragma unroll
    for (int ch = 0; ch < 6; ch++) {
        float dx = v[ch].x - mu, dy = v[ch].y - mu, dz = v[ch].z - mu, dw = v[ch].w - mu;
        var += dx * dx + dy * dy + dz * dz + dw * dw;
    }
    #pragma unroll
    for (int o = 16; o > 0; o >>= 1) var += __shfl_xor_sync(0xffffffffu, var, o);
    float rstd = rsqrtf(var * (1.0f / DM) + 1e-5f);

    float4* po = reinterpret_cast<float4*>(out + (size_t)row * DM);
    #pragma unroll
    for (int ch = 0; ch < 6; ch++) {
        float4 gg = pg[lane + 32 * ch];
        float4 bb = pb[lane + 32 * ch];
        float4 y;
        y.x = (v[ch].x - mu) * rstd * gg.x + bb.x;
        y.y = (v[ch].y - mu) * rstd * gg.y + bb.y;
        y.z = (v[ch].z - mu) * rstd * gg.z + bb.z;
        y.w = (v[ch].w - mu) * rstd * gg.w + bb.w;
        po[lane + 32 * ch] = y;
    }
}

// ================= launch =================
extern "C" void kernel_launch(void* const* d_in, const int* in_sizes, int n_in,
                              void* d_out, int out_size) {
    const float* x     = (const float*)d_in[0];
    const float* Wq    = (const float*)d_in[1];
    const float* bq    = (const float*)d_in[2];
    const float* Wk    = (const float*)d_in[3];
    const float* bk    = (const float*)d_in[4];
    const float* Wv    = (const float*)d_in[5];
    const float* bv    = (const float*)d_in[6];
    const float* ln1_g = (const float*)d_in[7];
    const float* ln1_b = (const float*)d_in[8];
    const float* W1    = (const float*)d_in[9];
    const float* b1    = (const float*)d_in[10];
    const float* W2    = (const float*)d_in[11];
    const float* b2    = (const float*)d_in[12];
    const float* ln2_g = (const float*)d_in[13];
    const float* ln2_b = (const float*)d_in[14];
    float* out = (float*)d_out;

    float *qf, *attn, *x1, *ffp, *bqkv;
    __nv_bfloat16 *kvh, *kvl, *xh, *xl, *x1h, *x1l, *hidh, *hidl;
    __nv_bfloat16 *wqkvh, *wqkvl, *w1h, *w1l, *w2h, *w2l;
    cudaGetSymbolAddress((void**)&qf, g_qf);     cudaGetSymbolAddress((void**)&attn, g_attn);
    cudaGetSymbolAddress((void**)&x1, g_x1);     cudaGetSymbolAddress((void**)&ffp, g_ffp);
    cudaGetSymbolAddress((void**)&bqkv, g_bqkv);
    cudaGetSymbolAddress((void**)&kvh, g_kvh);   cudaGetSymbolAddress((void**)&kvl, g_kvl);
    cudaGetSymbolAddress((void**)&xh, g_xh);     cudaGetSymbolAddress((void**)&xl, g_xl);
    cudaGetSymbolAddress((void**)&x1h, g_x1h);   cudaGetSymbolAddress((void**)&x1l, g_x1l);
    cudaGetSymbolAddress((void**)&hidh, g_hidh); cudaGetSymbolAddress((void**)&hidl, g_hidl);
    cudaGetSymbolAddress((void**)&wqkvh, g_wqkvh); cudaGetSymbolAddress((void**)&wqkvl, g_wqkvl);
    cudaGetSymbolAddress((void**)&w1h, g_w1h);   cudaGetSymbolAddress((void**)&w1l, g_w1l);
    cudaGetSymbolAddress((void**)&w2h, g_w2h);   cudaGetSymbolAddress((void**)&w2l, g_w2l);

    cudaFuncSetAttribute(tc_gemm, cudaFuncAttributeMaxDynamicSharedMemorySize, GEMM_SMEM);
    cudaFuncSetAttribute(attn_kernel, cudaFuncAttributeMaxDynamicSharedMemorySize, ATTN_SMEM);

    // ---- convert inputs ----
    {
        int n4 = MROWS * DM / 4;
        split_convert<<<(n4 + 255) / 256, 256>>>(x, xh, xl, n4);
        prep_weights<<<6345, 256>>>(Wq, Wk, Wv, W1, W2, bq, bk, bv,
                                    wqkvh, wqkvl, w1h, w1l, w2h, w2l, bqkv);
    }

    // ---- fused QKV projection: q fp32 (scaled), k/v bf16 hi/lo ----
    {
        dim3 grid(QKVN / 128, MROWS / 128);
        tc_gemm<<<grid, 256, GEMM_SMEM>>>(xh, xl, wqkvh, wqkvl, bqkv, qf,
                                          kvh, kvl, MROWS, QKVN, DM, 2);
    }

    // ---- attention (HMMA, R6 config) ----
    {
        dim3 grid(NC, NH, BB);
        attn_kernel<<<grid, 128, ATTN_SMEM>>>(qf, kvh, kvl, attn);
    }

    // ---- x1 = LN(attn + x), emit bf16 hi/lo ----
    add_ln_kernel<<<MROWS / 8, 256>>>(attn, x, ln1_g, ln1_b, x1, x1h, x1l);

    // ---- FFN ----
    {
        dim3 grid1(FF / 128, MROWS / 128);
        tc_gemm<<<grid1, 256, GEMM_SMEM>>>(x1h, x1l, w1h, w1l, b1, nullptr,
                                           hidh, hidl, MROWS, FF, DM, 1);
        dim3 grid2(DM / 128, MROWS / 128, 3);   // split-K = 3
        tc_gemm<<<grid2, 256, GEMM_SMEM>>>(hidh, hidl, w2h, w2l, nullptr, ffp,
                                           nullptr, nullptr, MROWS, DM, FF, 3);
    }

    // ---- out = LN(p0+p1+p2 + b2 + x1) ----
    add_ln3_kernel<<<MROWS / 8, 256>>>(ffp, x1, b2, ln2_g, ln2_b, out);
}

// round 10
// speedup vs baseline: 1.3343x; 1.2829x over previous
#include <cuda_runtime.h>
#include <cuda_bf16.h>
#include <cuda_fp16.h>
#include <math.h>
#include <cstdint>

#define BB 2
#define SS 4096
#define DM 768
#define NH 12
#define FF 3072
#define WIN 64
#define HD 64
#define NC (SS / WIN)
#define MROWS (BB * SS)    // 8192
#define QKVN (3 * DM)      // 2304
#define KVW (2 * DM)       // 1536
#define MD (MROWS * DM)

// ================= helpers =================
__device__ __forceinline__ uint32_t smem_to_u32(const void* p) {
    uint32_t a;
    asm("{ .reg .u64 t; cvta.to.shared.u64 t, %1; cvt.u32.u64 %0, t; }" : "=r"(a) : "l"(p));
    return a;
}
#define SMEM_SWIZZLE_128B(o) ((o) ^ (((o) >> 3) & 0x70))

__device__ __forceinline__ void ldsm_x4(uint32_t r[4], uint32_t addr) {
    asm volatile("ldmatrix.sync.aligned.m8n8.x4.shared.b16 {%0,%1,%2,%3}, [%4];"
        : "=r"(r[0]), "=r"(r[1]), "=r"(r[2]), "=r"(r[3]) : "r"(addr));
}
__device__ __forceinline__ void ldsm_x4_trans(uint32_t r[4], uint32_t addr) {
    asm volatile("ldmatrix.sync.aligned.m8n8.x4.trans.shared.b16 {%0,%1,%2,%3}, [%4];"
        : "=r"(r[0]), "=r"(r[1]), "=r"(r[2]), "=r"(r[3]) : "r"(addr));
}
__device__ __forceinline__ void mma_bf16(float c[4], const uint32_t a[4],
                                         uint32_t b0, uint32_t b1) {
    asm volatile("mma.sync.aligned.m16n8k16.row.col.f32.bf16.bf16.f32 "
        "{%0,%1,%2,%3}, {%4,%5,%6,%7}, {%8,%9}, {%0,%1,%2,%3};"
        : "+f"(c[0]), "+f"(c[1]), "+f"(c[2]), "+f"(c[3])
        : "r"(a[0]), "r"(a[1]), "r"(a[2]), "r"(a[3]), "r"(b0), "r"(b1));
}
__device__ __forceinline__ void mma_fp16(float c[4], const uint32_t a[4],
                                         uint32_t b0, uint32_t b1) {
    asm volatile("mma.sync.aligned.m16n8k16.row.col.f32.f16.f16.f32 "
        "{%0,%1,%2,%3}, {%4,%5,%6,%7}, {%8,%9}, {%0,%1,%2,%3};"
        : "+f"(c[0]), "+f"(c[1]), "+f"(c[2]), "+f"(c[3])
        : "r"(a[0]), "r"(a[1]), "r"(a[2]), "r"(a[3]), "r"(b0), "r"(b1));
}
__device__ __forceinline__ void split_bf16(float v, __nv_bfloat16& h, __nv_bfloat16& l) {
    h = __float2bfloat16(v);
    l = __float2bfloat16(v - __bfloat162float(h));
}
__device__ __forceinline__ void split_half(float v, __half& h, __half& l) {
    h = __float2half(v);
    l = __float2half(v - __half2float(h));
}
__device__ __forceinline__ uint32_t pack_hi(float x, float y) {
    __nv_bfloat162 t(__float2bfloat16(x), __float2bfloat16(y));
    return *reinterpret_cast<uint32_t*>(&t);
}
__device__ __forceinline__ uint32_t pack_lo(float x, float y) {
    __nv_bfloat16 hx = __float2bfloat16(x), hy = __float2bfloat16(y);
    __nv_bfloat162 t(__float2bfloat16(x - __bfloat162float(hx)),
                     __float2bfloat16(y - __bfloat162float(hy)));
    return *reinterpret_cast<uint32_t*>(&t);
}
__device__ __forceinline__ float gelu_tanh(float x) {
    const float c = 0.7978845608028654f;
    float x3 = x * x * x;
    return 0.5f * x * (1.0f + tanhf(c * (x + 0.044715f * x3)));
}

// ================= scratch =================
__device__ float g_qf[MD];
__device__ float g_attn[MD];
__device__ float g_x1[MD];
__device__ float g_ffp[3 * MD];
__device__ float g_bqkv[QKVN];
__device__ __nv_bfloat16 g_kvh[MROWS * KVW], g_kvl[MROWS * KVW];
__device__ __half g_xh[MD],  g_xl[MD];
__device__ __half g_x1h[MD], g_x1l[MD];
__device__ __half g_hidh[MROWS * FF], g_hidl[MROWS * FF];
__device__ __half g_wqkv[QKVN * DM];
__device__ __half g_w1[FF * DM];
__device__ __half g_w2[DM * FF];

// ========== elementwise fp32 -> fp16 hi/lo ==========
__global__ void split_convert(const float* __restrict__ in,
                              __half* __restrict__ hi,
                              __half* __restrict__ lo, int n4) {
    int i = blockIdx.x * blockDim.x + threadIdx.x;
    if (i >= n4) return;
    float4 v = reinterpret_cast<const float4*>(in)[i];
    __half h0,l0,h1,l1,h2,l2,h3,l3;
    split_half(v.x, h0, l0); split_half(v.y, h1, l1);
    split_half(v.z, h2, l2); split_half(v.w, h3, l3);
    reinterpret_cast<__half2*>(hi)[i*2+0] = __half2(h0, h1);
    reinterpret_cast<__half2*>(hi)[i*2+1] = __half2(h2, h3);
    reinterpret_cast<__half2*>(lo)[i*2+0] = __half2(l0, l1);
    reinterpret_cast<__half2*>(lo)[i*2+1] = __half2(l2, l3);
}

// ========== merged weight transpose (single fp16) + bias pack ==========
__global__ void prep_weights(const float* __restrict__ Wq, const float* __restrict__ Wk,
                             const float* __restrict__ Wv, const float* __restrict__ W1,
                             const float* __restrict__ W2,
                             const float* __restrict__ bq, const float* __restrict__ bk,
                             const float* __restrict__ bv,
                             __half* __restrict__ wqkv,
                             __half* __restrict__ w1,
                             __half* __restrict__ w2,
                             float* __restrict__ bqkv) {
    int id = blockIdx.x;
    if (id >= 6336) {
        int i = (id - 6336) * 256 + threadIdx.x;
        if (i < QKVN)
            bqkv[i] = (i < DM) ? bq[i] : (i < 2 * DM) ? bk[i - DM] : bv[i - 2 * DM];
        return;
    }
    const float* W; __half* T; int K, N, tix;
    if (id < 576)       { W = Wq; T = wqkv;               K = DM; N = DM; tix = id; }
    else if (id < 1152) { W = Wk; T = wqkv + DM * DM;     K = DM; N = DM; tix = id - 576; }
    else if (id < 1728) { W = Wv; T = wqkv + 2 * DM * DM; K = DM; N = DM; tix = id - 1152; }
    else if (id < 4032) { W = W1; T = w1;                 K = DM; N = FF; tix = id - 1728; }
    else                { W = W2; T = w2;                 K = FF; N = DM; tix = id - 4032; }
    int nt = N / 32;
    int n0 = (tix % nt) * 32, k0 = (tix / nt) * 32;
    __shared__ float t[32][33];
    int tx = threadIdx.x & 31, ty = threadIdx.x >> 5;
    #pragma unroll
    for (int i = 0; i < 4; i++)
        t[ty + i*8][tx] = W[(size_t)(k0 + ty + i*8) * N + n0 + tx];
    __syncthreads();
    #pragma unroll
    for (int i = 0; i < 4; i++) {
        T[(size_t)(n0 + ty + i*8) * K + k0 + tx] = __float2half(t[tx][ty + i*8]);
    }
}

// ========== HMMA GEMM: C = A @ B^T + bias, 2-term fp16 (Ah*B + Al*B) ==========
// A: fp16 hi/lo (activations, exact); B: single fp16 (weights).
// CTA 128x128, 8 warps 32x64, K-block 64, 3 stages x 48KB.
// mode 0: fp32+bias. mode 1: gelu + fp16 hi/lo. mode 2: QKV (q fp32*0.125,
// k/v bf16 hi/lo). mode 3: split-K partial fp32.
#define STAGE_BYTES 49152
#define GEMM_SMEM (3 * STAGE_BYTES)
__global__ void __launch_bounds__(256, 1)
tc_gemm(const __half* __restrict__ Ah, const __half* __restrict__ Al,
        const __half* __restrict__ B,
        const float* __restrict__ bias,
        float* __restrict__ outF,
        void* __restrict__ outHiV, void* __restrict__ outLoV,
        int M, int N, int K, int mode) {
    extern __shared__ char smem[];
    const uint32_t tiles = smem_to_u32(smem);
    const int tid = threadIdx.x;
    const int wid = tid >> 5;
    const int lane = tid & 31;
    const int warpM = wid >> 1;
    const int warpN = wid & 1;
    const int bm = blockIdx.y * 128;
    const int bn = blockIdx.x * 128;
    const int kb0 = (mode == 3) ? blockIdx.z * 16 : 0;
    const int NB  = (mode == 3) ? 16 : (K >> 6);
    if (mode == 3) outF += (size_t)blockIdx.z * M * N;

    const __half* srcs[3] = {Ah, Al, B};

    auto stage = [&](int kb, int s) {
        #pragma unroll
        for (int t = 0; t < 3; t++) {
            const __half* src = srcs[t];
            const int rbase = (t < 2) ? bm : bn;
            const uint32_t sb = tiles + (uint32_t)s * STAGE_BYTES + (uint32_t)t * 16384u;
            #pragma unroll
            for (int i = 0; i < 4; i++) {
                int chunk = tid + i * 256;
                int row = chunk >> 3;
                int c16 = chunk & 7;
                uint32_t off = (uint32_t)(row * 128 + c16 * 16);
                uint32_t dst = sb + SMEM_SWIZZLE_128B(off);
                const void* g = src + (size_t)(rbase + row) * K + kb * 64 + c16 * 8;
                asm volatile("cp.async.cg.shared.global [%0], [%1], 16;" :: "r"(dst), "l"(g));
            }
        }
        asm volatile("cp.async.commit_group;" ::: "memory");
    };

    float c[2][8][4] = {};

    stage(kb0, 0);
    if (NB > 1) stage(kb0 + 1, 1);

    const int lrow = lane & 15;
    const int lchunk = lane >> 4;

    for (int kb = 0; kb < NB; kb++) {
        const int s = kb % 3;
        if (kb + 1 < NB) asm volatile("cp.async.wait_group 1;" ::: "memory");
        else             asm volatile("cp.async.wait_group 0;" ::: "memory");
        __syncthreads();
        if (kb + 2 < NB) stage(kb0 + kb + 2, (kb + 2) % 3);

        const uint32_t base_s = tiles + (uint32_t)s * STAGE_BYTES;
        #pragma unroll
        for (int ks = 0; ks < 4; ks++) {
            uint32_t ah[2][4], al2[2][4];
            #pragma unroll
            for (int mt = 0; mt < 2; mt++) {
                uint32_t off = (uint32_t)((warpM * 32 + mt * 16 + lrow) * 128 + ks * 32 + lchunk * 16);
                uint32_t sw = SMEM_SWIZZLE_128B(off);
                ldsm_x4(ah[mt],  base_s + sw);
                ldsm_x4(al2[mt], base_s + 16384u + sw);
            }
            // B double-buffer: prefetch np+1 while issuing np's mma
            uint32_t bb[2][4];
            {
                uint32_t off0 = (uint32_t)((warpN * 64 + lrow) * 128 + ks * 32 + lchunk * 16);
                ldsm_x4(bb[0], base_s + 32768u + SMEM_SWIZZLE_128B(off0));
            }
            #pragma unroll
            for (int np = 0; np < 4; np++) {
                const int cur = np & 1;
                if (np < 3) {
                    uint32_t off = (uint32_t)((warpN * 64 + (np + 1) * 16 + lrow) * 128 + ks * 32 + lchunk * 16);
                    ldsm_x4(bb[cur ^ 1], base_s + 32768u + SMEM_SWIZZLE_128B(off));
                }
                #pragma unroll
                for (int mt = 0; mt < 2; mt++) {
                    mma_fp16(c[mt][2*np],   ah[mt],  bb[cur][0], bb[cur][2]);
                    mma_fp16(c[mt][2*np+1], ah[mt],  bb[cur][1], bb[cur][3]);
                    mma_fp16(c[mt][2*np],   al2[mt], bb[cur][0], bb[cur][2]);
                    mma_fp16(c[mt][2*np+1], al2[mt], bb[cur][1], bb[cur][3]);
                }
            }
        }
    }
    __syncthreads();

    float* sD = reinterpret_cast<float*>(smem);   // 128 x 129
    #pragma unroll
    for (int mt = 0; mt < 2; mt++) {
        #pragma unroll
        for (int nt = 0; nt < 8; nt++) {
            int r0 = warpM * 32 + mt * 16 + (lane >> 2);
            int col = warpN * 64 + nt * 8 + (lane & 3) * 2;
            sD[r0 * 129 + col]           = c[mt][nt][0];
            sD[r0 * 129 + col + 1]       = c[mt][nt][1];
            sD[(r0 + 8) * 129 + col]     = c[mt][nt][2];
            sD[(r0 + 8) * 129 + col + 1] = c[mt][nt][3];
        }
    }
    __syncthreads();

    for (int idx = tid; idx < 128 * 128; idx += 256) {
        int r = idx >> 7, cc = idx & 127;
        float v = sD[r * 129 + cc];
        size_t row = (size_t)(bm + r);
        int gc = bn + cc;
        if (mode == 3) {
            outF[row * N + gc] = v;
            continue;
        }
        v += bias[gc];
        if (mode == 0) {
            outF[row * N + gc] = v;
        } else if (mode == 1) {
            v = gelu_tanh(v);
            __half h, l; split_half(v, h, l);
            ((__half*)outHiV)[row * N + gc] = h;
            ((__half*)outLoV)[row * N + gc] = l;
        } else {
            if (gc < DM) {
                outF[row * DM + gc] = v * 0.125f;
            } else {
                __nv_bfloat16 h, l; split_bf16(v, h, l);
                size_t o = row * KVW + (gc - DM);
                ((__nv_bfloat16*)outHiV)[o] = h;
                ((__nv_bfloat16*)outLoV)[o] = l;
            }
        }
    }
}

// ================= HMMA sliding-window attention (R6 exact) =================
#define AQH 0
#define AQL 8192
#define AKH 16384
#define AKL 40960
#define AVH 65536
#define AVL 90112
#define ATTN_SMEM 114688
__global__ void __launch_bounds__(128, 1)
attn_kernel(const float* __restrict__ qf,
            const __nv_bfloat16* __restrict__ kvh,
            const __nv_bfloat16* __restrict__ kvl,
            float* __restrict__ out) {
    extern __shared__ char smem[];
    const uint32_t sb = smem_to_u32(smem);
    const int c = blockIdx.x, h = blockIdx.y, b = blockIdx.z;
    const int tid = threadIdx.x, warp = tid >> 5, lane = tid & 31;

    for (int idx = tid; idx < 64 * 16; idx += 128) {
        int r = idx >> 4, ch = idx & 15;
        float4 v = *reinterpret_cast<const float4*>(
            &qf[((size_t)b * SS + c * 64 + r) * DM + h * HD + ch * 4]);
        uint32_t off = SMEM_SWIZZLE_128B((uint32_t)(r * 128 + ch * 8));
        uint2 hh, ll;
        hh.x = pack_hi(v.x, v.y); hh.y = pack_hi(v.z, v.w);
        ll.x = pack_lo(v.x, v.y); ll.y = pack_lo(v.z, v.w);
        *reinterpret_cast<uint2*>(smem + AQH + off) = hh;
        *reinterpret_cast<uint2*>(smem + AQL + off) = ll;
    }
    for (int idx = tid; idx < 192 * 8; idx += 128) {
        int j = idx >> 3, ch = idx & 7;
        int g = c * 64 - 64 + j;
        uint4 z = {0, 0, 0, 0};
        uint4 kh4 = z, kl4 = z, vh4 = z, vl4 = z;
        if (g >= 0 && g < SS) {
            size_t rb = ((size_t)b * SS + g) * KVW + h * HD + ch * 8;
            kh4 = *reinterpret_cast<const uint4*>(&kvh[rb]);
            kl4 = *reinterpret_cast<const uint4*>(&kvl[rb]);
            vh4 = *reinterpret_cast<const uint4*>(&kvh[rb + DM]);
            vl4 = *reinterpret_cast<const uint4*>(&kvl[rb + DM]);
        }
        uint32_t off = SMEM_SWIZZLE_128B((uint32_t)(j * 128 + ch * 16));
        *reinterpret_cast<uint4*>(smem + AKH + off) = kh4;
        *reinterpret_cast<uint4*>(smem + AKL + off) = kl4;
        *reinterpret_cast<uint4*>(smem + AVH + off) = vh4;
        *reinterpret_cast<uint4*>(smem + AVL + off) = vl4;
    }
    __syncthreads();

    const int m0 = warp * 16;
    const int lrow = lane & 15;
    const int lch = lane >> 4;

    float s[24][4];
    #pragma unroll
    for (int nt = 0; nt < 24; nt++)
        #pragma unroll
        for (int u = 0; u < 4; u++) s[nt][u] = 0.f;

    #pragma unroll
    for (int ks = 0; ks < 4; ks++) {
        uint32_t aoff = SMEM_SWIZZLE_128B((uint32_t)((m0 + lrow) * 128 + ks * 32 + lch * 16));
        uint32_t ah[4], al[4];
        ldsm_x4(ah, sb + AQH + aoff);
        ldsm_x4(al, sb + AQL + aoff);
        #pragma unroll
        for (int n6 = 0; n6 < 12; n6++) {
            uint32_t boff = SMEM_SWIZZLE_128B((uint32_t)((n6 * 16 + lrow) * 128 + ks * 32 + lch * 16));
            uint32_t bh[4], bl[4];
            ldsm_x4(bh, sb + AKH + boff);
            ldsm_x4(bl, sb + AKL + boff);
            mma_bf16(s[2*n6],   ah, bh[0], bh[2]);
            mma_bf16(s[2*n6+1], ah, bh[1], bh[3]);
            mma_bf16(s[2*n6],   ah, bl[0], bl[2]);
            mma_bf16(s[2*n6+1], ah, bl[1], bl[3]);
            mma_bf16(s[2*n6],   al, bh[0], bh[2]);
            mma_bf16(s[2*n6+1], al, bh[1], bh[3]);
        }
    }

    const int rA = m0 + (lane >> 2);
    const int rB = rA + 8;
    const int jb = 2 * (lane & 3);
    const int gof = c * 64 - 64;
    float mA = -INFINITY, mB = -INFINITY;
    #pragma unroll
    for (int nt = 0; nt < 24; nt++) {
        int j0 = nt * 8 + jb, j1 = j0 + 1;
        int g0 = gof + j0, g1 = gof + j1;
        bool in0 = (g0 >= 0) && (g0 < SS);
        bool in1 = (g1 >= 0) && (g1 < SS);
        if (!((j0 >= rA) && (j0 <= rA + 128) && in0)) s[nt][0] = -INFINITY;
        if (!((j1 >= rA) && (j1 <= rA + 128) && in1)) s[nt][1] = -INFINITY;
        if (!((j0 >= rB) && (j0 <= rB + 128) && in0)) s[nt][2] = -INFINITY;
        if (!((j1 >= rB) && (j1 <= rB + 128) && in1)) s[nt][3] = -INFINITY;
        mA = fmaxf(mA, fmaxf(s[nt][0], s[nt][1]));
        mB = fmaxf(mB, fmaxf(s[nt][2], s[nt][3]));
    }
    mA = fmaxf(mA, __shfl_xor_sync(0xffffffffu, mA, 1));
    mA = fmaxf(mA, __shfl_xor_sync(0xffffffffu, mA, 2));
    mB = fmaxf(mB, __shfl_xor_sync(0xffffffffu, mB, 1));
    mB = fmaxf(mB, __shfl_xor_sync(0xffffffffu, mB, 2));
    float sA = 0.f, sB = 0.f;
    #pragma unroll
    for (int nt = 0; nt < 24; nt++) {
        s[nt][0] = __expf(s[nt][0] - mA);
        s[nt][1] = __expf(s[nt][1] - mA);
        s[nt][2] = __expf(s[nt][2] - mB);
        s[nt][3] = __expf(s[nt][3] - mB);
        sA += s[nt][0] + s[nt][1];
        sB += s[nt][2] + s[nt][3];
    }
    sA += __shfl_xor_sync(0xffffffffu, sA, 1);
    sA += __shfl_xor_sync(0xffffffffu, sA, 2);
    sB += __shfl_xor_sync(0xffffffffu, sB, 1);
    sB += __shfl_xor_sync(0xffffffffu, sB, 2);
    const float invA = 1.0f / sA, invB = 1.0f / sB;

    float o[8][4];
    #pragma unroll
    for (int nt = 0; nt < 8; nt++)
        #pragma unroll
        for (int u = 0; u < 4; u++) o[nt][u] = 0.f;

    #pragma unroll
    for (int t = 0; t < 12; t++) {
        uint32_t ph[4], pl[4];
        ph[0] = pack_hi(s[2*t][0],   s[2*t][1]);
        ph[1] = pack_hi(s[2*t][2],   s[2*t][3]);
        ph[2] = pack_hi(s[2*t+1][0], s[2*t+1][1]);
        ph[3] = pack_hi(s[2*t+1][2], s[2*t+1][3]);
        pl[0] = pack_lo(s[2*t][0],   s[2*t][1]);
        pl[1] = pack_lo(s[2*t][2],   s[2*t][3]);
        pl[2] = pack_lo(s[2*t+1][0], s[2*t+1][1]);
        pl[3] = pack_lo(s[2*t+1][2], s[2*t+1][3]);
        #pragma unroll
        for (int nn = 0; nn < 4; nn++) {
            uint32_t voff = SMEM_SWIZZLE_128B(
                (uint32_t)((t * 16 + (lane & 15)) * 128 + (nn * 16 + (lane >> 4) * 8) * 2));
            uint32_t vh[4], vl[4];
            ldsm_x4_trans(vh, sb + AVH + voff);
            ldsm_x4_trans(vl, sb + AVL + voff);
            mma_bf16(o[2*nn],   ph, vh[0], vh[1]);
            mma_bf16(o[2*nn+1], ph, vh[2], vh[3]);
            mma_bf16(o[2*nn],   ph, vl[0], vl[1]);
            mma_bf16(o[2*nn+1], ph, vl[2], vl[3]);
            mma_bf16(o[2*nn],   pl, vh[0], vh[1]);
            mma_bf16(o[2*nn+1], pl, vh[2], vh[3]);
        }
    }

    const size_t rowg = (size_t)b * SS + c * 64;
    #pragma unroll
    for (int nt = 0; nt < 8; nt++) {
        int col = h * HD + nt * 8 + jb;
        float2 v0 = make_float2(o[nt][0] * invA, o[nt][1] * invA);
        float2 v1 = make_float2(o[nt][2] * invB, o[nt][3] * invB);
        *reinterpret_cast<float2*>(&out[(rowg + rA) * DM + col]) = v0;
        *reinterpret_cast<float2*>(&out[(rowg + rB) * DM + col]) = v1;
    }
}

// ================= warp-per-row residual + LayerNorm (fp16 hi/lo emit) ==========
__global__ void __launch_bounds__(256)
add_ln_kernel(const float* __restrict__ a,
              const float* __restrict__ r,
              const float* __restrict__ g,
              const float* __restrict__ beta,
              float* __restrict__ out,
              __half* __restrict__ outHi,
              __half* __restrict__ outLo) {
    const int warp = threadIdx.x >> 5, lane = threadIdx.x & 31;
    const int row = blockIdx.x * 8 + warp;
    const float4* pa = reinterpret_cast<const float4*>(a + (size_t)row * DM);
    const float4* pr = reinterpret_cast<const float4*>(r + (size_t)row * DM);
    const float4* pg = reinterpret_cast<const float4*>(g);
    const float4* pb = reinterpret_cast<const float4*>(beta);

    float4 v[6];
    float sum = 0.f;
    #pragma unroll
    for (int ch = 0; ch < 6; ch++) {
        float4 va = pa[lane + 32 * ch];
        float4 vr = pr[lane + 32 * ch];
        v[ch] = make_float4(va.x + vr.x, va.y + vr.y, va.z + vr.z, va.w + vr.w);
        sum += v[ch].x + v[ch].y + v[ch].z + v[ch].w;
    }
    #pragma unroll
    for (int o = 16; o > 0; o >>= 1) sum += __shfl_xor_sync(0xffffffffu, sum, o);
    float mu = sum * (1.0f / DM);

    float var = 0.f;
    #pragma unroll
    for (int ch = 0; ch < 6; ch++) {
        float dx = v[ch].x - mu, dy = v[ch].y - mu, dz = v[ch].z - mu, dw = v[ch].w - mu;
        var += dx * dx + dy * dy + dz * dz + dw * dw;
    }
    #pragma unroll
    for (int o = 16; o > 0; o >>= 1) var += __shfl_xor_sync(0xffffffffu, var, o);
    float rstd = rsqrtf(var * (1.0f / DM) + 1e-5f);

    float4* po = reinterpret_cast<float4*>(out + (size_t)row * DM);
    #pragma unroll
    for (int ch = 0; ch < 6; ch++) {
        float4 gg = pg[lane + 32 * ch];
        float4 bb = pb[lane + 32 * ch];
        float4 y;
        y.x = (v[ch].x - mu) * rstd * gg.x + bb.x;
        y.y = (v[ch].y - mu) * rstd * gg.y + bb.y;
        y.z = (v[ch].z - mu) * rstd * gg.z + bb.z;
        y.w = (v[ch].w - mu) * rstd * gg.w + bb.w;
        po[lane + 32 * ch] = y;
        if (outHi) {
            size_t o4 = (size_t)row * DM + (lane + 32 * ch) * 4;
            __half h0,l0,h1,l1,h2,l2,h3,l3;
            split_half(y.x, h0, l0); split_half(y.y, h1, l1);
            split_half(y.z, h2, l2); split_half(y.w, h3, l3);
            reinterpret_cast<__half2*>(outHi + o4)[0] = __half2(h0, h1);
            reinterpret_cast<__half2*>(outHi + o4)[1] = __half2(h2, h3);
            reinterpret_cast<__half2*>(outLo + o4)[0] = __half2(l0, l1);
            reinterpret_cast<__half2*>(outLo + o4)[1] = __half2(l2, l3);
        }
    }
}

// ===== final LN: out = LN(p0+p1+p2 + bias2 + x1) =====
__global__ void __launch_bounds__(256)
add_ln3_kernel(const float* __restrict__ p,
               const float* __restrict__ r,
               const float* __restrict__ bias2,
               const float* __restrict__ g,
               const float* __restrict__ beta,
               float* __restrict__ out) {
    const int warp = threadIdx.x >> 5, lane = threadIdx.x & 31;
    const int row = blockIdx.x * 8 + warp;
    const float4* p0 = reinterpret_cast<const float4*>(p + (size_t)row * DM);
    const float4* p1 = reinterpret_cast<const float4*>(p + (size_t)row * DM + MD);
    const float4* p2 = reinterpret_cast<const float4*>(p + (size_t)row * DM + 2 * (size_t)MD);
    const float4* pr = reinterpret_cast<const float4*>(r + (size_t)row * DM);
    const float4* pb2 = reinterpret_cast<const float4*>(bias2);
    const float4* pg = reinterpret_cast<const float4*>(g);
    const float4* pb = reinterpret_cast<const float4*>(beta);

    float4 v[6];
    float sum = 0.f;
    #pragma unroll
    for (int ch = 0; ch < 6; ch++) {
        float4 a0 = p0[lane + 32 * ch];
        float4 a1 = p1[lane + 32 * ch];
        float4 a2 = p2[lane + 32 * ch];
        float4 vr = pr[lane + 32 * ch];
        float4 b2 = pb2[lane + 32 * ch];
        v[ch] = make_float4(a0.x + a1.x + a2.x + b2.x + vr.x,
                            a0.y + a1.y + a2.y + b2.y + vr.y,
                            a0.z + a1.z + a2.z + b2.z + vr.z,
                            a0.w + a1.w + a2.w + b2.w + vr.w);
        sum += v[ch].x + v[ch].y + v[ch].z + v[ch].w;
    }
    #pragma unroll
    for (int o = 16; o > 0; o >>= 1) sum += __shfl_xor_sync(0xffffffffu, sum, o);
    float mu = sum * (1.0f / DM);

    float var = 0.f;
    #pragma unroll
    for (int ch = 0; ch < 6; ch++) {
        float dx = v[ch].x - mu, dy = v[ch].y - mu, dz = v[ch].z - mu, dw = v[ch].w - mu;
        var += dx * dx + dy * dy + dz * dz + dw * dw;
    }
    #pragma unroll
    for (int o = 16; o > 0; o >>= 1) var += __shfl_xor_sync(0xffffffffu, var, o);
    float rstd = rsqrtf(var * (1.0f / DM) + 1e-5f);

    float4* po = reinterpret_cast<float4*>(out + (size_t)row * DM);
    #pragma unroll
    for (int ch = 0; ch < 6; ch++) {
        float4 gg = pg[lane + 32 * ch];
        float4 bb = pb[lane + 32 * ch];
        float4 y;
        y.x = (v[ch].x - mu) * rstd * gg.x + bb.x;
        y.y = (v[ch].y - mu) * rstd * gg.y + bb.y;
        y.z = (v[ch].z - mu) * rstd * gg.z + bb.z;
        y.w = (v[ch].w - mu) * rstd * gg.w + bb.w;
        po[lane + 32 * ch] = y;
    }
}

// ================= launch =================
extern "C" void kernel_launch(void* const* d_in, const int* in_sizes, int n_in,
                              void* d_out, int out_size) {
    const float* x     = (const float*)d_in[0];
    const float* Wq    = (const float*)d_in[1];
    const float* bq    = (const float*)d_in[2];
    const float* Wk    = (const float*)d_in[3];
    const float* bk    = (const float*)d_in[4];
    const float* Wv    = (const float*)d_in[5];
    const float* bv    = (const float*)d_in[6];
    const float* ln1_g = (const float*)d_in[7];
    const float* ln1_b = (const float*)d_in[8];
    const float* W1    = (const float*)d_in[9];
    const float* b1    = (const float*)d_in[10];
    const float* W2    = (const float*)d_in[11];
    const float* b2    = (const float*)d_in[12];
    const float* ln2_g = (const float*)d_in[13];
    const float* ln2_b = (const float*)d_in[14];
    float* out = (float*)d_out;

    float *qf, *attn, *x1, *ffp, *bqkv;
    __nv_bfloat16 *kvh, *kvl;
    __half *xh, *xl, *x1h, *x1l, *hidh, *hidl, *wqkv, *w1, *w2;
    cudaGetSymbolAddress((void**)&qf, g_qf);     cudaGetSymbolAddress((void**)&attn, g_attn);
    cudaGetSymbolAddress((void**)&x1, g_x1);     cudaGetSymbolAddress((void**)&ffp, g_ffp);
    cudaGetSymbolAddress((void**)&bqkv, g_bqkv);
    cudaGetSymbolAddress((void**)&kvh, g_kvh);   cudaGetSymbolAddress((void**)&kvl, g_kvl);
    cudaGetSymbolAddress((void**)&xh, g_xh);     cudaGetSymbolAddress((void**)&xl, g_xl);
    cudaGetSymbolAddress((void**)&x1h, g_x1h);   cudaGetSymbolAddress((void**)&x1l, g_x1l);
    cudaGetSymbolAddress((void**)&hidh, g_hidh); cudaGetSymbolAddress((void**)&hidl, g_hidl);
    cudaGetSymbolAddress((void**)&wqkv, g_wqkv);
    cudaGetSymbolAddress((void**)&w1, g_w1);     cudaGetSymbolAddress((void**)&w2, g_w2);

    cudaFuncSetAttribute(tc_gemm, cudaFuncAttributeMaxDynamicSharedMemorySize, GEMM_SMEM);
    cudaFuncSetAttribute(attn_kernel, cudaFuncAttributeMaxDynamicSharedMemorySize, ATTN_SMEM);

    // ---- convert inputs ----
    {
        int n4 = MROWS * DM / 4;
        split_convert<<<(n4 + 255) / 256, 256>>>(x, xh, xl, n4);
        prep_weights<<<6345, 256>>>(Wq, Wk, Wv, W1, W2, bq, bk, bv,
                                    wqkv, w1, w2, bqkv);
    }

    // ---- fused QKV projection: q fp32 (scaled), k/v bf16 hi/lo ----
    {
        dim3 grid(QKVN / 128, MROWS / 128);
        tc_gemm<<<grid, 256, GEMM_SMEM>>>(xh, xl, wqkv, bqkv, qf,
                                          kvh, kvl, MROWS, QKVN, DM, 2);
    }

    // ---- attention (HMMA) ----
    {
        dim3 grid(NC, NH, BB);
        attn_kernel<<<grid, 128, ATTN_SMEM>>>(qf, kvh, kvl, attn);
    }

    // ---- x1 = LN(attn + x), emit fp16 hi/lo ----
    add_ln_kernel<<<MROWS / 8, 256>>>(attn, x, ln1_g, ln1_b, x1, x1h, x1l);

    // ---- FFN ----
    {
        dim3 grid1(FF / 128, MROWS / 128);
        tc_gemm<<<grid1, 256, GEMM_SMEM>>>(x1h, x1l, w1, b1, nullptr,
                                           hidh, hidl, MROWS, FF, DM, 1);
        dim3 grid2(DM / 128, MROWS / 128, 3);   // split-K = 3
        tc_gemm<<<grid2, 256, GEMM_SMEM>>>(hidh, hidl, w2, nullptr, ffp,
                                           nullptr, nullptr, MROWS, DM, FF, 3);
    }

    // ---- out = LN(p0+p1+p2 + b2 + x1) ----
    add_ln3_kernel<<<MROWS / 8, 256>>>(ffp, x1, b2, ln2_g, ln2_b, out);
}

// round 11
// speedup vs baseline: 1.3822x; 1.0359x over previous
#include <cuda_runtime.h>
#include <cuda_bf16.h>
#include <cuda_fp16.h>
#include <math.h>
#include <cstdint>

#define BB 2
#define SS 4096
#define DM 768
#define NH 12
#define FF 3072
#define WIN 64
#define HD 64
#define NC (SS / WIN)
#define MROWS (BB * SS)    // 8192
#define QKVN (3 * DM)      // 2304
#define KVW (2 * DM)       // 1536
#define MD (MROWS * DM)

// ================= helpers =================
__device__ __forceinline__ uint32_t smem_to_u32(const void* p) {
    uint32_t a;
    asm("{ .reg .u64 t; cvta.to.shared.u64 t, %1; cvt.u32.u64 %0, t; }" : "=r"(a) : "l"(p));
    return a;
}
#define SMEM_SWIZZLE_128B(o) ((o) ^ (((o) >> 3) & 0x70))

__device__ __forceinline__ void ldsm_x4(uint32_t r[4], uint32_t addr) {
    asm volatile("ldmatrix.sync.aligned.m8n8.x4.shared.b16 {%0,%1,%2,%3}, [%4];"
        : "=r"(r[0]), "=r"(r[1]), "=r"(r[2]), "=r"(r[3]) : "r"(addr));
}
__device__ __forceinline__ void ldsm_x4_trans(uint32_t r[4], uint32_t addr) {
    asm volatile("ldmatrix.sync.aligned.m8n8.x4.trans.shared.b16 {%0,%1,%2,%3}, [%4];"
        : "=r"(r[0]), "=r"(r[1]), "=r"(r[2]), "=r"(r[3]) : "r"(addr));
}
__device__ __forceinline__ void mma_fp16(float c[4], const uint32_t a[4],
                                         uint32_t b0, uint32_t b1) {
    asm volatile("mma.sync.aligned.m16n8k16.row.col.f32.f16.f16.f32 "
        "{%0,%1,%2,%3}, {%4,%5,%6,%7}, {%8,%9}, {%0,%1,%2,%3};"
        : "+f"(c[0]), "+f"(c[1]), "+f"(c[2]), "+f"(c[3])
        : "r"(a[0]), "r"(a[1]), "r"(a[2]), "r"(a[3]), "r"(b0), "r"(b1));
}
__device__ __forceinline__ void split_half(float v, __half& h, __half& l) {
    h = __float2half(v);
    l = __float2half(v - __half2float(h));
}
__device__ __forceinline__ uint32_t pack_hi16(float x, float y) {
    __half2 t(__float2half(x), __float2half(y));
    return *reinterpret_cast<uint32_t*>(&t);
}
__device__ __forceinline__ uint32_t pack_lo16(float x, float y) {
    __half hx = __float2half(x), hy = __float2half(y);
    __half2 t(__float2half(x - __half2float(hx)),
              __float2half(y - __half2float(hy)));
    return *reinterpret_cast<uint32_t*>(&t);
}
__device__ __forceinline__ float gelu_tanh(float x) {
    const float c = 0.7978845608028654f;
    float x3 = x * x * x;
    return 0.5f * x * (1.0f + tanhf(c * (x + 0.044715f * x3)));
}

// ================= scratch =================
__device__ float g_qf[MD];
__device__ float g_attn[MD];
__device__ float g_x1[MD];
__device__ float g_ffp[3 * MD];
__device__ float g_bqkv[QKVN];
__device__ __half g_kv[MROWS * KVW];          // k|v single fp16
__device__ __half g_xh[MD],  g_xl[MD];
__device__ __half g_x1h[MD], g_x1l[MD];
__device__ __half g_hidh[MROWS * FF], g_hidl[MROWS * FF];
__device__ __half g_wqkv[QKVN * DM];
__device__ __half g_w1[FF * DM];
__device__ __half g_w2[DM * FF];

// ========== elementwise fp32 -> fp16 hi/lo ==========
__global__ void split_convert(const float* __restrict__ in,
                              __half* __restrict__ hi,
                              __half* __restrict__ lo, int n4) {
    int i = blockIdx.x * blockDim.x + threadIdx.x;
    if (i >= n4) return;
    float4 v = reinterpret_cast<const float4*>(in)[i];
    __half h0,l0,h1,l1,h2,l2,h3,l3;
    split_half(v.x, h0, l0); split_half(v.y, h1, l1);
    split_half(v.z, h2, l2); split_half(v.w, h3, l3);
    reinterpret_cast<__half2*>(hi)[i*2+0] = __half2(h0, h1);
    reinterpret_cast<__half2*>(hi)[i*2+1] = __half2(h2, h3);
    reinterpret_cast<__half2*>(lo)[i*2+0] = __half2(l0, l1);
    reinterpret_cast<__half2*>(lo)[i*2+1] = __half2(l2, l3);
}

// ========== merged weight transpose (single fp16) + bias pack ==========
__global__ void prep_weights(const float* __restrict__ Wq, const float* __restrict__ Wk,
                             const float* __restrict__ Wv, const float* __restrict__ W1,
                             const float* __restrict__ W2,
                             const float* __restrict__ bq, const float* __restrict__ bk,
                             const float* __restrict__ bv,
                             __half* __restrict__ wqkv,
                             __half* __restrict__ w1,
                             __half* __restrict__ w2,
                             float* __restrict__ bqkv) {
    int id = blockIdx.x;
    if (id >= 6336) {
        int i = (id - 6336) * 256 + threadIdx.x;
        if (i < QKVN)
            bqkv[i] = (i < DM) ? bq[i] : (i < 2 * DM) ? bk[i - DM] : bv[i - 2 * DM];
        return;
    }
    const float* W; __half* T; int K, N, tix;
    if (id < 576)       { W = Wq; T = wqkv;               K = DM; N = DM; tix = id; }
    else if (id < 1152) { W = Wk; T = wqkv + DM * DM;     K = DM; N = DM; tix = id - 576; }
    else if (id < 1728) { W = Wv; T = wqkv + 2 * DM * DM; K = DM; N = DM; tix = id - 1152; }
    else if (id < 4032) { W = W1; T = w1;                 K = DM; N = FF; tix = id - 1728; }
    else                { W = W2; T = w2;                 K = FF; N = DM; tix = id - 4032; }
    int nt = N / 32;
    int n0 = (tix % nt) * 32, k0 = (tix / nt) * 32;
    __shared__ float t[32][33];
    int tx = threadIdx.x & 31, ty = threadIdx.x >> 5;
    #pragma unroll
    for (int i = 0; i < 4; i++)
        t[ty + i*8][tx] = W[(size_t)(k0 + ty + i*8) * N + n0 + tx];
    __syncthreads();
    #pragma unroll
    for (int i = 0; i < 4; i++) {
        T[(size_t)(n0 + ty + i*8) * K + k0 + tx] = __float2half(t[tx][ty + i*8]);
    }
}

// ========== HMMA GEMM: C = A @ B^T + bias, 2-term fp16 ==========
// mode 0: fp32+bias. mode 1: gelu + fp16 hi/lo. mode 2: QKV (q fp32*0.125,
// k/v single fp16). mode 3: split-K partial fp32.
#define STAGE_BYTES 49152
#define GEMM_SMEM (3 * STAGE_BYTES)
__global__ void __launch_bounds__(256, 1)
tc_gemm(const __half* __restrict__ Ah, const __half* __restrict__ Al,
        const __half* __restrict__ B,
        const float* __restrict__ bias,
        float* __restrict__ outF,
        void* __restrict__ outHiV, void* __restrict__ outLoV,
        int M, int N, int K, int mode) {
    extern __shared__ char smem[];
    const uint32_t tiles = smem_to_u32(smem);
    const int tid = threadIdx.x;
    const int wid = tid >> 5;
    const int lane = tid & 31;
    const int warpM = wid >> 1;
    const int warpN = wid & 1;
    const int bm = blockIdx.y * 128;
    const int bn = blockIdx.x * 128;
    const int kb0 = (mode == 3) ? blockIdx.z * 16 : 0;
    const int NB  = (mode == 3) ? 16 : (K >> 6);
    if (mode == 3) outF += (size_t)blockIdx.z * M * N;

    const __half* srcs[3] = {Ah, Al, B};

    auto stage = [&](int kb, int s) {
        #pragma unroll
        for (int t = 0; t < 3; t++) {
            const __half* src = srcs[t];
            const int rbase = (t < 2) ? bm : bn;
            const uint32_t sb = tiles + (uint32_t)s * STAGE_BYTES + (uint32_t)t * 16384u;
            #pragma unroll
            for (int i = 0; i < 4; i++) {
                int chunk = tid + i * 256;
                int row = chunk >> 3;
                int c16 = chunk & 7;
                uint32_t off = (uint32_t)(row * 128 + c16 * 16);
                uint32_t dst = sb + SMEM_SWIZZLE_128B(off);
                const void* g = src + (size_t)(rbase + row) * K + kb * 64 + c16 * 8;
                asm volatile("cp.async.cg.shared.global [%0], [%1], 16;" :: "r"(dst), "l"(g));
            }
        }
        asm volatile("cp.async.commit_group;" ::: "memory");
    };

    float c[2][8][4] = {};

    stage(kb0, 0);
    if (NB > 1) stage(kb0 + 1, 1);

    const int lrow = lane & 15;
    const int lchunk = lane >> 4;

    for (int kb = 0; kb < NB; kb++) {
        const int s = kb % 3;
        if (kb + 1 < NB) asm volatile("cp.async.wait_group 1;" ::: "memory");
        else             asm volatile("cp.async.wait_group 0;" ::: "memory");
        __syncthreads();
        if (kb + 2 < NB) stage(kb0 + kb + 2, (kb + 2) % 3);

        const uint32_t base_s = tiles + (uint32_t)s * STAGE_BYTES;
        #pragma unroll
        for (int ks = 0; ks < 4; ks++) {
            uint32_t ah[2][4], al2[2][4];
            #pragma unroll
            for (int mt = 0; mt < 2; mt++) {
                uint32_t off = (uint32_t)((warpM * 32 + mt * 16 + lrow) * 128 + ks * 32 + lchunk * 16);
                uint32_t sw = SMEM_SWIZZLE_128B(off);
                ldsm_x4(ah[mt],  base_s + sw);
                ldsm_x4(al2[mt], base_s + 16384u + sw);
            }
            uint32_t bb[2][4];
            {
                uint32_t off0 = (uint32_t)((warpN * 64 + lrow) * 128 + ks * 32 + lchunk * 16);
                ldsm_x4(bb[0], base_s + 32768u + SMEM_SWIZZLE_128B(off0));
            }
            #pragma unroll
            for (int np = 0; np < 4; np++) {
                const int cur = np & 1;
                if (np < 3) {
                    uint32_t off = (uint32_t)((warpN * 64 + (np + 1) * 16 + lrow) * 128 + ks * 32 + lchunk * 16);
                    ldsm_x4(bb[cur ^ 1], base_s + 32768u + SMEM_SWIZZLE_128B(off));
                }
                #pragma unroll
                for (int mt = 0; mt < 2; mt++) {
                    mma_fp16(c[mt][2*np],   ah[mt],  bb[cur][0], bb[cur][2]);
                    mma_fp16(c[mt][2*np+1], ah[mt],  bb[cur][1], bb[cur][3]);
                    mma_fp16(c[mt][2*np],   al2[mt], bb[cur][0], bb[cur][2]);
                    mma_fp16(c[mt][2*np+1], al2[mt], bb[cur][1], bb[cur][3]);
                }
            }
        }
    }
    __syncthreads();

    float* sD = reinterpret_cast<float*>(smem);   // 128 x 129
    #pragma unroll
    for (int mt = 0; mt < 2; mt++) {
        #pragma unroll
        for (int nt = 0; nt < 8; nt++) {
            int r0 = warpM * 32 + mt * 16 + (lane >> 2);
            int col = warpN * 64 + nt * 8 + (lane & 3) * 2;
            sD[r0 * 129 + col]           = c[mt][nt][0];
            sD[r0 * 129 + col + 1]       = c[mt][nt][1];
            sD[(r0 + 8) * 129 + col]     = c[mt][nt][2];
            sD[(r0 + 8) * 129 + col + 1] = c[mt][nt][3];
        }
    }
    __syncthreads();

    for (int idx = tid; idx < 128 * 128; idx += 256) {
        int r = idx >> 7, cc = idx & 127;
        float v = sD[r * 129 + cc];
        size_t row = (size_t)(bm + r);
        int gc = bn + cc;
        if (mode == 3) {
            outF[row * N + gc] = v;
            continue;
        }
        v += bias[gc];
        if (mode == 0) {
            outF[row * N + gc] = v;
        } else if (mode == 1) {
            v = gelu_tanh(v);
            __half h, l; split_half(v, h, l);
            ((__half*)outHiV)[row * N + gc] = h;
            ((__half*)outLoV)[row * N + gc] = l;
        } else {
            if (gc < DM) {
                outF[row * DM + gc] = v * 0.125f;
            } else {
                ((__half*)outHiV)[row * KVW + (gc - DM)] = __float2half(v);
            }
        }
    }
}

// ================= HMMA sliding-window attention, 2-term fp16 =================
// block = (c, h, b), 128 threads / 4 warps; 64KB smem -> 2 CTAs/SM.
// q: fp16 hi/lo (exact); k, v: single fp16.
#define AQH 0
#define AQL 8192
#define AK  16384
#define AV  40960
#define ATTN_SMEM 65536
__global__ void __launch_bounds__(128, 2)
attn_kernel(const float* __restrict__ qf,
            const __half* __restrict__ kv,
            float* __restrict__ out) {
    extern __shared__ char smem[];
    const uint32_t sb = smem_to_u32(smem);
    const int c = blockIdx.x, h = blockIdx.y, b = blockIdx.z;
    const int tid = threadIdx.x, warp = tid >> 5, lane = tid & 31;

    // ---- load q (fp32, pre-scaled) -> split fp16 hi/lo ----
    for (int idx = tid; idx < 64 * 16; idx += 128) {
        int r = idx >> 4, ch = idx & 15;
        float4 v = *reinterpret_cast<const float4*>(
            &qf[((size_t)b * SS + c * 64 + r) * DM + h * HD + ch * 4]);
        uint32_t off = SMEM_SWIZZLE_128B((uint32_t)(r * 128 + ch * 8));
        uint2 hh, ll;
        hh.x = pack_hi16(v.x, v.y); hh.y = pack_hi16(v.z, v.w);
        ll.x = pack_lo16(v.x, v.y); ll.y = pack_lo16(v.z, v.w);
        *reinterpret_cast<uint2*>(smem + AQH + off) = hh;
        *reinterpret_cast<uint2*>(smem + AQL + off) = ll;
    }
    // ---- load k/v window (192 rows, single fp16, zero-padded) ----
    for (int idx = tid; idx < 192 * 8; idx += 128) {
        int j = idx >> 3, ch = idx & 7;
        int g = c * 64 - 64 + j;
        uint4 z = {0, 0, 0, 0};
        uint4 k4 = z, v4 = z;
        if (g >= 0 && g < SS) {
            size_t rb = ((size_t)b * SS + g) * KVW + h * HD + ch * 8;
            k4 = *reinterpret_cast<const uint4*>(&kv[rb]);
            v4 = *reinterpret_cast<const uint4*>(&kv[rb + DM]);
        }
        uint32_t off = SMEM_SWIZZLE_128B((uint32_t)(j * 128 + ch * 16));
        *reinterpret_cast<uint4*>(smem + AK + off) = k4;
        *reinterpret_cast<uint4*>(smem + AV + off) = v4;
    }
    __syncthreads();

    const int m0 = warp * 16;
    const int lrow = lane & 15;
    const int lch = lane >> 4;

    // ---- QK^T: 16 x 192 per warp, 2-term fp16 ----
    float s[24][4];
    #pragma unroll
    for (int nt = 0; nt < 24; nt++)
        #pragma unroll
        for (int u = 0; u < 4; u++) s[nt][u] = 0.f;

    #pragma unroll
    for (int ks = 0; ks < 4; ks++) {
        uint32_t aoff = SMEM_SWIZZLE_128B((uint32_t)((m0 + lrow) * 128 + ks * 32 + lch * 16));
        uint32_t ah[4], al[4];
        ldsm_x4(ah, sb + AQH + aoff);
        ldsm_x4(al, sb + AQL + aoff);
        #pragma unroll
        for (int n6 = 0; n6 < 12; n6++) {
            uint32_t boff = SMEM_SWIZZLE_128B((uint32_t)((n6 * 16 + lrow) * 128 + ks * 32 + lch * 16));
            uint32_t bk4[4];
            ldsm_x4(bk4, sb + AK + boff);
            mma_fp16(s[2*n6],   ah, bk4[0], bk4[2]);
            mma_fp16(s[2*n6+1], ah, bk4[1], bk4[3]);
            mma_fp16(s[2*n6],   al, bk4[0], bk4[2]);
            mma_fp16(s[2*n6+1], al, bk4[1], bk4[3]);
        }
    }

    // ---- mask + softmax in registers ----
    const int rA = m0 + (lane >> 2);
    const int rB = rA + 8;
    const int jb = 2 * (lane & 3);
    const int gof = c * 64 - 64;
    float mA = -INFINITY, mB = -INFINITY;
    #pragma unroll
    for (int nt = 0; nt < 24; nt++) {
        int j0 = nt * 8 + jb, j1 = j0 + 1;
        int g0 = gof + j0, g1 = gof + j1;
        bool in0 = (g0 >= 0) && (g0 < SS);
        bool in1 = (g1 >= 0) && (g1 < SS);
        if (!((j0 >= rA) && (j0 <= rA + 128) && in0)) s[nt][0] = -INFINITY;
        if (!((j1 >= rA) && (j1 <= rA + 128) && in1)) s[nt][1] = -INFINITY;
        if (!((j0 >= rB) && (j0 <= rB + 128) && in0)) s[nt][2] = -INFINITY;
        if (!((j1 >= rB) && (j1 <= rB + 128) && in1)) s[nt][3] = -INFINITY;
        mA = fmaxf(mA, fmaxf(s[nt][0], s[nt][1]));
        mB = fmaxf(mB, fmaxf(s[nt][2], s[nt][3]));
    }
    mA = fmaxf(mA, __shfl_xor_sync(0xffffffffu, mA, 1));
    mA = fmaxf(mA, __shfl_xor_sync(0xffffffffu, mA, 2));
    mB = fmaxf(mB, __shfl_xor_sync(0xffffffffu, mB, 1));
    mB = fmaxf(mB, __shfl_xor_sync(0xffffffffu, mB, 2));
    float sA = 0.f, sB = 0.f;
    #pragma unroll
    for (int nt = 0; nt < 24; nt++) {
        s[nt][0] = __expf(s[nt][0] - mA);
        s[nt][1] = __expf(s[nt][1] - mA);
        s[nt][2] = __expf(s[nt][2] - mB);
        s[nt][3] = __expf(s[nt][3] - mB);
        sA += s[nt][0] + s[nt][1];
        sB += s[nt][2] + s[nt][3];
    }
    sA += __shfl_xor_sync(0xffffffffu, sA, 1);
    sA += __shfl_xor_sync(0xffffffffu, sA, 2);
    sB += __shfl_xor_sync(0xffffffffu, sB, 1);
    sB += __shfl_xor_sync(0xffffffffu, sB, 2);
    const float invA = 1.0f / sA, invB = 1.0f / sB;

    // ---- PV: P fp16 hi/lo x V single fp16 ----
    float o[8][4];
    #pragma unroll
    for (int nt = 0; nt < 8; nt++)
        #pragma unroll
        for (int u = 0; u < 4; u++) o[nt][u] = 0.f;

    #pragma unroll
    for (int t = 0; t < 12; t++) {
        uint32_t ph[4], pl[4];
        ph[0] = pack_hi16(s[2*t][0],   s[2*t][1]);
        ph[1] = pack_hi16(s[2*t][2],   s[2*t][3]);
        ph[2] = pack_hi16(s[2*t+1][0], s[2*t+1][1]);
        ph[3] = pack_hi16(s[2*t+1][2], s[2*t+1][3]);
        pl[0] = pack_lo16(s[2*t][0],   s[2*t][1]);
        pl[1] = pack_lo16(s[2*t][2],   s[2*t][3]);
        pl[2] = pack_lo16(s[2*t+1][0], s[2*t+1][1]);
        pl[3] = pack_lo16(s[2*t+1][2], s[2*t+1][3]);
        #pragma unroll
        for (int nn = 0; nn < 4; nn++) {
            uint32_t voff = SMEM_SWIZZLE_128B(
                (uint32_t)((t * 16 + (lane & 15)) * 128 + (nn * 16 + (lane >> 4) * 8) * 2));
            uint32_t vv[4];
            ldsm_x4_trans(vv, sb + AV + voff);
            mma_fp16(o[2*nn],   ph, vv[0], vv[1]);
            mma_fp16(o[2*nn+1], ph, vv[2], vv[3]);
            mma_fp16(o[2*nn],   pl, vv[0], vv[1]);
            mma_fp16(o[2*nn+1], pl, vv[2], vv[3]);
        }
    }

    const size_t rowg = (size_t)b * SS + c * 64;
    #pragma unroll
    for (int nt = 0; nt < 8; nt++) {
        int col = h * HD + nt * 8 + jb;
        float2 v0 = make_float2(o[nt][0] * invA, o[nt][1] * invA);
        float2 v1 = make_float2(o[nt][2] * invB, o[nt][3] * invB);
        *reinterpret_cast<float2*>(&out[(rowg + rA) * DM + col]) = v0;
        *reinterpret_cast<float2*>(&out[(rowg + rB) * DM + col]) = v1;
    }
}

// ================= warp-per-row residual + LayerNorm (fp16 hi/lo emit) ==========
__global__ void __launch_bounds__(256)
add_ln_kernel(const float* __restrict__ a,
              const float* __restrict__ r,
              const float* __restrict__ g,
              const float* __restrict__ beta,
              float* __restrict__ out,
              __half* __restrict__ outHi,
              __half* __restrict__ outLo) {
    const int warp = threadIdx.x >> 5, lane = threadIdx.x & 31;
    const int row = blockIdx.x * 8 + warp;
    const float4* pa = reinterpret_cast<const float4*>(a + (size_t)row * DM);
    const float4* pr = reinterpret_cast<const float4*>(r + (size_t)row * DM);
    const float4* pg = reinterpret_cast<const float4*>(g);
    const float4* pb = reinterpret_cast<const float4*>(beta);

    float4 v[6];
    float sum = 0.f;
    #pragma unroll
    for (int ch = 0; ch < 6; ch++) {
        float4 va = pa[lane + 32 * ch];
        float4 vr = pr[lane + 32 * ch];
        v[ch] = make_float4(va.x + vr.x, va.y + vr.y, va.z + vr.z, va.w + vr.w);
        sum += v[ch].x + v[ch].y + v[ch].z + v[ch].w;
    }
    #pragma unroll
    for (int o = 16; o > 0; o >>= 1) sum += __shfl_xor_sync(0xffffffffu, sum, o);
    float mu = sum * (1.0f / DM);

    float var = 0.f;
    #pragma unroll
    for (int ch = 0; ch < 6; ch++) {
        float dx = v[ch].x - mu, dy = v[ch].y - mu, dz = v[ch].z - mu, dw = v[ch].w - mu;
        var += dx * dx + dy * dy + dz * dz + dw * dw;
    }
    #pragma unroll
    for (int o = 16; o > 0; o >>= 1) var += __shfl_xor_sync(0xffffffffu, var, o);
    float rstd = rsqrtf(var * (1.0f / DM) + 1e-5f);

    float4* po = reinterpret_cast<float4*>(out + (size_t)row * DM);
    #pragma unroll
    for (int ch = 0; ch < 6; ch++) {
        float4 gg = pg[lane + 32 * ch];
        float4 bb = pb[lane + 32 * ch];
        float4 y;
        y.x = (v[ch].x - mu) * rstd * gg.x + bb.x;
        y.y = (v[ch].y - mu) * rstd * gg.y + bb.y;
        y.z = (v[ch].z - mu) * rstd * gg.z + bb.z;
        y.w = (v[ch].w - mu) * rstd * gg.w + bb.w;
        po[lane + 32 * ch] = y;
        if (outHi) {
            size_t o4 = (size_t)row * DM + (lane + 32 * ch) * 4;
            __half h0,l0,h1,l1,h2,l2,h3,l3;
            split_half(y.x, h0, l0); split_half(y.y, h1, l1);
            split_half(y.z, h2, l2); split_half(y.w, h3, l3);
            reinterpret_cast<__half2*>(outHi + o4)[0] = __half2(h0, h1);
            reinterpret_cast<__half2*>(outHi + o4)[1] = __half2(h2, h3);
            reinterpret_cast<__half2*>(outLo + o4)[0] = __half2(l0, l1);
            reinterpret_cast<__half2*>(outLo + o4)[1] = __half2(l2, l3);
        }
    }
}

// ===== final LN: out = LN(p0+p1+p2 + bias2 + x1) =====
__global__ void __launch_bounds__(256)
add_ln3_kernel(const float* __restrict__ p,
               const float* __restrict__ r,
               const float* __restrict__ bias2,
               const float* __restrict__ g,
               const float* __restrict__ beta,
               float* __restrict__ out) {
    const int warp = threadIdx.x >> 5, lane = threadIdx.x & 31;
    const int row = blockIdx.x * 8 + warp;
    const float4* p0 = reinterpret_cast<const float4*>(p + (size_t)row * DM);
    const float4* p1 = reinterpret_cast<const float4*>(p + (size_t)row * DM + MD);
    const float4* p2 = reinterpret_cast<const float4*>(p + (size_t)row * DM + 2 * (size_t)MD);
    const float4* pr = reinterpret_cast<const float4*>(r + (size_t)row * DM);
    const float4* pb2 = reinterpret_cast<const float4*>(bias2);
    const float4* pg = reinterpret_cast<const float4*>(g);
    const float4* pb = reinterpret_cast<const float4*>(beta);

    float4 v[6];
    float sum = 0.f;
    #pragma unroll
    for (int ch = 0; ch < 6; ch++) {
        float4 a0 = p0[lane + 32 * ch];
        float4 a1 = p1[lane + 32 * ch];
        float4 a2 = p2[lane + 32 * ch];
        float4 vr = pr[lane + 32 * ch];
        float4 b2 = pb2[lane + 32 * ch];
        v[ch] = make_float4(a0.x + a1.x + a2.x + b2.x + vr.x,
                            a0.y + a1.y + a2.y + b2.y + vr.y,
                            a0.z + a1.z + a2.z + b2.z + vr.z,
                            a0.w + a1.w + a2.w + b2.w + vr.w);
        sum += v[ch].x + v[ch].y + v[ch].z + v[ch].w;
    }
    #pragma unroll
    for (int o = 16; o > 0; o >>= 1) sum += __shfl_xor_sync(0xffffffffu, sum, o);
    float mu = sum * (1.0f / DM);

    float var = 0.f;
    #pragma unroll
    for (int ch = 0; ch < 6; ch++) {
        float dx = v[ch].x - mu, dy = v[ch].y - mu, dz = v[ch].z - mu, dw = v[ch].w - mu;
        var += dx * dx + dy * dy + dz * dz + dw * dw;
    }
    #pragma unroll
    for (int o = 16; o > 0; o >>= 1) var += __shfl_xor_sync(0xffffffffu, var, o);
    float rstd = rsqrtf(var * (1.0f / DM) + 1e-5f);

    float4* po = reinterpret_cast<float4*>(out + (size_t)row * DM);
    #pragma unroll
    for (int ch = 0; ch < 6; ch++) {
        float4 gg = pg[lane + 32 * ch];
        float4 bb = pb[lane + 32 * ch];
        float4 y;
        y.x = (v[ch].x - mu) * rstd * gg.x + bb.x;
        y.y = (v[ch].y - mu) * rstd * gg.y + bb.y;
        y.z = (v[ch].z - mu) * rstd * gg.z + bb.z;
        y.w = (v[ch].w - mu) * rstd * gg.w + bb.w;
        po[lane + 32 * ch] = y;
    }
}

// ================= launch =================
extern "C" void kernel_launch(void* const* d_in, const int* in_sizes, int n_in,
                              void* d_out, int out_size) {
    const float* x     = (const float*)d_in[0];
    const float* Wq    = (const float*)d_in[1];
    const float* bq    = (const float*)d_in[2];
    const float* Wk    = (const float*)d_in[3];
    const float* bk    = (const float*)d_in[4];
    const float* Wv    = (const float*)d_in[5];
    const float* bv    = (const float*)d_in[6];
    const float* ln1_g = (const float*)d_in[7];
    const float* ln1_b = (const float*)d_in[8];
    const float* W1    = (const float*)d_in[9];
    const float* b1    = (const float*)d_in[10];
    const float* W2    = (const float*)d_in[11];
    const float* b2    = (const float*)d_in[12];
    const float* ln2_g = (const float*)d_in[13];
    const float* ln2_b = (const float*)d_in[14];
    float* out = (float*)d_out;

    float *qf, *attn, *x1, *ffp, *bqkv;
    __half *kv, *xh, *xl, *x1h, *x1l, *hidh, *hidl, *wqkv, *w1, *w2;
    cudaGetSymbolAddress((void**)&qf, g_qf);     cudaGetSymbolAddress((void**)&attn, g_attn);
    cudaGetSymbolAddress((void**)&x1, g_x1);     cudaGetSymbolAddress((void**)&ffp, g_ffp);
    cudaGetSymbolAddress((void**)&bqkv, g_bqkv);
    cudaGetSymbolAddress((void**)&kv, g_kv);
    cudaGetSymbolAddress((void**)&xh, g_xh);     cudaGetSymbolAddress((void**)&xl, g_xl);
    cudaGetSymbolAddress((void**)&x1h, g_x1h);   cudaGetSymbolAddress((void**)&x1l, g_x1l);
    cudaGetSymbolAddress((void**)&hidh, g_hidh); cudaGetSymbolAddress((void**)&hidl, g_hidl);
    cudaGetSymbolAddress((void**)&wqkv, g_wqkv);
    cudaGetSymbolAddress((void**)&w1, g_w1);     cudaGetSymbolAddress((void**)&w2, g_w2);

    cudaFuncSetAttribute(tc_gemm, cudaFuncAttributeMaxDynamicSharedMemorySize, GEMM_SMEM);
    cudaFuncSetAttribute(attn_kernel, cudaFuncAttributeMaxDynamicSharedMemorySize, ATTN_SMEM);

    // ---- convert inputs ----
    {
        int n4 = MROWS * DM / 4;
        split_convert<<<(n4 + 255) / 256, 256>>>(x, xh, xl, n4);
        prep_weights<<<6345, 256>>>(Wq, Wk, Wv, W1, W2, bq, bk, bv,
                                    wqkv, w1, w2, bqkv);
    }

    // ---- fused QKV projection: q fp32 (scaled), k/v single fp16 ----
    {
        dim3 grid(QKVN / 128, MROWS / 128);
        tc_gemm<<<grid, 256, GEMM_SMEM>>>(xh, xl, wqkv, bqkv, qf,
                                          kv, nullptr, MROWS, QKVN, DM, 2);
    }

    // ---- attention (HMMA, 2-term fp16, 2 CTAs/SM) ----
    {
        dim3 grid(NC, NH, BB);
        attn_kernel<<<grid, 128, ATTN_SMEM>>>(qf, kv, attn);
    }

    // ---- x1 = LN(attn + x), emit fp16 hi/lo ----
    add_ln_kernel<<<MROWS / 8, 256>>>(attn, x, ln1_g, ln1_b, x1, x1h, x1l);

    // ---- FFN ----
    {
        dim3 grid1(FF / 128, MROWS / 128);
        tc_gemm<<<grid1, 256, GEMM_SMEM>>>(x1h, x1l, w1, b1, nullptr,
                                           hidh, hidl, MROWS, FF, DM, 1);
        dim3 grid2(DM / 128, MROWS / 128, 3);   // split-K = 3
        tc_gemm<<<grid2, 256, GEMM_SMEM>>>(hidh, hidl, w2, nullptr, ffp,
                                           nullptr, nullptr, MROWS, DM, FF, 3);
    }

    // ---- out = LN(p0+p1+p2 + b2 + x1) ----
    add_ln3_kernel<<<MROWS / 8, 256>>>(ffp, x1, b2, ln2_g, ln2_b, out);
}

// round 12
// speedup vs baseline: 1.4336x; 1.0372x over previous
#include <cuda_runtime.h>
#include <cuda_bf16.h>
#include <cuda_fp16.h>
#include <math.h>
#include <cstdint>

#define BB 2
#define SS 4096
#define DM 768
#define NH 12
#define FF 3072
#define WIN 64
#define HD 64
#define NC (SS / WIN)
#define MROWS (BB * SS)    // 8192
#define QKVN (3 * DM)      // 2304
#define KVW (2 * DM)       // 1536
#define MD (MROWS * DM)

// ================= helpers =================
__device__ __forceinline__ uint32_t smem_to_u32(const void* p) {
    uint32_t a;
    asm("{ .reg .u64 t; cvta.to.shared.u64 t, %1; cvt.u32.u64 %0, t; }" : "=r"(a) : "l"(p));
    return a;
}
#define SMEM_SWIZZLE_128B(o) ((o) ^ (((o) >> 3) & 0x70))

__device__ __forceinline__ void ldsm_x4(uint32_t r[4], uint32_t addr) {
    asm volatile("ldmatrix.sync.aligned.m8n8.x4.shared.b16 {%0,%1,%2,%3}, [%4];"
        : "=r"(r[0]), "=r"(r[1]), "=r"(r[2]), "=r"(r[3]) : "r"(addr));
}
__device__ __forceinline__ void ldsm_x4_trans(uint32_t r[4], uint32_t addr) {
    asm volatile("ldmatrix.sync.aligned.m8n8.x4.trans.shared.b16 {%0,%1,%2,%3}, [%4];"
        : "=r"(r[0]), "=r"(r[1]), "=r"(r[2]), "=r"(r[3]) : "r"(addr));
}
__device__ __forceinline__ void mma_fp16(float c[4], const uint32_t a[4],
                                         uint32_t b0, uint32_t b1) {
    asm volatile("mma.sync.aligned.m16n8k16.row.col.f32.f16.f16.f32 "
        "{%0,%1,%2,%3}, {%4,%5,%6,%7}, {%8,%9}, {%0,%1,%2,%3};"
        : "+f"(c[0]), "+f"(c[1]), "+f"(c[2]), "+f"(c[3])
        : "r"(a[0]), "r"(a[1]), "r"(a[2]), "r"(a[3]), "r"(b0), "r"(b1));
}
__device__ __forceinline__ void split_half(float v, __half& h, __half& l) {
    h = __float2half(v);
    l = __float2half(v - __half2float(h));
}
__device__ __forceinline__ uint32_t pack_hi16(float x, float y) {
    __half2 t(__float2half(x), __float2half(y));
    return *reinterpret_cast<uint32_t*>(&t);
}
__device__ __forceinline__ uint32_t pack_lo16(float x, float y) {
    __half hx = __float2half(x), hy = __float2half(y);
    __half2 t(__float2half(x - __half2float(hx)),
              __float2half(y - __half2float(hy)));
    return *reinterpret_cast<uint32_t*>(&t);
}
__device__ __forceinline__ float gelu_tanh(float x) {
    const float c = 0.7978845608028654f;
    float x3 = x * x * x;
    return 0.5f * x * (1.0f + tanhf(c * (x + 0.044715f * x3)));
}

// ================= scratch =================
__device__ float g_qf[MD];
__device__ float g_attn[MD];
__device__ float g_x1[MD];
__device__ float g_ffp[3 * MD];
__device__ float g_bqkv[QKVN];
__device__ __half g_kv[MROWS * KVW];          // k|v single fp16
__device__ __half g_xh[MD],  g_xl[MD];        // x hi/lo (QKV stays 2-term)
__device__ __half g_x1h[MD];                  // x1 single fp16
__device__ __half g_hid[MROWS * FF];          // hid single fp16
__device__ __half g_wqkv[QKVN * DM];
__device__ __half g_w1[FF * DM];
__device__ __half g_w2[DM * FF];

// ========== elementwise fp32 -> fp16 hi/lo ==========
__global__ void split_convert(const float* __restrict__ in,
                              __half* __restrict__ hi,
                              __half* __restrict__ lo, int n4) {
    int i = blockIdx.x * blockDim.x + threadIdx.x;
    if (i >= n4) return;
    float4 v = reinterpret_cast<const float4*>(in)[i];
    __half h0,l0,h1,l1,h2,l2,h3,l3;
    split_half(v.x, h0, l0); split_half(v.y, h1, l1);
    split_half(v.z, h2, l2); split_half(v.w, h3, l3);
    reinterpret_cast<__half2*>(hi)[i*2+0] = __half2(h0, h1);
    reinterpret_cast<__half2*>(hi)[i*2+1] = __half2(h2, h3);
    reinterpret_cast<__half2*>(lo)[i*2+0] = __half2(l0, l1);
    reinterpret_cast<__half2*>(lo)[i*2+1] = __half2(l2, l3);
}

// ========== merged weight transpose (single fp16) + bias pack ==========
__global__ void prep_weights(const float* __restrict__ Wq, const float* __restrict__ Wk,
                             const float* __restrict__ Wv, const float* __restrict__ W1,
                             const float* __restrict__ W2,
                             const float* __restrict__ bq, const float* __restrict__ bk,
                             const float* __restrict__ bv,
                             __half* __restrict__ wqkv,
                             __half* __restrict__ w1,
                             __half* __restrict__ w2,
                             float* __restrict__ bqkv) {
    int id = blockIdx.x;
    if (id >= 6336) {
        int i = (id - 6336) * 256 + threadIdx.x;
        if (i < QKVN)
            bqkv[i] = (i < DM) ? bq[i] : (i < 2 * DM) ? bk[i - DM] : bv[i - 2 * DM];
        return;
    }
    const float* W; __half* T; int K, N, tix;
    if (id < 576)       { W = Wq; T = wqkv;               K = DM; N = DM; tix = id; }
    else if (id < 1152) { W = Wk; T = wqkv + DM * DM;     K = DM; N = DM; tix = id - 576; }
    else if (id < 1728) { W = Wv; T = wqkv + 2 * DM * DM; K = DM; N = DM; tix = id - 1152; }
    else if (id < 4032) { W = W1; T = w1;                 K = DM; N = FF; tix = id - 1728; }
    else                { W = W2; T = w2;                 K = FF; N = DM; tix = id - 4032; }
    int nt = N / 32;
    int n0 = (tix % nt) * 32, k0 = (tix / nt) * 32;
    __shared__ float t[32][33];
    int tx = threadIdx.x & 31, ty = threadIdx.x >> 5;
    #pragma unroll
    for (int i = 0; i < 4; i++)
        t[ty + i*8][tx] = W[(size_t)(k0 + ty + i*8) * N + n0 + tx];
    __syncthreads();
    #pragma unroll
    for (int i = 0; i < 4; i++) {
        T[(size_t)(n0 + ty + i*8) * K + k0 + tx] = __float2half(t[tx][ty + i*8]);
    }
}

// ========== HMMA GEMM: C = A @ B^T + bias; terms = 1 or 2 fp16 A-terms ==========
// mode 0: fp32+bias. mode 1: gelu + single fp16. mode 2: QKV (q fp32*0.125,
// k/v single fp16). mode 3: split-K partial fp32.
#define STAGE_BYTES 49152
#define GEMM_SMEM (3 * STAGE_BYTES)
__global__ void __launch_bounds__(256, 1)
tc_gemm(const __half* __restrict__ Ah, const __half* __restrict__ Al,
        const __half* __restrict__ B,
        const float* __restrict__ bias,
        float* __restrict__ outF,
        void* __restrict__ outAux,
        int M, int N, int K, int mode, int terms) {
    extern __shared__ char smem[];
    const uint32_t tiles = smem_to_u32(smem);
    const int tid = threadIdx.x;
    const int wid = tid >> 5;
    const int lane = tid & 31;
    const int warpM = wid >> 1;
    const int warpN = wid & 1;
    const int bm = blockIdx.y * 128;
    const int bn = blockIdx.x * 128;
    const int kb0 = (mode == 3) ? blockIdx.z * 16 : 0;
    const int NB  = (mode == 3) ? 16 : (K >> 6);
    if (mode == 3) outF += (size_t)blockIdx.z * M * N;

    const uint32_t bOff = (uint32_t)terms * 16384u;   // B tile slot
    const __half* srcs[3] = {Ah, Al, B};

    auto stage = [&](int kb, int s) {
        const int ntiles = terms + 1;
        for (int t = 0; t < ntiles; t++) {
            const __half* src = (t < terms) ? srcs[t] : B;
            const int rbase = (t < terms) ? bm : bn;
            const uint32_t sb = tiles + (uint32_t)s * STAGE_BYTES + (uint32_t)t * 16384u;
            #pragma unroll
            for (int i = 0; i < 4; i++) {
                int chunk = tid + i * 256;
                int row = chunk >> 3;
                int c16 = chunk & 7;
                uint32_t off = (uint32_t)(row * 128 + c16 * 16);
                uint32_t dst = sb + SMEM_SWIZZLE_128B(off);
                const void* g = src + (size_t)(rbase + row) * K + kb * 64 + c16 * 8;
                asm volatile("cp.async.cg.shared.global [%0], [%1], 16;" :: "r"(dst), "l"(g));
            }
        }
        asm volatile("cp.async.commit_group;" ::: "memory");
    };

    float c[2][8][4] = {};

    stage(kb0, 0);
    if (NB > 1) stage(kb0 + 1, 1);

    const int lrow = lane & 15;
    const int lchunk = lane >> 4;

    for (int kb = 0; kb < NB; kb++) {
        const int s = kb % 3;
        if (kb + 1 < NB) asm volatile("cp.async.wait_group 1;" ::: "memory");
        else             asm volatile("cp.async.wait_group 0;" ::: "memory");
        __syncthreads();
        if (kb + 2 < NB) stage(kb0 + kb + 2, (kb + 2) % 3);

        const uint32_t base_s = tiles + (uint32_t)s * STAGE_BYTES;
        const uint32_t baseB = base_s + bOff;
        #pragma unroll
        for (int ks = 0; ks < 4; ks++) {
            uint32_t ah[2][4], al2[2][4];
            #pragma unroll
            for (int mt = 0; mt < 2; mt++) {
                uint32_t off = (uint32_t)((warpM * 32 + mt * 16 + lrow) * 128 + ks * 32 + lchunk * 16);
                uint32_t sw = SMEM_SWIZZLE_128B(off);
                ldsm_x4(ah[mt], base_s + sw);
                if (terms == 2) ldsm_x4(al2[mt], base_s + 16384u + sw);
            }
            uint32_t bb[2][4];
            {
                uint32_t off0 = (uint32_t)((warpN * 64 + lrow) * 128 + ks * 32 + lchunk * 16);
                ldsm_x4(bb[0], baseB + SMEM_SWIZZLE_128B(off0));
            }
            #pragma unroll
            for (int np = 0; np < 4; np++) {
                const int cur = np & 1;
                if (np < 3) {
                    uint32_t off = (uint32_t)((warpN * 64 + (np + 1) * 16 + lrow) * 128 + ks * 32 + lchunk * 16);
                    ldsm_x4(bb[cur ^ 1], baseB + SMEM_SWIZZLE_128B(off));
                }
                #pragma unroll
                for (int mt = 0; mt < 2; mt++) {
                    mma_fp16(c[mt][2*np],   ah[mt], bb[cur][0], bb[cur][2]);
                    mma_fp16(c[mt][2*np+1], ah[mt], bb[cur][1], bb[cur][3]);
                    if (terms == 2) {
                        mma_fp16(c[mt][2*np],   al2[mt], bb[cur][0], bb[cur][2]);
                        mma_fp16(c[mt][2*np+1], al2[mt], bb[cur][1], bb[cur][3]);
                    }
                }
            }
        }
    }
    __syncthreads();

    float* sD = reinterpret_cast<float*>(smem);   // 128 x 129
    #pragma unroll
    for (int mt = 0; mt < 2; mt++) {
        #pragma unroll
        for (int nt = 0; nt < 8; nt++) {
            int r0 = warpM * 32 + mt * 16 + (lane >> 2);
            int col = warpN * 64 + nt * 8 + (lane & 3) * 2;
            sD[r0 * 129 + col]           = c[mt][nt][0];
            sD[r0 * 129 + col + 1]       = c[mt][nt][1];
            sD[(r0 + 8) * 129 + col]     = c[mt][nt][2];
            sD[(r0 + 8) * 129 + col + 1] = c[mt][nt][3];
        }
    }
    __syncthreads();

    for (int idx = tid; idx < 128 * 128; idx += 256) {
        int r = idx >> 7, cc = idx & 127;
        float v = sD[r * 129 + cc];
        size_t row = (size_t)(bm + r);
        int gc = bn + cc;
        if (mode == 3) {
            outF[row * N + gc] = v;
            continue;
        }
        v += bias[gc];
        if (mode == 0) {
            outF[row * N + gc] = v;
        } else if (mode == 1) {
            v = gelu_tanh(v);
            ((__half*)outAux)[row * N + gc] = __float2half(v);
        } else {
            if (gc < DM) {
                outF[row * DM + gc] = v * 0.125f;
            } else {
                ((__half*)outAux)[row * KVW + (gc - DM)] = __float2half(v);
            }
        }
    }
}

// ================= HMMA sliding-window attention (R11: 2-term fp16) ============
#define AQH 0
#define AQL 8192
#define AK  16384
#define AV  40960
#define ATTN_SMEM 65536
__global__ void __launch_bounds__(128, 2)
attn_kernel(const float* __restrict__ qf,
            const __half* __restrict__ kv,
            float* __restrict__ out) {
    extern __shared__ char smem[];
    const uint32_t sb = smem_to_u32(smem);
    const int c = blockIdx.x, h = blockIdx.y, b = blockIdx.z;
    const int tid = threadIdx.x, warp = tid >> 5, lane = tid & 31;

    for (int idx = tid; idx < 64 * 16; idx += 128) {
        int r = idx >> 4, ch = idx & 15;
        float4 v = *reinterpret_cast<const float4*>(
            &qf[((size_t)b * SS + c * 64 + r) * DM + h * HD + ch * 4]);
        uint32_t off = SMEM_SWIZZLE_128B((uint32_t)(r * 128 + ch * 8));
        uint2 hh, ll;
        hh.x = pack_hi16(v.x, v.y); hh.y = pack_hi16(v.z, v.w);
        ll.x = pack_lo16(v.x, v.y); ll.y = pack_lo16(v.z, v.w);
        *reinterpret_cast<uint2*>(smem + AQH + off) = hh;
        *reinterpret_cast<uint2*>(smem + AQL + off) = ll;
    }
    for (int idx = tid; idx < 192 * 8; idx += 128) {
        int j = idx >> 3, ch = idx & 7;
        int g = c * 64 - 64 + j;
        uint4 z = {0, 0, 0, 0};
        uint4 k4 = z, v4 = z;
        if (g >= 0 && g < SS) {
            size_t rb = ((size_t)b * SS + g) * KVW + h * HD + ch * 8;
            k4 = *reinterpret_cast<const uint4*>(&kv[rb]);
            v4 = *reinterpret_cast<const uint4*>(&kv[rb + DM]);
        }
        uint32_t off = SMEM_SWIZZLE_128B((uint32_t)(j * 128 + ch * 16));
        *reinterpret_cast<uint4*>(smem + AK + off) = k4;
        *reinterpret_cast<uint4*>(smem + AV + off) = v4;
    }
    __syncthreads();

    const int m0 = warp * 16;
    const int lrow = lane & 15;
    const int lch = lane >> 4;

    float s[24][4];
    #pragma unroll
    for (int nt = 0; nt < 24; nt++)
        #pragma unroll
        for (int u = 0; u < 4; u++) s[nt][u] = 0.f;

    #pragma unroll
    for (int ks = 0; ks < 4; ks++) {
        uint32_t aoff = SMEM_SWIZZLE_128B((uint32_t)((m0 + lrow) * 128 + ks * 32 + lch * 16));
        uint32_t ah[4], al[4];
        ldsm_x4(ah, sb + AQH + aoff);
        ldsm_x4(al, sb + AQL + aoff);
        #pragma unroll
        for (int n6 = 0; n6 < 12; n6++) {
            uint32_t boff = SMEM_SWIZZLE_128B((uint32_t)((n6 * 16 + lrow) * 128 + ks * 32 + lch * 16));
            uint32_t bk4[4];
            ldsm_x4(bk4, sb + AK + boff);
            mma_fp16(s[2*n6],   ah, bk4[0], bk4[2]);
            mma_fp16(s[2*n6+1], ah, bk4[1], bk4[3]);
            mma_fp16(s[2*n6],   al, bk4[0], bk4[2]);
            mma_fp16(s[2*n6+1], al, bk4[1], bk4[3]);
        }
    }

    const int rA = m0 + (lane >> 2);
    const int rB = rA + 8;
    const int jb = 2 * (lane & 3);
    const int gof = c * 64 - 64;
    float mA = -INFINITY, mB = -INFINITY;
    #pragma unroll
    for (int nt = 0; nt < 24; nt++) {
        int j0 = nt * 8 + jb, j1 = j0 + 1;
        int g0 = gof + j0, g1 = gof + j1;
        bool in0 = (g0 >= 0) && (g0 < SS);
        bool in1 = (g1 >= 0) && (g1 < SS);
        if (!((j0 >= rA) && (j0 <= rA + 128) && in0)) s[nt][0] = -INFINITY;
        if (!((j1 >= rA) && (j1 <= rA + 128) && in1)) s[nt][1] = -INFINITY;
        if (!((j0 >= rB) && (j0 <= rB + 128) && in0)) s[nt][2] = -INFINITY;
        if (!((j1 >= rB) && (j1 <= rB + 128) && in1)) s[nt][3] = -INFINITY;
        mA = fmaxf(mA, fmaxf(s[nt][0], s[nt][1]));
        mB = fmaxf(mB, fmaxf(s[nt][2], s[nt][3]));
    }
    mA = fmaxf(mA, __shfl_xor_sync(0xffffffffu, mA, 1));
    mA = fmaxf(mA, __shfl_xor_sync(0xffffffffu, mA, 2));
    mB = fmaxf(mB, __shfl_xor_sync(0xffffffffu, mB, 1));
    mB = fmaxf(mB, __shfl_xor_sync(0xffffffffu, mB, 2));
    float sA = 0.f, sB = 0.f;
    #pragma unroll
    for (int nt = 0; nt < 24; nt++) {
        s[nt][0] = __expf(s[nt][0] - mA);
        s[nt][1] = __expf(s[nt][1] - mA);
        s[nt][2] = __expf(s[nt][2] - mB);
        s[nt][3] = __expf(s[nt][3] - mB);
        sA += s[nt][0] + s[nt][1];
        sB += s[nt][2] + s[nt][3];
    }
    sA += __shfl_xor_sync(0xffffffffu, sA, 1);
    sA += __shfl_xor_sync(0xffffffffu, sA, 2);
    sB += __shfl_xor_sync(0xffffffffu, sB, 1);
    sB += __shfl_xor_sync(0xffffffffu, sB, 2);
    const float invA = 1.0f / sA, invB = 1.0f / sB;

    float o[8][4];
    #pragma unroll
    for (int nt = 0; nt < 8; nt++)
        #pragma unroll
        for (int u = 0; u < 4; u++) o[nt][u] = 0.f;

    #pragma unroll
    for (int t = 0; t < 12; t++) {
        uint32_t ph[4], pl[4];
        ph[0] = pack_hi16(s[2*t][0],   s[2*t][1]);
        ph[1] = pack_hi16(s[2*t][2],   s[2*t][3]);
        ph[2] = pack_hi16(s[2*t+1][0], s[2*t+1][1]);
        ph[3] = pack_hi16(s[2*t+1][2], s[2*t+1][3]);
        pl[0] = pack_lo16(s[2*t][0],   s[2*t][1]);
        pl[1] = pack_lo16(s[2*t][2],   s[2*t][3]);
        pl[2] = pack_lo16(s[2*t+1][0], s[2*t+1][1]);
        pl[3] = pack_lo16(s[2*t+1][2], s[2*t+1][3]);
        #pragma unroll
        for (int nn = 0; nn < 4; nn++) {
            uint32_t voff = SMEM_SWIZZLE_128B(
                (uint32_t)((t * 16 + (lane & 15)) * 128 + (nn * 16 + (lane >> 4) * 8) * 2));
            uint32_t vv[4];
            ldsm_x4_trans(vv, sb + AV + voff);
            mma_fp16(o[2*nn],   ph, vv[0], vv[1]);
            mma_fp16(o[2*nn+1], ph, vv[2], vv[3]);
            mma_fp16(o[2*nn],   pl, vv[0], vv[1]);
            mma_fp16(o[2*nn+1], pl, vv[2], vv[3]);
        }
    }

    const size_t rowg = (size_t)b * SS + c * 64;
    #pragma unroll
    for (int nt = 0; nt < 8; nt++) {
        int col = h * HD + nt * 8 + jb;
        float2 v0 = make_float2(o[nt][0] * invA, o[nt][1] * invA);
        float2 v1 = make_float2(o[nt][2] * invB, o[nt][3] * invB);
        *reinterpret_cast<float2*>(&out[(rowg + rA) * DM + col]) = v0;
        *reinterpret_cast<float2*>(&out[(rowg + rB) * DM + col]) = v1;
    }
}

// ============ warp-per-row residual + LayerNorm (single fp16 emit) ============
__global__ void __launch_bounds__(256)
add_ln_kernel(const float* __restrict__ a,
              const float* __restrict__ r,
              const float* __restrict__ g,
              const float* __restrict__ beta,
              float* __restrict__ out,
              __half* __restrict__ outH) {
    const int warp = threadIdx.x >> 5, lane = threadIdx.x & 31;
    const int row = blockIdx.x * 8 + warp;
    const float4* pa = reinterpret_cast<const float4*>(a + (size_t)row * DM);
    const float4* pr = reinterpret_cast<const float4*>(r + (size_t)row * DM);
    const float4* pg = reinterpret_cast<const float4*>(g);
    const float4* pb = reinterpret_cast<const float4*>(beta);

    float4 v[6];
    float sum = 0.f;
    #pragma unroll
    for (int ch = 0; ch < 6; ch++) {
        float4 va = pa[lane + 32 * ch];
        float4 vr = pr[lane + 32 * ch];
        v[ch] = make_float4(va.x + vr.x, va.y + vr.y, va.z + vr.z, va.w + vr.w);
        sum += v[ch].x + v[ch].y + v[ch].z + v[ch].w;
    }
    #pragma unroll
    for (int o = 16; o > 0; o >>= 1) sum += __shfl_xor_sync(0xffffffffu, sum, o);
    float mu = sum * (1.0f / DM);

    float var = 0.f;
    #pragma unroll
    for (int ch = 0; ch < 6; ch++) {
        float dx = v[ch].x - mu, dy = v[ch].y - mu, dz = v[ch].z - mu, dw = v[ch].w - mu;
        var += dx * dx + dy * dy + dz * dz + dw * dw;
    }
    #pragma unroll
    for (int o = 16; o > 0; o >>= 1) var += __shfl_xor_sync(0xffffffffu, var, o);
    float rstd = rsqrtf(var * (1.0f / DM) + 1e-5f);

    float4* po = reinterpret_cast<float4*>(out + (size_t)row * DM);
    #pragma unroll
    for (int ch = 0; ch < 6; ch++) {
        float4 gg = pg[lane + 32 * ch];
        float4 bb = pb[lane + 32 * ch];
        float4 y;
        y.x = (v[ch].x - mu) * rstd * gg.x + bb.x;
        y.y = (v[ch].y - mu) * rstd * gg.y + bb.y;
        y.z = (v[ch].z - mu) * rstd * gg.z + bb.z;
        y.w = (v[ch].w - mu) * rstd * gg.w + bb.w;
        po[lane + 32 * ch] = y;
        if (outH) {
            size_t o4 = (size_t)row * DM + (lane + 32 * ch) * 4;
            reinterpret_cast<__half2*>(outH + o4)[0] =
                __half2(__float2half(y.x), __float2half(y.y));
            reinterpret_cast<__half2*>(outH + o4)[1] =
                __half2(__float2half(y.z), __float2half(y.w));
        }
    }
}

// ===== final LN: out = LN(p0+p1+p2 + bias2 + x1) =====
__global__ void __launch_bounds__(256)
add_ln3_kernel(const float* __restrict__ p,
               const float* __restrict__ r,
               const float* __restrict__ bias2,
               const float* __restrict__ g,
               const float* __restrict__ beta,
               float* __restrict__ out) {
    const int warp = threadIdx.x >> 5, lane = threadIdx.x & 31;
    const int row = blockIdx.x * 8 + warp;
    const float4* p0 = reinterpret_cast<const float4*>(p + (size_t)row * DM);
    const float4* p1 = reinterpret_cast<const float4*>(p + (size_t)row * DM + MD);
    const float4* p2 = reinterpret_cast<const float4*>(p + (size_t)row * DM + 2 * (size_t)MD);
    const float4* pr = reinterpret_cast<const float4*>(r + (size_t)row * DM);
    const float4* pb2 = reinterpret_cast<const float4*>(bias2);
    const float4* pg = reinterpret_cast<const float4*>(g);
    const float4* pb = reinterpret_cast<const float4*>(beta);

    float4 v[6];
    float sum = 0.f;
    #pragma unroll
    for (int ch = 0; ch < 6; ch++) {
        float4 a0 = p0[lane + 32 * ch];
        float4 a1 = p1[lane + 32 * ch];
        float4 a2 = p2[lane + 32 * ch];
        float4 vr = pr[lane + 32 * ch];
        float4 b2 = pb2[lane + 32 * ch];
        v[ch] = make_float4(a0.x + a1.x + a2.x + b2.x + vr.x,
                            a0.y + a1.y + a2.y + b2.y + vr.y,
                            a0.z + a1.z + a2.z + b2.z + vr.z,
                            a0.w + a1.w + a2.w + b2.w + vr.w);
        sum += v[ch].x + v[ch].y + v[ch].z + v[ch].w;
    }
    #pragma unroll
    for (int o = 16; o > 0; o >>= 1) sum += __shfl_xor_sync(0xffffffffu, sum, o);
    float mu = sum * (1.0f / DM);

    float var = 0.f;
    #pragma unroll
    for (int ch = 0; ch < 6; ch++) {
        float dx = v[ch].x - mu, dy = v[ch].y - mu, dz = v[ch].z - mu, dw = v[ch].w - mu;
        var += dx * dx + dy * dy + dz * dz + dw * dw;
    }
    #pragma unroll
    for (int o = 16; o > 0; o >>= 1) var += __shfl_xor_sync(0xffffffffu, var, o);
    float rstd = rsqrtf(var * (1.0f / DM) + 1e-5f);

    float4* po = reinterpret_cast<float4*>(out + (size_t)row * DM);
    #pragma unroll
    for (int ch = 0; ch < 6; ch++) {
        float4 gg = pg[lane + 32 * ch];
        float4 bb = pb[lane + 32 * ch];
        float4 y;
        y.x = (v[ch].x - mu) * rstd * gg.x + bb.x;
        y.y = (v[ch].y - mu) * rstd * gg.y + bb.y;
        y.z = (v[ch].z - mu) * rstd * gg.z + bb.z;
        y.w = (v[ch].w - mu) * rstd * gg.w + bb.w;
        po[lane + 32 * ch] = y;
    }
}

// ================= launch =================
extern "C" void kernel_launch(void* const* d_in, const int* in_sizes, int n_in,
                              void* d_out, int out_size) {
    const float* x     = (const float*)d_in[0];
    const float* Wq    = (const float*)d_in[1];
    const float* bq    = (const float*)d_in[2];
    const float* Wk    = (const float*)d_in[3];
    const float* bk    = (const float*)d_in[4];
    const float* Wv    = (const float*)d_in[5];
    const float* bv    = (const float*)d_in[6];
    const float* ln1_g = (const float*)d_in[7];
    const float* ln1_b = (const float*)d_in[8];
    const float* W1    = (const float*)d_in[9];
    const float* b1    = (const float*)d_in[10];
    const float* W2    = (const float*)d_in[11];
    const float* b2    = (const float*)d_in[12];
    const float* ln2_g = (const float*)d_in[13];
    const float* ln2_b = (const float*)d_in[14];
    float* out = (float*)d_out;

    float *qf, *attn, *x1, *ffp, *bqkv;
    __half *kv, *xh, *xl, *x1h, *hid, *wqkv, *w1, *w2;
    cudaGetSymbolAddress((void**)&qf, g_qf);     cudaGetSymbolAddress((void**)&attn, g_attn);
    cudaGetSymbolAddress((void**)&x1, g_x1);     cudaGetSymbolAddress((void**)&ffp, g_ffp);
    cudaGetSymbolAddress((void**)&bqkv, g_bqkv);
    cudaGetSymbolAddress((void**)&kv, g_kv);
    cudaGetSymbolAddress((void**)&xh, g_xh);     cudaGetSymbolAddress((void**)&xl, g_xl);
    cudaGetSymbolAddress((void**)&x1h, g_x1h);
    cudaGetSymbolAddress((void**)&hid, g_hid);
    cudaGetSymbolAddress((void**)&wqkv, g_wqkv);
    cudaGetSymbolAddress((void**)&w1, g_w1);     cudaGetSymbolAddress((void**)&w2, g_w2);

    cudaFuncSetAttribute(tc_gemm, cudaFuncAttributeMaxDynamicSharedMemorySize, GEMM_SMEM);
    cudaFuncSetAttribute(attn_kernel, cudaFuncAttributeMaxDynamicSharedMemorySize, ATTN_SMEM);

    // ---- convert inputs ----
    {
        int n4 = MROWS * DM / 4;
        split_convert<<<(n4 + 255) / 256, 256>>>(x, xh, xl, n4);
        prep_weights<<<6345, 256>>>(Wq, Wk, Wv, W1, W2, bq, bk, bv,
                                    wqkv, w1, w2, bqkv);
    }

    // ---- fused QKV projection (2-term): q fp32 (scaled), k/v single fp16 ----
    {
        dim3 grid(QKVN / 128, MROWS / 128);
        tc_gemm<<<grid, 256, GEMM_SMEM>>>(xh, xl, wqkv, bqkv, qf,
                                          kv, MROWS, QKVN, DM, 2, 2);
    }

    // ---- attention (HMMA, 2-term fp16) ----
    {
        dim3 grid(NC, NH, BB);
        attn_kernel<<<grid, 128, ATTN_SMEM>>>(qf, kv, attn);
    }

    // ---- x1 = LN(attn + x), emit single fp16 ----
    add_ln_kernel<<<MROWS / 8, 256>>>(attn, x, ln1_g, ln1_b, x1, x1h);

    // ---- FFN (both 1-term) ----
    {
        dim3 grid1(FF / 128, MROWS / 128);
        tc_gemm<<<grid1, 256, GEMM_SMEM>>>(x1h, nullptr, w1, b1, nullptr,
                                           hid, MROWS, FF, DM, 1, 1);
        dim3 grid2(DM / 128, MROWS / 128, 3);   // split-K = 3
        tc_gemm<<<grid2, 256, GEMM_SMEM>>>(hid, nullptr, w2, nullptr, ffp,
                                           nullptr, MROWS, DM, FF, 3, 1);
    }

    // ---- out = LN(p0+p1+p2 + b2 + x1) ----
    add_ln3_kernel<<<MROWS / 8, 256>>>(ffp, x1, b2, ln2_g, ln2_b, out);
}

// round 13
// speedup vs baseline: 2.1028x; 1.4668x over previous
#include <cuda_runtime.h>
#include <cuda_bf16.h>
#include <cuda_fp16.h>
#include <math.h>
#include <cstdint>

#define BB 2
#define SS 4096
#define DM 768
#define NH 12
#define FF 3072
#define WIN 64
#define HD 64
#define NC (SS / WIN)
#define MROWS (BB * SS)    // 8192
#define QKVN (3 * DM)      // 2304
#define KVW (2 * DM)       // 1536
#define MD (MROWS * DM)

// ================= helpers =================
__device__ __forceinline__ uint32_t smem_to_u32(const void* p) {
    uint32_t a;
    asm("{ .reg .u64 t; cvta.to.shared.u64 t, %1; cvt.u32.u64 %0, t; }" : "=r"(a) : "l"(p));
    return a;
}
#define SMEM_SWIZZLE_128B(o) ((o) ^ (((o) >> 3) & 0x70))

__device__ __forceinline__ void ldsm_x4(uint32_t r[4], uint32_t addr) {
    asm volatile("ldmatrix.sync.aligned.m8n8.x4.shared.b16 {%0,%1,%2,%3}, [%4];"
        : "=r"(r[0]), "=r"(r[1]), "=r"(r[2]), "=r"(r[3]) : "r"(addr));
}
__device__ __forceinline__ void ldsm_x4_trans(uint32_t r[4], uint32_t addr) {
    asm volatile("ldmatrix.sync.aligned.m8n8.x4.trans.shared.b16 {%0,%1,%2,%3}, [%4];"
        : "=r"(r[0]), "=r"(r[1]), "=r"(r[2]), "=r"(r[3]) : "r"(addr));
}
__device__ __forceinline__ void mma_fp16(float c[4], const uint32_t a[4],
                                         uint32_t b0, uint32_t b1) {
    asm volatile("mma.sync.aligned.m16n8k16.row.col.f32.f16.f16.f32 "
        "{%0,%1,%2,%3}, {%4,%5,%6,%7}, {%8,%9}, {%0,%1,%2,%3};"
        : "+f"(c[0]), "+f"(c[1]), "+f"(c[2]), "+f"(c[3])
        : "r"(a[0]), "r"(a[1]), "r"(a[2]), "r"(a[3]), "r"(b0), "r"(b1));
}
__device__ __forceinline__ void split_half(float v, __half& h, __half& l) {
    h = __float2half(v);
    l = __float2half(v - __half2float(h));
}
__device__ __forceinline__ uint32_t pack_hi16(float x, float y) {
    __half2 t(__float2half(x), __float2half(y));
    return *reinterpret_cast<uint32_t*>(&t);
}
__device__ __forceinline__ uint32_t pack_lo16(float x, float y) {
    __half hx = __float2half(x), hy = __float2half(y);
    __half2 t(__float2half(x - __half2float(hx)),
              __float2half(y - __half2float(hy)));
    return *reinterpret_cast<uint32_t*>(&t);
}
__device__ __forceinline__ float gelu_tanh(float x) {
    const float c = 0.7978845608028654f;
    float x3 = x * x * x;
    return 0.5f * x * (1.0f + tanhf(c * (x + 0.044715f * x3)));
}

// ================= scratch =================
__device__ float g_qf[MD];
__device__ float g_attn[MD];
__device__ float g_x1[MD];
__device__ float g_ffp[3 * MD];
__device__ float g_bqkv[QKVN];
__device__ __half g_kv[MROWS * KVW];
__device__ __half g_xh[MD],  g_xl[MD];
__device__ __half g_x1h[MD];
__device__ __half g_hid[MROWS * FF];
__device__ __half g_wqkv[QKVN * DM];
__device__ __half g_w1[FF * DM];
__device__ __half g_w2[DM * FF];

// ========== elementwise fp32 -> fp16 hi/lo ==========
__global__ void split_convert(const float* __restrict__ in,
                              __half* __restrict__ hi,
                              __half* __restrict__ lo, int n4) {
    int i = blockIdx.x * blockDim.x + threadIdx.x;
    if (i >= n4) return;
    float4 v = reinterpret_cast<const float4*>(in)[i];
    __half h0,l0,h1,l1,h2,l2,h3,l3;
    split_half(v.x, h0, l0); split_half(v.y, h1, l1);
    split_half(v.z, h2, l2); split_half(v.w, h3, l3);
    reinterpret_cast<__half2*>(hi)[i*2+0] = __half2(h0, h1);
    reinterpret_cast<__half2*>(hi)[i*2+1] = __half2(h2, h3);
    reinterpret_cast<__half2*>(lo)[i*2+0] = __half2(l0, l1);
    reinterpret_cast<__half2*>(lo)[i*2+1] = __half2(l2, l3);
}

// ========== merged weight transpose (single fp16) + bias pack ==========
__global__ void prep_weights(const float* __restrict__ Wq, const float* __restrict__ Wk,
                             const float* __restrict__ Wv, const float* __restrict__ W1,
                             const float* __restrict__ W2,
                             const float* __restrict__ bq, const float* __restrict__ bk,
                             const float* __restrict__ bv,
                             __half* __restrict__ wqkv,
                             __half* __restrict__ w1,
                             __half* __restrict__ w2,
                             float* __restrict__ bqkv) {
    int id = blockIdx.x;
    if (id >= 6336) {
        int i = (id - 6336) * 256 + threadIdx.x;
        if (i < QKVN)
            bqkv[i] = (i < DM) ? bq[i] : (i < 2 * DM) ? bk[i - DM] : bv[i - 2 * DM];
        return;
    }
    const float* W; __half* T; int K, N, tix;
    if (id < 576)       { W = Wq; T = wqkv;               K = DM; N = DM; tix = id; }
    else if (id < 1152) { W = Wk; T = wqkv + DM * DM;     K = DM; N = DM; tix = id - 576; }
    else if (id < 1728) { W = Wv; T = wqkv + 2 * DM * DM; K = DM; N = DM; tix = id - 1152; }
    else if (id < 4032) { W = W1; T = w1;                 K = DM; N = FF; tix = id - 1728; }
    else                { W = W2; T = w2;                 K = FF; N = DM; tix = id - 4032; }
    int nt = N / 32;
    int n0 = (tix % nt) * 32, k0 = (tix / nt) * 32;
    __shared__ float t[32][33];
    int tx = threadIdx.x & 31, ty = threadIdx.x >> 5;
    #pragma unroll
    for (int i = 0; i < 4; i++)
        t[ty + i*8][tx] = W[(size_t)(k0 + ty + i*8) * N + n0 + tx];
    __syncthreads();
    #pragma unroll
    for (int i = 0; i < 4; i++) {
        T[(size_t)(n0 + ty + i*8) * K + k0 + tx] = __float2half(t[tx][ty + i*8]);
    }
}

// ========== HMMA GEMM: templated on TERMS (A fp16 hi/lo or single) & NSTAGES ====
// mode 0: fp32+bias. mode 1: gelu + single fp16. mode 2: QKV (q fp32*0.125,
// k/v single fp16). mode 3: split-K partial fp32.
// smem/CTA = NSTAGES * (TERMS+1) * 16KB = 96KB -> 2 CTAs/SM.
template<int TERMS, int NSTAGES>
__global__ void __launch_bounds__(256, 2)
tc_gemm(const __half* __restrict__ Ah, const __half* __restrict__ Al,
        const __half* __restrict__ B,
        const float* __restrict__ bias,
        float* __restrict__ outF,
        void* __restrict__ outAux,
        int M, int N, int K, int mode) {
    constexpr uint32_t STAGE = (TERMS + 1) * 16384u;
    extern __shared__ char smem[];
    const uint32_t tiles = smem_to_u32(smem);
    const int tid = threadIdx.x;
    const int wid = tid >> 5;
    const int lane = tid & 31;
    const int warpM = wid >> 1;
    const int warpN = wid & 1;
    const int bm = blockIdx.y * 128;
    const int bn = blockIdx.x * 128;
    const int kb0 = (mode == 3) ? blockIdx.z * 16 : 0;
    const int NB  = (mode == 3) ? 16 : (K >> 6);
    if (mode == 3) outF += (size_t)blockIdx.z * M * N;

    const __half* srcs[2] = {Ah, Al};

    auto stage = [&](int kb, int s) {
        #pragma unroll
        for (int t = 0; t < TERMS + 1; t++) {
            const __half* src = (t < TERMS) ? srcs[t] : B;
            const int rbase = (t < TERMS) ? bm : bn;
            const uint32_t sb = tiles + (uint32_t)s * STAGE + (uint32_t)t * 16384u;
            #pragma unroll
            for (int i = 0; i < 4; i++) {
                int chunk = tid + i * 256;
                int row = chunk >> 3;
                int c16 = chunk & 7;
                uint32_t off = (uint32_t)(row * 128 + c16 * 16);
                uint32_t dst = sb + SMEM_SWIZZLE_128B(off);
                const void* g = src + (size_t)(rbase + row) * K + kb * 64 + c16 * 8;
                asm volatile("cp.async.cg.shared.global [%0], [%1], 16;" :: "r"(dst), "l"(g));
            }
        }
        asm volatile("cp.async.commit_group;" ::: "memory");
    };

    float c[2][8][4] = {};

    stage(kb0, 0);
    if (NSTAGES >= 3 && NB > 1) stage(kb0 + 1, 1);

    const int lrow = lane & 15;
    const int lchunk = lane >> 4;

    for (int kb = 0; kb < NB; kb++) {
        const int s = kb % NSTAGES;
        if (NSTAGES >= 3) {
            if (kb + 1 < NB) asm volatile("cp.async.wait_group 1;" ::: "memory");
            else             asm volatile("cp.async.wait_group 0;" ::: "memory");
            __syncthreads();
            if (kb + 2 < NB) stage(kb0 + kb + 2, (kb + 2) % NSTAGES);
        } else {
            asm volatile("cp.async.wait_group 0;" ::: "memory");
            __syncthreads();
            if (kb + 1 < NB) stage(kb0 + kb + 1, (kb + 1) % NSTAGES);
        }

        const uint32_t base_s = tiles + (uint32_t)s * STAGE;
        const uint32_t baseB = base_s + (uint32_t)TERMS * 16384u;
        #pragma unroll
        for (int ks = 0; ks < 4; ks++) {
            uint32_t ah[2][4], al2[2][4];
            #pragma unroll
            for (int mt = 0; mt < 2; mt++) {
                uint32_t off = (uint32_t)((warpM * 32 + mt * 16 + lrow) * 128 + ks * 32 + lchunk * 16);
                uint32_t sw = SMEM_SWIZZLE_128B(off);
                ldsm_x4(ah[mt], base_s + sw);
                if (TERMS == 2) ldsm_x4(al2[mt], base_s + 16384u + sw);
            }
            uint32_t bb[2][4];
            {
                uint32_t off0 = (uint32_t)((warpN * 64 + lrow) * 128 + ks * 32 + lchunk * 16);
                ldsm_x4(bb[0], baseB + SMEM_SWIZZLE_128B(off0));
            }
            #pragma unroll
            for (int np = 0; np < 4; np++) {
                const int cur = np & 1;
                if (np < 3) {
                    uint32_t off = (uint32_t)((warpN * 64 + (np + 1) * 16 + lrow) * 128 + ks * 32 + lchunk * 16);
                    ldsm_x4(bb[cur ^ 1], baseB + SMEM_SWIZZLE_128B(off));
                }
                #pragma unroll
                for (int mt = 0; mt < 2; mt++) {
                    mma_fp16(c[mt][2*np],   ah[mt], bb[cur][0], bb[cur][2]);
                    mma_fp16(c[mt][2*np+1], ah[mt], bb[cur][1], bb[cur][3]);
                    if (TERMS == 2) {
                        mma_fp16(c[mt][2*np],   al2[mt], bb[cur][0], bb[cur][2]);
                        mma_fp16(c[mt][2*np+1], al2[mt], bb[cur][1], bb[cur][3]);
                    }
                }
            }
        }
        if (NSTAGES == 2) __syncthreads();   // compute(kb) done before next overwrite
    }
    __syncthreads();

    float* sD = reinterpret_cast<float*>(smem);   // 128 x 129 (66KB <= 96KB)
    #pragma unroll
    for (int mt = 0; mt < 2; mt++) {
        #pragma unroll
        for (int nt = 0; nt < 8; nt++) {
            int r0 = warpM * 32 + mt * 16 + (lane >> 2);
            int col = warpN * 64 + nt * 8 + (lane & 3) * 2;
            sD[r0 * 129 + col]           = c[mt][nt][0];
            sD[r0 * 129 + col + 1]       = c[mt][nt][1];
            sD[(r0 + 8) * 129 + col]     = c[mt][nt][2];
            sD[(r0 + 8) * 129 + col + 1] = c[mt][nt][3];
        }
    }
    __syncthreads();

    for (int idx = tid; idx < 128 * 128; idx += 256) {
        int r = idx >> 7, cc = idx & 127;
        float v = sD[r * 129 + cc];
        size_t row = (size_t)(bm + r);
        int gc = bn + cc;
        if (mode == 3) {
            outF[row * N + gc] = v;
            continue;
        }
        v += bias[gc];
        if (mode == 0) {
            outF[row * N + gc] = v;
        } else if (mode == 1) {
            v = gelu_tanh(v);
            ((__half*)outAux)[row * N + gc] = __float2half(v);
        } else {
            if (gc < DM) {
                outF[row * DM + gc] = v * 0.125f;
            } else {
                ((__half*)outAux)[row * KVW + (gc - DM)] = __float2half(v);
            }
        }
    }
}

// ================= HMMA sliding-window attention (R11: 2-term fp16) ============
#define AQH 0
#define AQL 8192
#define AK  16384
#define AV  40960
#define ATTN_SMEM 65536
__global__ void __launch_bounds__(128, 2)
attn_kernel(const float* __restrict__ qf,
            const __half* __restrict__ kv,
            float* __restrict__ out) {
    extern __shared__ char smem[];
    const uint32_t sb = smem_to_u32(smem);
    const int c = blockIdx.x, h = blockIdx.y, b = blockIdx.z;
    const int tid = threadIdx.x, warp = tid >> 5, lane = tid & 31;

    for (int idx = tid; idx < 64 * 16; idx += 128) {
        int r = idx >> 4, ch = idx & 15;
        float4 v = *reinterpret_cast<const float4*>(
            &qf[((size_t)b * SS + c * 64 + r) * DM + h * HD + ch * 4]);
        uint32_t off = SMEM_SWIZZLE_128B((uint32_t)(r * 128 + ch * 8));
        uint2 hh, ll;
        hh.x = pack_hi16(v.x, v.y); hh.y = pack_hi16(v.z, v.w);
        ll.x = pack_lo16(v.x, v.y); ll.y = pack_lo16(v.z, v.w);
        *reinterpret_cast<uint2*>(smem + AQH + off) = hh;
        *reinterpret_cast<uint2*>(smem + AQL + off) = ll;
    }
    for (int idx = tid; idx < 192 * 8; idx += 128) {
        int j = idx >> 3, ch = idx & 7;
        int g = c * 64 - 64 + j;
        uint4 z = {0, 0, 0, 0};
        uint4 k4 = z, v4 = z;
        if (g >= 0 && g < SS) {
            size_t rb = ((size_t)b * SS + g) * KVW + h * HD + ch * 8;
            k4 = *reinterpret_cast<const uint4*>(&kv[rb]);
            v4 = *reinterpret_cast<const uint4*>(&kv[rb + DM]);
        }
        uint32_t off = SMEM_SWIZZLE_128B((uint32_t)(j * 128 + ch * 16));
        *reinterpret_cast<uint4*>(smem + AK + off) = k4;
        *reinterpret_cast<uint4*>(smem + AV + off) = v4;
    }
    __syncthreads();

    const int m0 = warp * 16;
    const int lrow = lane & 15;
    const int lch = lane >> 4;

    float s[24][4];
    #pragma unroll
    for (int nt = 0; nt < 24; nt++)
        #pragma unroll
        for (int u = 0; u < 4; u++) s[nt][u] = 0.f;

    #pragma unroll
    for (int ks = 0; ks < 4; ks++) {
        uint32_t aoff = SMEM_SWIZZLE_128B((uint32_t)((m0 + lrow) * 128 + ks * 32 + lch * 16));
        uint32_t ah[4], al[4];
        ldsm_x4(ah, sb + AQH + aoff);
        ldsm_x4(al, sb + AQL + aoff);
        #pragma unroll
        for (int n6 = 0; n6 < 12; n6++) {
            uint32_t boff = SMEM_SWIZZLE_128B((uint32_t)((n6 * 16 + lrow) * 128 + ks * 32 + lch * 16));
            uint32_t bk4[4];
            ldsm_x4(bk4, sb + AK + boff);
            mma_fp16(s[2*n6],   ah, bk4[0], bk4[2]);
            mma_fp16(s[2*n6+1], ah, bk4[1], bk4[3]);
            mma_fp16(s[2*n6],   al, bk4[0], bk4[2]);
            mma_fp16(s[2*n6+1], al, bk4[1], bk4[3]);
        }
    }

    const int rA = m0 + (lane >> 2);
    const int rB = rA + 8;
    const int jb = 2 * (lane & 3);
    const int gof = c * 64 - 64;
    float mA = -INFINITY, mB = -INFINITY;
    #pragma unroll
    for (int nt = 0; nt < 24; nt++) {
        int j0 = nt * 8 + jb, j1 = j0 + 1;
        int g0 = gof + j0, g1 = gof + j1;
        bool in0 = (g0 >= 0) && (g0 < SS);
        bool in1 = (g1 >= 0) && (g1 < SS);
        if (!((j0 >= rA) && (j0 <= rA + 128) && in0)) s[nt][0] = -INFINITY;
        if (!((j1 >= rA) && (j1 <= rA + 128) && in1)) s[nt][1] = -INFINITY;
        if (!((j0 >= rB) && (j0 <= rB + 128) && in0)) s[nt][2] = -INFINITY;
        if (!((j1 >= rB) && (j1 <= rB + 128) && in1)) s[nt][3] = -INFINITY;
        mA = fmaxf(mA, fmaxf(s[nt][0], s[nt][1]));
        mB = fmaxf(mB, fmaxf(s[nt][2], s[nt][3]));
    }
    mA = fmaxf(mA, __shfl_xor_sync(0xffffffffu, mA, 1));
    mA = fmaxf(mA, __shfl_xor_sync(0xffffffffu, mA, 2));
    mB = fmaxf(mB, __shfl_xor_sync(0xffffffffu, mB, 1));
    mB = fmaxf(mB, __shfl_xor_sync(0xffffffffu, mB, 2));
    float sA = 0.f, sB = 0.f;
    #pragma unroll
    for (int nt = 0; nt < 24; nt++) {
        s[nt][0] = __expf(s[nt][0] - mA);
        s[nt][1] = __expf(s[nt][1] - mA);
        s[nt][2] = __expf(s[nt][2] - mB);
        s[nt][3] = __expf(s[nt][3] - mB);
        sA += s[nt][0] + s[nt][1];
        sB += s[nt][2] + s[nt][3];
    }
    sA += __shfl_xor_sync(0xffffffffu, sA, 1);
    sA += __shfl_xor_sync(0xffffffffu, sA, 2);
    sB += __shfl_xor_sync(0xffffffffu, sB, 1);
    sB += __shfl_xor_sync(0xffffffffu, sB, 2);
    const float invA = 1.0f / sA, invB = 1.0f / sB;

    float o[8][4];
    #pragma unroll
    for (int nt = 0; nt < 8; nt++)
        #pragma unroll
        for (int u = 0; u < 4; u++) o[nt][u] = 0.f;

    #pragma unroll
    for (int t = 0; t < 12; t++) {
        uint32_t ph[4], pl[4];
        ph[0] = pack_hi16(s[2*t][0],   s[2*t][1]);
        ph[1] = pack_hi16(s[2*t][2],   s[2*t][3]);
        ph[2] = pack_hi16(s[2*t+1][0], s[2*t+1][1]);
        ph[3] = pack_hi16(s[2*t+1][2], s[2*t+1][3]);
        pl[0] = pack_lo16(s[2*t][0],   s[2*t][1]);
        pl[1] = pack_lo16(s[2*t][2],   s[2*t][3]);
        pl[2] = pack_lo16(s[2*t+1][0], s[2*t+1][1]);
        pl[3] = pack_lo16(s[2*t+1][2], s[2*t+1][3]);
        #pragma unroll
        for (int nn = 0; nn < 4; nn++) {
            uint32_t voff = SMEM_SWIZZLE_128B(
                (uint32_t)((t * 16 + (lane & 15)) * 128 + (nn * 16 + (lane >> 4) * 8) * 2));
            uint32_t vv[4];
            ldsm_x4_trans(vv, sb + AV + voff);
            mma_fp16(o[2*nn],   ph, vv[0], vv[1]);
            mma_fp16(o[2*nn+1], ph, vv[2], vv[3]);
            mma_fp16(o[2*nn],   pl, vv[0], vv[1]);
            mma_fp16(o[2*nn+1], pl, vv[2], vv[3]);
        }
    }

    const size_t rowg = (size_t)b * SS + c * 64;
    #pragma unroll
    for (int nt = 0; nt < 8; nt++) {
        int col = h * HD + nt * 8 + jb;
        float2 v0 = make_float2(o[nt][0] * invA, o[nt][1] * invA);
        float2 v1 = make_float2(o[nt][2] * invB, o[nt][3] * invB);
        *reinterpret_cast<float2*>(&out[(rowg + rA) * DM + col]) = v0;
        *reinterpret_cast<float2*>(&out[(rowg + rB) * DM + col]) = v1;
    }
}

// ============ warp-per-row residual + LayerNorm (single fp16 emit) ============
__global__ void __launch_bounds__(256)
add_ln_kernel(const float* __restrict__ a,
              const float* __restrict__ r,
              const float* __restrict__ g,
              const float* __restrict__ beta,
              float* __restrict__ out,
              __half* __restrict__ outH) {
    const int warp = threadIdx.x >> 5, lane = threadIdx.x & 31;
    const int row = blockIdx.x * 8 + warp;
    const float4* pa = reinterpret_cast<const float4*>(a + (size_t)row * DM);
    const float4* pr = reinterpret_cast<const float4*>(r + (size_t)row * DM);
    const float4* pg = reinterpret_cast<const float4*>(g);
    const float4* pb = reinterpret_cast<const float4*>(beta);

    float4 v[6];
    float sum = 0.f;
    #pragma unroll
    for (int ch = 0; ch < 6; ch++) {
        float4 va = pa[lane + 32 * ch];
        float4 vr = pr[lane + 32 * ch];
        v[ch] = make_float4(va.x + vr.x, va.y + vr.y, va.z + vr.z, va.w + vr.w);
        sum += v[ch].x + v[ch].y + v[ch].z + v[ch].w;
    }
    #pragma unroll
    for (int o = 16; o > 0; o >>= 1) sum += __shfl_xor_sync(0xffffffffu, sum, o);
    float mu = sum * (1.0f / DM);

    float var = 0.f;
    #pragma unroll
    for (int ch = 0; ch < 6; ch++) {
        float dx = v[ch].x - mu, dy = v[ch].y - mu, dz = v[ch].z - mu, dw = v[ch].w - mu;
        var += dx * dx + dy * dy + dz * dz + dw * dw;
    }
    #pragma unroll
    for (int o = 16; o > 0; o >>= 1) var += __shfl_xor_sync(0xffffffffu, var, o);
    float rstd = rsqrtf(var * (1.0f / DM) + 1e-5f);

    float4* po = reinterpret_cast<float4*>(out + (size_t)row * DM);
    #pragma unroll
    for (int ch = 0; ch < 6; ch++) {
        float4 gg = pg[lane + 32 * ch];
        float4 bb = pb[lane + 32 * ch];
        float4 y;
        y.x = (v[ch].x - mu) * rstd * gg.x + bb.x;
        y.y = (v[ch].y - mu) * rstd * gg.y + bb.y;
        y.z = (v[ch].z - mu) * rstd * gg.z + bb.z;
        y.w = (v[ch].w - mu) * rstd * gg.w + bb.w;
        po[lane + 32 * ch] = y;
        if (outH) {
            size_t o4 = (size_t)row * DM + (lane + 32 * ch) * 4;
            reinterpret_cast<__half2*>(outH + o4)[0] =
                __half2(__float2half(y.x), __float2half(y.y));
            reinterpret_cast<__half2*>(outH + o4)[1] =
                __half2(__float2half(y.z), __float2half(y.w));
        }
    }
}

// ===== final LN: out = LN(p0+p1+p2 + bias2 + x1) =====
__global__ void __launch_bounds__(256)
add_ln3_kernel(const float* __restrict__ p,
               const float* __restrict__ r,
               const float* __restrict__ bias2,
               const float* __restrict__ g,
               const float* __restrict__ beta,
               float* __restrict__ out) {
    const int warp = threadIdx.x >> 5, lane = threadIdx.x & 31;
    const int row = blockIdx.x * 8 + warp;
    const float4* p0 = reinterpret_cast<const float4*>(p + (size_t)row * DM);
    const float4* p1 = reinterpret_cast<const float4*>(p + (size_t)row * DM + MD);
    const float4* p2 = reinterpret_cast<const float4*>(p + (size_t)row * DM + 2 * (size_t)MD);
    const float4* pr = reinterpret_cast<const float4*>(r + (size_t)row * DM);
    const float4* pb2 = reinterpret_cast<const float4*>(bias2);
    const float4* pg = reinterpret_cast<const float4*>(g);
    const float4* pb = reinterpret_cast<const float4*>(beta);

    float4 v[6];
    float sum = 0.f;
    #pragma unroll
    for (int ch = 0; ch < 6; ch++) {
        float4 a0 = p0[lane + 32 * ch];
        float4 a1 = p1[lane + 32 * ch];
        float4 a2 = p2[lane + 32 * ch];
        float4 vr = pr[lane + 32 * ch];
        float4 b2 = pb2[lane + 32 * ch];
        v[ch] = make_float4(a0.x + a1.x + a2.x + b2.x + vr.x,
                            a0.y + a1.y + a2.y + b2.y + vr.y,
                            a0.z + a1.z + a2.z + b2.z + vr.z,
                            a0.w + a1.w + a2.w + b2.w + vr.w);
        sum += v[ch].x + v[ch].y + v[ch].z + v[ch].w;
    }
    #pragma unroll
    for (int o = 16; o > 0; o >>= 1) sum += __shfl_xor_sync(0xffffffffu, sum, o);
    float mu = sum * (1.0f / DM);

    float var = 0.f;
    #pragma unroll
    for (int ch = 0; ch < 6; ch++) {
        float dx = v[ch].x - mu, dy = v[ch].y - mu, dz = v[ch].z - mu, dw = v[ch].w - mu;
        var += dx * dx + dy * dy + dz * dz + dw * dw;
    }
    #pragma unroll
    for (int o = 16; o > 0; o >>= 1) var += __shfl_xor_sync(0xffffffffu, var, o);
    float rstd = rsqrtf(var * (1.0f / DM) + 1e-5f);

    float4* po = reinterpret_cast<float4*>(out + (size_t)row * DM);
    #pragma unroll
    for (int ch = 0; ch < 6; ch++) {
        float4 gg = pg[lane + 32 * ch];
        float4 bb = pb[lane + 32 * ch];
        float4 y;
        y.x = (v[ch].x - mu) * rstd * gg.x + bb.x;
        y.y = (v[ch].y - mu) * rstd * gg.y + bb.y;
        y.z = (v[ch].z - mu) * rstd * gg.z + bb.z;
        y.w = (v[ch].w - mu) * rstd * gg.w + bb.w;
        po[lane + 32 * ch] = y;
    }
}

// ================= launch =================
extern "C" void kernel_launch(void* const* d_in, const int* in_sizes, int n_in,
                              void* d_out, int out_size) {
    const float* x     = (const float*)d_in[0];
    const float* Wq    = (const float*)d_in[1];
    const float* bq    = (const float*)d_in[2];
    const float* Wk    = (const float*)d_in[3];
    const float* bk    = (const float*)d_in[4];
    const float* Wv    = (const float*)d_in[5];
    const float* bv    = (const float*)d_in[6];
    const float* ln1_g = (const float*)d_in[7];
    const float* ln1_b = (const float*)d_in[8];
    const float* W1    = (const float*)d_in[9];
    const float* b1    = (const float*)d_in[10];
    const float* W2    = (const float*)d_in[11];
    const float* b2    = (const float*)d_in[12];
    const float* ln2_g = (const float*)d_in[13];
    const float* ln2_b = (const float*)d_in[14];
    float* out = (float*)d_out;

    float *qf, *attn, *x1, *ffp, *bqkv;
    __half *kv, *xh, *xl, *x1h, *hid, *wqkv, *w1, *w2;
    cudaGetSymbolAddress((void**)&qf, g_qf);     cudaGetSymbolAddress((void**)&attn, g_attn);
    cudaGetSymbolAddress((void**)&x1, g_x1);     cudaGetSymbolAddress((void**)&ffp, g_ffp);
    cudaGetSymbolAddress((void**)&bqkv, g_bqkv);
    cudaGetSymbolAddress((void**)&kv, g_kv);
    cudaGetSymbolAddress((void**)&xh, g_xh);     cudaGetSymbolAddress((void**)&xl, g_xl);
    cudaGetSymbolAddress((void**)&x1h, g_x1h);
    cudaGetSymbolAddress((void**)&hid, g_hid);
    cudaGetSymbolAddress((void**)&wqkv, g_wqkv);
    cudaGetSymbolAddress((void**)&w1, g_w1);     cudaGetSymbolAddress((void**)&w2, g_w2);

    const int SMEM_Q = 2 * 3 * 16384;   // 2-term, 2 stages = 96KB
    const int SMEM_F = 3 * 2 * 16384;   // 1-term, 3 stages = 96KB
    cudaFuncSetAttribute((const void*)tc_gemm<2,2>, cudaFuncAttributeMaxDynamicSharedMemorySize, SMEM_Q);
    cudaFuncSetAttribute((const void*)tc_gemm<1,3>, cudaFuncAttributeMaxDynamicSharedMemorySize, SMEM_F);
    cudaFuncSetAttribute(attn_kernel, cudaFuncAttributeMaxDynamicSharedMemorySize, ATTN_SMEM);

    // ---- convert inputs ----
    {
        int n4 = MROWS * DM / 4;
        split_convert<<<(n4 + 255) / 256, 256>>>(x, xh, xl, n4);
        prep_weights<<<6345, 256>>>(Wq, Wk, Wv, W1, W2, bq, bk, bv,
                                    wqkv, w1, w2, bqkv);
    }

    // ---- fused QKV projection (2-term, 2-stage): q fp32 (scaled), k/v fp16 ----
    {
        dim3 grid(QKVN / 128, MROWS / 128);
        tc_gemm<2,2><<<grid, 256, SMEM_Q>>>(xh, xl, wqkv, bqkv, qf,
                                            kv, MROWS, QKVN, DM, 2);
    }

    // ---- attention (HMMA, 2-term fp16) ----
    {
        dim3 grid(NC, NH, BB);
        attn_kernel<<<grid, 128, ATTN_SMEM>>>(qf, kv, attn);
    }

    // ---- x1 = LN(attn + x), emit single fp16 ----
    add_ln_kernel<<<MROWS / 8, 256>>>(attn, x, ln1_g, ln1_b, x1, x1h);

    // ---- FFN (1-term, 3-stage, 2 CTAs/SM) ----
    {
        dim3 grid1(FF / 128, MROWS / 128);
        tc_gemm<1,3><<<grid1, 256, SMEM_F>>>(x1h, nullptr, w1, b1, nullptr,
                                             hid, MROWS, FF, DM, 1);
        dim3 grid2(DM / 128, MROWS / 128, 3);   // split-K = 3
        tc_gemm<1,3><<<grid2, 256, SMEM_F>>>(hid, nullptr, w2, nullptr, ffp,
                                             nullptr, MROWS, DM, FF, 3);
    }

    // ---- out = LN(p0+p1+p2 + b2 + x1) ----
    add_ln3_kernel<<<MROWS / 8, 256>>>(ffp, x1, b2, ln2_g, ln2_b, out);
}

// round 14
// speedup vs baseline: 2.2580x; 1.0738x over previous
#include <cuda_runtime.h>
#include <cuda_bf16.h>
#include <cuda_fp16.h>
#include <math.h>
#include <cstdint>

#define BB 2
#define SS 4096
#define DM 768
#define NH 12
#define FF 3072
#define WIN 64
#define HD 64
#define NC (SS / WIN)
#define MROWS (BB * SS)    // 8192
#define QKVN (3 * DM)      // 2304
#define KVW (2 * DM)       // 1536
#define MD (MROWS * DM)

// ================= helpers =================
__device__ __forceinline__ uint32_t smem_to_u32(const void* p) {
    uint32_t a;
    asm("{ .reg .u64 t; cvta.to.shared.u64 t, %1; cvt.u32.u64 %0, t; }" : "=r"(a) : "l"(p));
    return a;
}
#define SMEM_SWIZZLE_128B(o) ((o) ^ (((o) >> 3) & 0x70))

__device__ __forceinline__ void ldsm_x4(uint32_t r[4], uint32_t addr) {
    asm volatile("ldmatrix.sync.aligned.m8n8.x4.shared.b16 {%0,%1,%2,%3}, [%4];"
        : "=r"(r[0]), "=r"(r[1]), "=r"(r[2]), "=r"(r[3]) : "r"(addr));
}
__device__ __forceinline__ void ldsm_x4_trans(uint32_t r[4], uint32_t addr) {
    asm volatile("ldmatrix.sync.aligned.m8n8.x4.trans.shared.b16 {%0,%1,%2,%3}, [%4];"
        : "=r"(r[0]), "=r"(r[1]), "=r"(r[2]), "=r"(r[3]) : "r"(addr));
}
__device__ __forceinline__ void mma_fp16(float c[4], const uint32_t a[4],
                                         uint32_t b0, uint32_t b1) {
    asm volatile("mma.sync.aligned.m16n8k16.row.col.f32.f16.f16.f32 "
        "{%0,%1,%2,%3}, {%4,%5,%6,%7}, {%8,%9}, {%0,%1,%2,%3};"
        : "+f"(c[0]), "+f"(c[1]), "+f"(c[2]), "+f"(c[3])
        : "r"(a[0]), "r"(a[1]), "r"(a[2]), "r"(a[3]), "r"(b0), "r"(b1));
}
__device__ __forceinline__ void split_half(float v, __half& h, __half& l) {
    h = __float2half(v);
    l = __float2half(v - __half2float(h));
}
__device__ __forceinline__ uint32_t pack_hi16(float x, float y) {
    __half2 t(__float2half(x), __float2half(y));
    return *reinterpret_cast<uint32_t*>(&t);
}
__device__ __forceinline__ uint32_t pack_lo16(float x, float y) {
    __half hx = __float2half(x), hy = __float2half(y);
    __half2 t(__float2half(x - __half2float(hx)),
              __float2half(y - __half2float(hy)));
    return *reinterpret_cast<uint32_t*>(&t);
}
__device__ __forceinline__ float gelu_tanh(float x) {
    const float c = 0.7978845608028654f;
    float x3 = x * x * x;
    return 0.5f * x * (1.0f + tanhf(c * (x + 0.044715f * x3)));
}

// ================= scratch =================
__device__ float g_attn[MD];
__device__ float g_bqkv[QKVN];
__device__ __half g_qh[MD], g_ql[MD];         // q pre-scaled fp16 hi/lo
__device__ __half g_kv[MROWS * KVW];
__device__ __half g_xh[MD],  g_xl[MD];
__device__ __half g_x1h[MD];
__device__ __half g_hid[MROWS * FF];
__device__ __half g_ffp[3 * MD];              // FFN2 split-K partials (fp16)
__device__ __half g_wqkv[QKVN * DM];
__device__ __half g_w1[FF * DM];
__device__ __half g_w2[DM * FF];

// ========== merged prep: weight transpose + bias pack + x split ==========
// blocks [0,6336): weight tiles; [6336,6345): bias; [6345,12489): x split.
__global__ void prep_all(const float* __restrict__ x,
                         const float* __restrict__ Wq, const float* __restrict__ Wk,
                         const float* __restrict__ Wv, const float* __restrict__ W1,
                         const float* __restrict__ W2,
                         const float* __restrict__ bq, const float* __restrict__ bk,
                         const float* __restrict__ bv,
                         __half* __restrict__ wqkv,
                         __half* __restrict__ w1,
                         __half* __restrict__ w2,
                         float* __restrict__ bqkv,
                         __half* __restrict__ xh, __half* __restrict__ xl) {
    int id = blockIdx.x;
    if (id >= 6345) {
        int i = (id - 6345) * 256 + threadIdx.x;   // float4 index, n4 = 1572864
        float4 v = reinterpret_cast<const float4*>(x)[i];
        __half h0,l0,h1,l1,h2,l2,h3,l3;
        split_half(v.x, h0, l0); split_half(v.y, h1, l1);
        split_half(v.z, h2, l2); split_half(v.w, h3, l3);
        reinterpret_cast<__half2*>(xh)[i*2+0] = __half2(h0, h1);
        reinterpret_cast<__half2*>(xh)[i*2+1] = __half2(h2, h3);
        reinterpret_cast<__half2*>(xl)[i*2+0] = __half2(l0, l1);
        reinterpret_cast<__half2*>(xl)[i*2+1] = __half2(l2, l3);
        return;
    }
    if (id >= 6336) {
        int i = (id - 6336) * 256 + threadIdx.x;
        if (i < QKVN)
            bqkv[i] = (i < DM) ? bq[i] : (i < 2 * DM) ? bk[i - DM] : bv[i - 2 * DM];
        return;
    }
    const float* W; __half* T; int K, N, tix;
    if (id < 576)       { W = Wq; T = wqkv;               K = DM; N = DM; tix = id; }
    else if (id < 1152) { W = Wk; T = wqkv + DM * DM;     K = DM; N = DM; tix = id - 576; }
    else if (id < 1728) { W = Wv; T = wqkv + 2 * DM * DM; K = DM; N = DM; tix = id - 1152; }
    else if (id < 4032) { W = W1; T = w1;                 K = DM; N = FF; tix = id - 1728; }
    else                { W = W2; T = w2;                 K = FF; N = DM; tix = id - 4032; }
    int nt = N / 32;
    int n0 = (tix % nt) * 32, k0 = (tix / nt) * 32;
    __shared__ float t[32][33];
    int tx = threadIdx.x & 31, ty = threadIdx.x >> 5;
    #pragma unroll
    for (int i = 0; i < 4; i++)
        t[ty + i*8][tx] = W[(size_t)(k0 + ty + i*8) * N + n0 + tx];
    __syncthreads();
    #pragma unroll
    for (int i = 0; i < 4; i++) {
        T[(size_t)(n0 + ty + i*8) * K + k0 + tx] = __float2half(t[tx][ty + i*8]);
    }
}

// ========== HMMA GEMM: templated on TERMS & NSTAGES (96KB smem, 2 CTAs/SM) =====
// mode 0: fp32+bias. mode 1: gelu + single fp16 (outAux). mode 2: QKV
// (q*0.125 fp16 hi/lo -> outAux/outAux2, k/v fp16 -> outF-as-half).
// mode 3: split-K fp16 partials (outAux + z*M*N).
template<int TERMS, int NSTAGES>
__global__ void __launch_bounds__(256, 2)
tc_gemm(const __half* __restrict__ Ah, const __half* __restrict__ Al,
        const __half* __restrict__ B,
        const float* __restrict__ bias,
        float* __restrict__ outF,
        void* __restrict__ outAux, void* __restrict__ outAux2,
        int M, int N, int K, int mode) {
    constexpr uint32_t STAGE = (TERMS + 1) * 16384u;
    extern __shared__ char smem[];
    const uint32_t tiles = smem_to_u32(smem);
    const int tid = threadIdx.x;
    const int wid = tid >> 5;
    const int lane = tid & 31;
    const int warpM = wid >> 1;
    const int warpN = wid & 1;
    const int bm = blockIdx.y * 128;
    const int bn = blockIdx.x * 128;
    const int kb0 = (mode == 3) ? blockIdx.z * 16 : 0;
    const int NB  = (mode == 3) ? 16 : (K >> 6);
    __half* aux  = (__half*)outAux;
    __half* aux2 = (__half*)outAux2;
    if (mode == 3) aux += (size_t)blockIdx.z * M * N;

    const __half* srcs[2] = {Ah, Al};

    auto stage = [&](int kb, int s) {
        #pragma unroll
        for (int t = 0; t < TERMS + 1; t++) {
            const __half* src = (t < TERMS) ? srcs[t] : B;
            const int rbase = (t < TERMS) ? bm : bn;
            const uint32_t sb = tiles + (uint32_t)s * STAGE + (uint32_t)t * 16384u;
            #pragma unroll
            for (int i = 0; i < 4; i++) {
                int chunk = tid + i * 256;
                int row = chunk >> 3;
                int c16 = chunk & 7;
                uint32_t off = (uint32_t)(row * 128 + c16 * 16);
                uint32_t dst = sb + SMEM_SWIZZLE_128B(off);
                const void* g = src + (size_t)(rbase + row) * K + kb * 64 + c16 * 8;
                asm volatile("cp.async.cg.shared.global [%0], [%1], 16;" :: "r"(dst), "l"(g));
            }
        }
        asm volatile("cp.async.commit_group;" ::: "memory");
    };

    float c[2][8][4] = {};

    stage(kb0, 0);
    if (NSTAGES >= 3 && NB > 1) stage(kb0 + 1, 1);

    const int lrow = lane & 15;
    const int lchunk = lane >> 4;

    for (int kb = 0; kb < NB; kb++) {
        const int s = kb % NSTAGES;
        if (NSTAGES >= 3) {
            if (kb + 1 < NB) asm volatile("cp.async.wait_group 1;" ::: "memory");
            else             asm volatile("cp.async.wait_group 0;" ::: "memory");
            __syncthreads();
            if (kb + 2 < NB) stage(kb0 + kb + 2, (kb + 2) % NSTAGES);
        } else {
            asm volatile("cp.async.wait_group 0;" ::: "memory");
            __syncthreads();
            if (kb + 1 < NB) stage(kb0 + kb + 1, (kb + 1) % NSTAGES);
        }

        const uint32_t base_s = tiles + (uint32_t)s * STAGE;
        const uint32_t baseB = base_s + (uint32_t)TERMS * 16384u;
        #pragma unroll
        for (int ks = 0; ks < 4; ks++) {
            uint32_t ah[2][4], al2[2][4];
            #pragma unroll
            for (int mt = 0; mt < 2; mt++) {
                uint32_t off = (uint32_t)((warpM * 32 + mt * 16 + lrow) * 128 + ks * 32 + lchunk * 16);
                uint32_t sw = SMEM_SWIZZLE_128B(off);
                ldsm_x4(ah[mt], base_s + sw);
                if (TERMS == 2) ldsm_x4(al2[mt], base_s + 16384u + sw);
            }
            uint32_t bb[2][4];
            {
                uint32_t off0 = (uint32_t)((warpN * 64 + lrow) * 128 + ks * 32 + lchunk * 16);
                ldsm_x4(bb[0], baseB + SMEM_SWIZZLE_128B(off0));
            }
            #pragma unroll
            for (int np = 0; np < 4; np++) {
                const int cur = np & 1;
                if (np < 3) {
                    uint32_t off = (uint32_t)((warpN * 64 + (np + 1) * 16 + lrow) * 128 + ks * 32 + lchunk * 16);
                    ldsm_x4(bb[cur ^ 1], baseB + SMEM_SWIZZLE_128B(off));
                }
                #pragma unroll
                for (int mt = 0; mt < 2; mt++) {
                    mma_fp16(c[mt][2*np],   ah[mt], bb[cur][0], bb[cur][2]);
                    mma_fp16(c[mt][2*np+1], ah[mt], bb[cur][1], bb[cur][3]);
                    if (TERMS == 2) {
                        mma_fp16(c[mt][2*np],   al2[mt], bb[cur][0], bb[cur][2]);
                        mma_fp16(c[mt][2*np+1], al2[mt], bb[cur][1], bb[cur][3]);
                    }
                }
            }
        }
        if (NSTAGES == 2) __syncthreads();
    }
    __syncthreads();

    float* sD = reinterpret_cast<float*>(smem);   // 128 x 129
    #pragma unroll
    for (int mt = 0; mt < 2; mt++) {
        #pragma unroll
        for (int nt = 0; nt < 8; nt++) {
            int r0 = warpM * 32 + mt * 16 + (lane >> 2);
            int col = warpN * 64 + nt * 8 + (lane & 3) * 2;
            sD[r0 * 129 + col]           = c[mt][nt][0];
            sD[r0 * 129 + col + 1]       = c[mt][nt][1];
            sD[(r0 + 8) * 129 + col]     = c[mt][nt][2];
            sD[(r0 + 8) * 129 + col + 1] = c[mt][nt][3];
        }
    }
    __syncthreads();

    for (int idx = tid; idx < 128 * 128; idx += 256) {
        int r = idx >> 7, cc = idx & 127;
        float v = sD[r * 129 + cc];
        size_t row = (size_t)(bm + r);
        int gc = bn + cc;
        if (mode == 3) {
            aux[row * N + gc] = __float2half(v);
            continue;
        }
        v += bias[gc];
        if (mode == 0) {
            outF[row * N + gc] = v;
        } else if (mode == 1) {
            v = gelu_tanh(v);
            aux[row * N + gc] = __float2half(v);
        } else {
            if (gc < DM) {
                float q = v * 0.125f;
                __half h, l; split_half(q, h, l);
                aux[row * DM + gc]  = h;
                aux2[row * DM + gc] = l;
            } else {
                ((__half*)outF)[row * KVW + (gc - DM)] = __float2half(v);
            }
        }
    }
}

// ================= HMMA sliding-window attention (cp.async loads) ==============
#define AQH 0
#define AQL 8192
#define AK  16384
#define AV  40960
#define ATTN_SMEM 65536
__global__ void __launch_bounds__(128, 2)
attn_kernel(const __half* __restrict__ qh, const __half* __restrict__ ql,
            const __half* __restrict__ kv,
            float* __restrict__ out) {
    extern __shared__ char smem[];
    const uint32_t sb = smem_to_u32(smem);
    const int c = blockIdx.x, h = blockIdx.y, b = blockIdx.z;
    const int tid = threadIdx.x, warp = tid >> 5, lane = tid & 31;

    // ---- q hi/lo: straight cp.async copies (pre-scaled, pre-split) ----
    for (int idx = tid; idx < 64 * 8; idx += 128) {
        int r = idx >> 3, ch = idx & 7;
        uint32_t off = SMEM_SWIZZLE_128B((uint32_t)(r * 128 + ch * 16));
        size_t gsrc = ((size_t)b * SS + c * 64 + r) * DM + h * HD + ch * 8;
        asm volatile("cp.async.cg.shared.global [%0], [%1], 16;"
                     :: "r"(sb + AQH + off), "l"(qh + gsrc));
        asm volatile("cp.async.cg.shared.global [%0], [%1], 16;"
                     :: "r"(sb + AQL + off), "l"(ql + gsrc));
    }
    // ---- k/v window: cp.async with zero-fill for OOB rows ----
    for (int idx = tid; idx < 192 * 8; idx += 128) {
        int j = idx >> 3, ch = idx & 7;
        int g = c * 64 - 64 + j;
        int in = (g >= 0 && g < SS);
        // clamp src to a valid address; src-size=0 zero-fills when OOB
        size_t rb = ((size_t)b * SS + (in ? g : 0)) * KVW + h * HD + ch * 8;
        uint32_t off = SMEM_SWIZZLE_128B((uint32_t)(j * 128 + ch * 16));
        int sz = in ? 16 : 0;
        asm volatile("cp.async.cg.shared.global [%0], [%1], 16, %2;"
                     :: "r"(sb + AK + off), "l"(kv + rb), "r"(sz));
        asm volatile("cp.async.cg.shared.global [%0], [%1], 16, %2;"
                     :: "r"(sb + AV + off), "l"(kv + rb + DM), "r"(sz));
    }
    asm volatile("cp.async.commit_group;" ::: "memory");
    asm volatile("cp.async.wait_group 0;" ::: "memory");
    __syncthreads();

    const int m0 = warp * 16;
    const int lrow = lane & 15;
    const int lch = lane >> 4;

    float s[24][4];
    #pragma unroll
    for (int nt = 0; nt < 24; nt++)
        #pragma unroll
        for (int u = 0; u < 4; u++) s[nt][u] = 0.f;

    #pragma unroll
    for (int ks = 0; ks < 4; ks++) {
        uint32_t aoff = SMEM_SWIZZLE_128B((uint32_t)((m0 + lrow) * 128 + ks * 32 + lch * 16));
        uint32_t ah[4], al[4];
        ldsm_x4(ah, sb + AQH + aoff);
        ldsm_x4(al, sb + AQL + aoff);
        #pragma unroll
        for (int n6 = 0; n6 < 12; n6++) {
            uint32_t boff = SMEM_SWIZZLE_128B((uint32_t)((n6 * 16 + lrow) * 128 + ks * 32 + lch * 16));
            uint32_t bk4[4];
            ldsm_x4(bk4, sb + AK + boff);
            mma_fp16(s[2*n6],   ah, bk4[0], bk4[2]);
            mma_fp16(s[2*n6+1], ah, bk4[1], bk4[3]);
            mma_fp16(s[2*n6],   al, bk4[0], bk4[2]);
            mma_fp16(s[2*n6+1], al, bk4[1], bk4[3]);
        }
    }

    const int rA = m0 + (lane >> 2);
    const int rB = rA + 8;
    const int jb = 2 * (lane & 3);
    const int gof = c * 64 - 64;
    float mA = -INFINITY, mB = -INFINITY;
    #pragma unroll
    for (int nt = 0; nt < 24; nt++) {
        int j0 = nt * 8 + jb, j1 = j0 + 1;
        int g0 = gof + j0, g1 = gof + j1;
        bool in0 = (g0 >= 0) && (g0 < SS);
        bool in1 = (g1 >= 0) && (g1 < SS);
        if (!((j0 >= rA) && (j0 <= rA + 128) && in0)) s[nt][0] = -INFINITY;
        if (!((j1 >= rA) && (j1 <= rA + 128) && in1)) s[nt][1] = -INFINITY;
        if (!((j0 >= rB) && (j0 <= rB + 128) && in0)) s[nt][2] = -INFINITY;
        if (!((j1 >= rB) && (j1 <= rB + 128) && in1)) s[nt][3] = -INFINITY;
        mA = fmaxf(mA, fmaxf(s[nt][0], s[nt][1]));
        mB = fmaxf(mB, fmaxf(s[nt][2], s[nt][3]));
    }
    mA = fmaxf(mA, __shfl_xor_sync(0xffffffffu, mA, 1));
    mA = fmaxf(mA, __shfl_xor_sync(0xffffffffu, mA, 2));
    mB = fmaxf(mB, __shfl_xor_sync(0xffffffffu, mB, 1));
    mB = fmaxf(mB, __shfl_xor_sync(0xffffffffu, mB, 2));
    float sA = 0.f, sB = 0.f;
    #pragma unroll
    for (int nt = 0; nt < 24; nt++) {
        s[nt][0] = __expf(s[nt][0] - mA);
        s[nt][1] = __expf(s[nt][1] - mA);
        s[nt][2] = __expf(s[nt][2] - mB);
        s[nt][3] = __expf(s[nt][3] - mB);
        sA += s[nt][0] + s[nt][1];
        sB += s[nt][2] + s[nt][3];
    }
    sA += __shfl_xor_sync(0xffffffffu, sA, 1);
    sA += __shfl_xor_sync(0xffffffffu, sA, 2);
    sB += __shfl_xor_sync(0xffffffffu, sB, 1);
    sB += __shfl_xor_sync(0xffffffffu, sB, 2);
    const float invA = 1.0f / sA, invB = 1.0f / sB;

    float o[8][4];
    #pragma unroll
    for (int nt = 0; nt < 8; nt++)
        #pragma unroll
        for (int u = 0; u < 4; u++) o[nt][u] = 0.f;

    #pragma unroll
    for (int t = 0; t < 12; t++) {
        uint32_t ph[4], pl[4];
        ph[0] = pack_hi16(s[2*t][0],   s[2*t][1]);
        ph[1] = pack_hi16(s[2*t][2],   s[2*t][3]);
        ph[2] = pack_hi16(s[2*t+1][0], s[2*t+1][1]);
        ph[3] = pack_hi16(s[2*t+1][2], s[2*t+1][3]);
        pl[0] = pack_lo16(s[2*t][0],   s[2*t][1]);
        pl[1] = pack_lo16(s[2*t][2],   s[2*t][3]);
        pl[2] = pack_lo16(s[2*t+1][0], s[2*t+1][1]);
        pl[3] = pack_lo16(s[2*t+1][2], s[2*t+1][3]);
        #pragma unroll
        for (int nn = 0; nn < 4; nn++) {
            uint32_t voff = SMEM_SWIZZLE_128B(
                (uint32_t)((t * 16 + (lane & 15)) * 128 + (nn * 16 + (lane >> 4) * 8) * 2));
            uint32_t vv[4];
            ldsm_x4_trans(vv, sb + AV + voff);
            mma_fp16(o[2*nn],   ph, vv[0], vv[1]);
            mma_fp16(o[2*nn+1], ph, vv[2], vv[3]);
            mma_fp16(o[2*nn],   pl, vv[0], vv[1]);
            mma_fp16(o[2*nn+1], pl, vv[2], vv[3]);
        }
    }

    const size_t rowg = (size_t)b * SS + c * 64;
    #pragma unroll
    for (int nt = 0; nt < 8; nt++) {
        int col = h * HD + nt * 8 + jb;
        float2 v0 = make_float2(o[nt][0] * invA, o[nt][1] * invA);
        float2 v1 = make_float2(o[nt][2] * invB, o[nt][3] * invB);
        *reinterpret_cast<float2*>(&out[(rowg + rA) * DM + col]) = v0;
        *reinterpret_cast<float2*>(&out[(rowg + rB) * DM + col]) = v1;
    }
}

// ============ LN1: x1 = LN(attn + x), emit ONLY fp16 ============
__global__ void __launch_bounds__(256)
add_ln_kernel(const float* __restrict__ a,
              const float* __restrict__ r,
              const float* __restrict__ g,
              const float* __restrict__ beta,
              __half* __restrict__ outH) {
    const int warp = threadIdx.x >> 5, lane = threadIdx.x & 31;
    const int row = blockIdx.x * 8 + warp;
    const float4* pa = reinterpret_cast<const float4*>(a + (size_t)row * DM);
    const float4* pr = reinterpret_cast<const float4*>(r + (size_t)row * DM);
    const float4* pg = reinterpret_cast<const float4*>(g);
    const float4* pb = reinterpret_cast<const float4*>(beta);

    float4 v[6];
    float sum = 0.f;
    #pragma unroll
    for (int ch = 0; ch < 6; ch++) {
        float4 va = pa[lane + 32 * ch];
        float4 vr = pr[lane + 32 * ch];
        v[ch] = make_float4(va.x + vr.x, va.y + vr.y, va.z + vr.z, va.w + vr.w);
        sum += v[ch].x + v[ch].y + v[ch].z + v[ch].w;
    }
    #pragma unroll
    for (int o = 16; o > 0; o >>= 1) sum += __shfl_xor_sync(0xffffffffu, sum, o);
    float mu = sum * (1.0f / DM);

    float var = 0.f;
    #pragma unroll
    for (int ch = 0; ch < 6; ch++) {
        float dx = v[ch].x - mu, dy = v[ch].y - mu, dz = v[ch].z - mu, dw = v[ch].w - mu;
        var += dx * dx + dy * dy + dz * dz + dw * dw;
    }
    #pragma unroll
    for (int o = 16; o > 0; o >>= 1) var += __shfl_xor_sync(0xffffffffu, var, o);
    float rstd = rsqrtf(var * (1.0f / DM) + 1e-5f);

    #pragma unroll
    for (int ch = 0; ch < 6; ch++) {
        float4 gg = pg[lane + 32 * ch];
        float4 bb = pb[lane + 32 * ch];
        float4 y;
        y.x = (v[ch].x - mu) * rstd * gg.x + bb.x;
        y.y = (v[ch].y - mu) * rstd * gg.y + bb.y;
        y.z = (v[ch].z - mu) * rstd * gg.z + bb.z;
        y.w = (v[ch].w - mu) * rstd * gg.w + bb.w;
        size_t o4 = (size_t)row * DM + (lane + 32 * ch) * 4;
        reinterpret_cast<__half2*>(outH + o4)[0] = __half2(__float2half(y.x), __float2half(y.y));
        reinterpret_cast<__half2*>(outH + o4)[1] = __half2(__float2half(y.z), __float2half(y.w));
    }
}

// ===== LN2: out = LN(p0+p1+p2 + bias2 + x1h), fp16 partials & residual =====
__global__ void __launch_bounds__(256)
add_ln3_kernel(const __half* __restrict__ p,
               const __half* __restrict__ rH,
               const float* __restrict__ bias2,
               const float* __restrict__ g,
               const float* __restrict__ beta,
               float* __restrict__ out) {
    const int warp = threadIdx.x >> 5, lane = threadIdx.x & 31;
    const int row = blockIdx.x * 8 + warp;
    const __half2* p0 = reinterpret_cast<const __half2*>(p + (size_t)row * DM);
    const __half2* p1 = reinterpret_cast<const __half2*>(p + (size_t)row * DM + MD);
    const __half2* p2 = reinterpret_cast<const __half2*>(p + (size_t)row * DM + 2 * (size_t)MD);
    const __half2* pr = reinterpret_cast<const __half2*>(rH + (size_t)row * DM);
    const float4* pb2 = reinterpret_cast<const float4*>(bias2);
    const float4* pg = reinterpret_cast<const float4*>(g);
    const float4* pb = reinterpret_cast<const float4*>(beta);

    float4 v[6];
    float sum = 0.f;
    #pragma unroll
    for (int ch = 0; ch < 6; ch++) {
        int e2 = (lane + 32 * ch) * 2;     // half2 index
        float2 a0 = __half22float2(p0[e2]),     a0b = __half22float2(p0[e2 + 1]);
        float2 a1 = __half22float2(p1[e2]),     a1b = __half22float2(p1[e2 + 1]);
        float2 a2 = __half22float2(p2[e2]),     a2b = __half22float2(p2[e2 + 1]);
        float2 rr = __half22float2(pr[e2]),     rrb = __half22float2(pr[e2 + 1]);
        float4 b2 = pb2[lane + 32 * ch];
        v[ch] = make_float4(a0.x + a1.x + a2.x + b2.x + rr.x,
                            a0.y + a1.y + a2.y + b2.y + rr.y,
                            a0b.x + a1b.x + a2b.x + b2.z + rrb.x,
                            a0b.y + a1b.y + a2b.y + b2.w + rrb.y);
        sum += v[ch].x + v[ch].y + v[ch].z + v[ch].w;
    }
    #pragma unroll
    for (int o = 16; o > 0; o >>= 1) sum += __shfl_xor_sync(0xffffffffu, sum, o);
    float mu = sum * (1.0f / DM);

    float var = 0.f;
    #pragma unroll
    for (int ch = 0; ch < 6; ch++) {
        float dx = v[ch].x - mu, dy = v[ch].y - mu, dz = v[ch].z - mu, dw = v[ch].w - mu;
        var += dx * dx + dy * dy + dz * dz + dw * dw;
    }
    #pragma unroll
    for (int o = 16; o > 0; o >>= 1) var += __shfl_xor_sync(0xffffffffu, var, o);
    float rstd = rsqrtf(var * (1.0f / DM) + 1e-5f);

    float4* po = reinterpret_cast<float4*>(out + (size_t)row * DM);
    #pragma unroll
    for (int ch = 0; ch < 6; ch++) {
        float4 gg = pg[lane + 32 * ch];
        float4 bb = pb[lane + 32 * ch];
        float4 y;
        y.x = (v[ch].x - mu) * rstd * gg.x + bb.x;
        y.y = (v[ch].y - mu) * rstd * gg.y + bb.y;
        y.z = (v[ch].z - mu) * rstd * gg.z + bb.z;
        y.w = (v[ch].w - mu) * rstd * gg.w + bb.w;
        po[lane + 32 * ch] = y;
    }
}

// ================= launch =================
extern "C" void kernel_launch(void* const* d_in, const int* in_sizes, int n_in,
                              void* d_out, int out_size) {
    const float* x     = (const float*)d_in[0];
    const float* Wq    = (const float*)d_in[1];
    const float* bq    = (const float*)d_in[2];
    const float* Wk    = (const float*)d_in[3];
    const float* bk    = (const float*)d_in[4];
    const float* Wv    = (const float*)d_in[5];
    const float* bv    = (const float*)d_in[6];
    const float* ln1_g = (const float*)d_in[7];
    const float* ln1_b = (const float*)d_in[8];
    const float* W1    = (const float*)d_in[9];
    const float* b1    = (const float*)d_in[10];
    const float* W2    = (const float*)d_in[11];
    const float* b2    = (const float*)d_in[12];
    const float* ln2_g = (const float*)d_in[13];
    const float* ln2_b = (const float*)d_in[14];
    float* out = (float*)d_out;

    float *attn, *bqkv;
    __half *qh, *ql, *kv, *xh, *xl, *x1h, *hid, *ffp, *wqkv, *w1, *w2;
    cudaGetSymbolAddress((void**)&attn, g_attn);
    cudaGetSymbolAddress((void**)&bqkv, g_bqkv);
    cudaGetSymbolAddress((void**)&qh, g_qh);     cudaGetSymbolAddress((void**)&ql, g_ql);
    cudaGetSymbolAddress((void**)&kv, g_kv);
    cudaGetSymbolAddress((void**)&xh, g_xh);     cudaGetSymbolAddress((void**)&xl, g_xl);
    cudaGetSymbolAddress((void**)&x1h, g_x1h);
    cudaGetSymbolAddress((void**)&hid, g_hid);
    cudaGetSymbolAddress((void**)&ffp, g_ffp);
    cudaGetSymbolAddress((void**)&wqkv, g_wqkv);
    cudaGetSymbolAddress((void**)&w1, g_w1);     cudaGetSymbolAddress((void**)&w2, g_w2);

    const int SMEM_Q = 2 * 3 * 16384;   // 2-term, 2 stages = 96KB
    const int SMEM_F = 3 * 2 * 16384;   // 1-term, 3 stages = 96KB
    cudaFuncSetAttribute((const void*)tc_gemm<2,2>, cudaFuncAttributeMaxDynamicSharedMemorySize, SMEM_Q);
    cudaFuncSetAttribute((const void*)tc_gemm<1,3>, cudaFuncAttributeMaxDynamicSharedMemorySize, SMEM_F);
    cudaFuncSetAttribute(attn_kernel, cudaFuncAttributeMaxDynamicSharedMemorySize, ATTN_SMEM);

    // ---- merged prep: weights + bias + x split (one launch) ----
    prep_all<<<12489, 256>>>(x, Wq, Wk, Wv, W1, W2, bq, bk, bv,
                             wqkv, w1, w2, bqkv, xh, xl);

    // ---- fused QKV projection (2-term): q fp16 hi/lo (scaled), k/v fp16 ----
    {
        dim3 grid(QKVN / 128, MROWS / 128);
        tc_gemm<2,2><<<grid, 256, SMEM_Q>>>(xh, xl, wqkv, bqkv, (float*)kv,
                                            qh, ql, MROWS, QKVN, DM, 2);
    }

    // ---- attention ----
    {
        dim3 grid(NC, NH, BB);
        attn_kernel<<<grid, 128, ATTN_SMEM>>>(qh, ql, kv, attn);
    }

    // ---- x1 = LN(attn + x), fp16 only ----
    add_ln_kernel<<<MROWS / 8, 256>>>(attn, x, ln1_g, ln1_b, x1h);

    // ---- FFN (1-term) ----
    {
        dim3 grid1(FF / 128, MROWS / 128);
        tc_gemm<1,3><<<grid1, 256, SMEM_F>>>(x1h, nullptr, w1, b1, nullptr,
                                             hid, nullptr, MROWS, FF, DM, 1);
        dim3 grid2(DM / 128, MROWS / 128, 3);   // split-K = 3, fp16 partials
        tc_gemm<1,3><<<grid2, 256, SMEM_F>>>(hid, nullptr, w2, nullptr, nullptr,
                                             ffp, nullptr, MROWS, DM, FF, 3);
    }

    // ---- out = LN(p0+p1+p2 + b2 + x1) ----
    add_ln3_kernel<<<MROWS / 8, 256>>>(ffp, x1h, b2, ln2_g, ln2_b, out);
}

// round 15
// speedup vs baseline: 2.6906x; 1.1916x over previous
#include <cuda_runtime.h>
#include <cuda_bf16.h>
#include <cuda_fp16.h>
#include <math.h>
#include <cstdint>

#define BB 2
#define SS 4096
#define DM 768
#define NH 12
#define FF 3072
#define WIN 64
#define HD 64
#define NC (SS / WIN)
#define MROWS (BB * SS)    // 8192
#define QKVN (3 * DM)      // 2304
#define KVW (2 * DM)       // 1536
#define MD (MROWS * DM)

// ================= helpers =================
__device__ __forceinline__ uint32_t smem_to_u32(const void* p) {
    uint32_t a;
    asm("{ .reg .u64 t; cvta.to.shared.u64 t, %1; cvt.u32.u64 %0, t; }" : "=r"(a) : "l"(p));
    return a;
}
#define SMEM_SWIZZLE_128B(o) ((o) ^ (((o) >> 3) & 0x70))

__device__ __forceinline__ void ldsm_x4(uint32_t r[4], uint32_t addr) {
    asm volatile("ldmatrix.sync.aligned.m8n8.x4.shared.b16 {%0,%1,%2,%3}, [%4];"
        : "=r"(r[0]), "=r"(r[1]), "=r"(r[2]), "=r"(r[3]) : "r"(addr));
}
__device__ __forceinline__ void ldsm_x4_trans(uint32_t r[4], uint32_t addr) {
    asm volatile("ldmatrix.sync.aligned.m8n8.x4.trans.shared.b16 {%0,%1,%2,%3}, [%4];"
        : "=r"(r[0]), "=r"(r[1]), "=r"(r[2]), "=r"(r[3]) : "r"(addr));
}
__device__ __forceinline__ void mma_fp16(float c[4], const uint32_t a[4],
                                         uint32_t b0, uint32_t b1) {
    asm volatile("mma.sync.aligned.m16n8k16.row.col.f32.f16.f16.f32 "
        "{%0,%1,%2,%3}, {%4,%5,%6,%7}, {%8,%9}, {%0,%1,%2,%3};"
        : "+f"(c[0]), "+f"(c[1]), "+f"(c[2]), "+f"(c[3])
        : "r"(a[0]), "r"(a[1]), "r"(a[2]), "r"(a[3]), "r"(b0), "r"(b1));
}
__device__ __forceinline__ uint32_t pack_hi16(float x, float y) {
    __half2 t(__float2half(x), __float2half(y));
    return *reinterpret_cast<uint32_t*>(&t);
}
__device__ __forceinline__ uint32_t pack_lo16(float x, float y) {
    __half hx = __float2half(x), hy = __float2half(y);
    __half2 t(__float2half(x - __half2float(hx)),
              __float2half(y - __half2float(hy)));
    return *reinterpret_cast<uint32_t*>(&t);
}
__device__ __forceinline__ float gelu_tanh(float x) {
    const float c = 0.7978845608028654f;
    float x3 = x * x * x;
    return 0.5f * x * (1.0f + tanhf(c * (x + 0.044715f * x3)));
}

// ================= scratch =================
__device__ float g_attn[MD];
__device__ float g_bqkv[QKVN];
__device__ __half g_q[MD];                    // q pre-scaled, single fp16
__device__ __half g_kv[MROWS * KVW];
__device__ __half g_xh[MD];                   // x single fp16
__device__ __half g_x1h[MD];
__device__ __half g_hid[MROWS * FF];
__device__ __half g_ffp[3 * MD];
__device__ __half g_wqkv[QKVN * DM];
__device__ __half g_w1[FF * DM];
__device__ __half g_w2[DM * FF];

// ========== merged prep: weight transpose + bias pack + x convert ==========
// blocks [0,6336): weight tiles; [6336,6345): bias; [6345,12489): x convert.
__global__ void prep_all(const float* __restrict__ x,
                         const float* __restrict__ Wq, const float* __restrict__ Wk,
                         const float* __restrict__ Wv, const float* __restrict__ W1,
                         const float* __restrict__ W2,
                         const float* __restrict__ bq, const float* __restrict__ bk,
                         const float* __restrict__ bv,
                         __half* __restrict__ wqkv,
                         __half* __restrict__ w1,
                         __half* __restrict__ w2,
                         float* __restrict__ bqkv,
                         __half* __restrict__ xh) {
    int id = blockIdx.x;
    if (id >= 6345) {
        int i = (id - 6345) * 256 + threadIdx.x;   // float4 index
        float4 v = reinterpret_cast<const float4*>(x)[i];
        reinterpret_cast<__half2*>(xh)[i*2+0] = __half2(__float2half(v.x), __float2half(v.y));
        reinterpret_cast<__half2*>(xh)[i*2+1] = __half2(__float2half(v.z), __float2half(v.w));
        return;
    }
    if (id >= 6336) {
        int i = (id - 6336) * 256 + threadIdx.x;
        if (i < QKVN)
            bqkv[i] = (i < DM) ? bq[i] : (i < 2 * DM) ? bk[i - DM] : bv[i - 2 * DM];
        return;
    }
    const float* W; __half* T; int K, N, tix;
    if (id < 576)       { W = Wq; T = wqkv;               K = DM; N = DM; tix = id; }
    else if (id < 1152) { W = Wk; T = wqkv + DM * DM;     K = DM; N = DM; tix = id - 576; }
    else if (id < 1728) { W = Wv; T = wqkv + 2 * DM * DM; K = DM; N = DM; tix = id - 1152; }
    else if (id < 4032) { W = W1; T = w1;                 K = DM; N = FF; tix = id - 1728; }
    else                { W = W2; T = w2;                 K = FF; N = DM; tix = id - 4032; }
    int nt = N / 32;
    int n0 = (tix % nt) * 32, k0 = (tix / nt) * 32;
    __shared__ float t[32][33];
    int tx = threadIdx.x & 31, ty = threadIdx.x >> 5;
    #pragma unroll
    for (int i = 0; i < 4; i++)
        t[ty + i*8][tx] = W[(size_t)(k0 + ty + i*8) * N + n0 + tx];
    __syncthreads();
    #pragma unroll
    for (int i = 0; i < 4; i++) {
        T[(size_t)(n0 + ty + i*8) * K + k0 + tx] = __float2half(t[tx][ty + i*8]);
    }
}

// ========== HMMA GEMM (templated TERMS/NSTAGES; 96KB smem, 2 CTAs/SM) ==========
// mode 0: fp32+bias. mode 1: gelu + single fp16 (outAux). mode 2: QKV
// (q*0.125 single fp16 -> outAux, k/v fp16 -> outF-as-half).
// mode 3: split-K fp16 partials (outAux + z*M*N).
template<int TERMS, int NSTAGES>
__global__ void __launch_bounds__(256, 2)
tc_gemm(const __half* __restrict__ Ah, const __half* __restrict__ Al,
        const __half* __restrict__ B,
        const float* __restrict__ bias,
        float* __restrict__ outF,
        void* __restrict__ outAux,
        int M, int N, int K, int mode) {
    constexpr uint32_t STAGE = (TERMS + 1) * 16384u;
    extern __shared__ char smem[];
    const uint32_t tiles = smem_to_u32(smem);
    const int tid = threadIdx.x;
    const int wid = tid >> 5;
    const int lane = tid & 31;
    const int warpM = wid >> 1;
    const int warpN = wid & 1;
    const int bm = blockIdx.y * 128;
    const int bn = blockIdx.x * 128;
    const int kb0 = (mode == 3) ? blockIdx.z * 16 : 0;
    const int NB  = (mode == 3) ? 16 : (K >> 6);
    __half* aux = (__half*)outAux;
    if (mode == 3) aux += (size_t)blockIdx.z * M * N;

    const __half* srcs[2] = {Ah, Al};

    auto stage = [&](int kb, int s) {
        #pragma unroll
        for (int t = 0; t < TERMS + 1; t++) {
            const __half* src = (t < TERMS) ? srcs[t] : B;
            const int rbase = (t < TERMS) ? bm : bn;
            const uint32_t sb = tiles + (uint32_t)s * STAGE + (uint32_t)t * 16384u;
            #pragma unroll
            for (int i = 0; i < 4; i++) {
                int chunk = tid + i * 256;
                int row = chunk >> 3;
                int c16 = chunk & 7;
                uint32_t off = (uint32_t)(row * 128 + c16 * 16);
                uint32_t dst = sb + SMEM_SWIZZLE_128B(off);
                const void* g = src + (size_t)(rbase + row) * K + kb * 64 + c16 * 8;
                asm volatile("cp.async.cg.shared.global [%0], [%1], 16;" :: "r"(dst), "l"(g));
            }
        }
        asm volatile("cp.async.commit_group;" ::: "memory");
    };

    float c[2][8][4] = {};

    stage(kb0, 0);
    if (NSTAGES >= 3 && NB > 1) stage(kb0 + 1, 1);

    const int lrow = lane & 15;
    const int lchunk = lane >> 4;

    for (int kb = 0; kb < NB; kb++) {
        const int s = kb % NSTAGES;
        if (NSTAGES >= 3) {
            if (kb + 1 < NB) asm volatile("cp.async.wait_group 1;" ::: "memory");
            else             asm volatile("cp.async.wait_group 0;" ::: "memory");
            __syncthreads();
            if (kb + 2 < NB) stage(kb0 + kb + 2, (kb + 2) % NSTAGES);
        } else {
            asm volatile("cp.async.wait_group 0;" ::: "memory");
            __syncthreads();
            if (kb + 1 < NB) stage(kb0 + kb + 1, (kb + 1) % NSTAGES);
        }

        const uint32_t base_s = tiles + (uint32_t)s * STAGE;
        const uint32_t baseB = base_s + (uint32_t)TERMS * 16384u;
        #pragma unroll
        for (int ks = 0; ks < 4; ks++) {
            uint32_t ah[2][4], al2[2][4];
            #pragma unroll
            for (int mt = 0; mt < 2; mt++) {
                uint32_t off = (uint32_t)((warpM * 32 + mt * 16 + lrow) * 128 + ks * 32 + lchunk * 16);
                uint32_t sw = SMEM_SWIZZLE_128B(off);
                ldsm_x4(ah[mt], base_s + sw);
                if (TERMS == 2) ldsm_x4(al2[mt], base_s + 16384u + sw);
            }
            uint32_t bb[2][4];
            {
                uint32_t off0 = (uint32_t)((warpN * 64 + lrow) * 128 + ks * 32 + lchunk * 16);
                ldsm_x4(bb[0], baseB + SMEM_SWIZZLE_128B(off0));
            }
            #pragma unroll
            for (int np = 0; np < 4; np++) {
                const int cur = np & 1;
                if (np < 3) {
                    uint32_t off = (uint32_t)((warpN * 64 + (np + 1) * 16 + lrow) * 128 + ks * 32 + lchunk * 16);
                    ldsm_x4(bb[cur ^ 1], baseB + SMEM_SWIZZLE_128B(off));
                }
                #pragma unroll
                for (int mt = 0; mt < 2; mt++) {
                    mma_fp16(c[mt][2*np],   ah[mt], bb[cur][0], bb[cur][2]);
                    mma_fp16(c[mt][2*np+1], ah[mt], bb[cur][1], bb[cur][3]);
                    if (TERMS == 2) {
                        mma_fp16(c[mt][2*np],   al2[mt], bb[cur][0], bb[cur][2]);
                        mma_fp16(c[mt][2*np+1], al2[mt], bb[cur][1], bb[cur][3]);
                    }
                }
            }
        }
        if (NSTAGES == 2) __syncthreads();
    }
    __syncthreads();

    float* sD = reinterpret_cast<float*>(smem);   // 128 x 129
    #pragma unroll
    for (int mt = 0; mt < 2; mt++) {
        #pragma unroll
        for (int nt = 0; nt < 8; nt++) {
            int r0 = warpM * 32 + mt * 16 + (lane >> 2);
            int col = warpN * 64 + nt * 8 + (lane & 3) * 2;
            sD[r0 * 129 + col]           = c[mt][nt][0];
            sD[r0 * 129 + col + 1]       = c[mt][nt][1];
            sD[(r0 + 8) * 129 + col]     = c[mt][nt][2];
            sD[(r0 + 8) * 129 + col + 1] = c[mt][nt][3];
        }
    }
    __syncthreads();

    for (int idx = tid; idx < 128 * 128; idx += 256) {
        int r = idx >> 7, cc = idx & 127;
        float v = sD[r * 129 + cc];
        size_t row = (size_t)(bm + r);
        int gc = bn + cc;
        if (mode == 3) {
            aux[row * N + gc] = __float2half(v);
            continue;
        }
        v += bias[gc];
        if (mode == 0) {
            outF[row * N + gc] = v;
        } else if (mode == 1) {
            v = gelu_tanh(v);
            aux[row * N + gc] = __float2half(v);
        } else {
            if (gc < DM) {
                aux[row * DM + gc] = __float2half(v * 0.125f);
            } else {
                ((__half*)outF)[row * KVW + (gc - DM)] = __float2half(v);
            }
        }
    }
}

// ================= HMMA sliding-window attention =================
// q single fp16 (pre-scaled), k/v single fp16; QK 1-term, PV 2-term (P hi/lo).
#define AQ  0
#define AK  8192
#define AV  32768
#define ATTN_SMEM 57344
__global__ void __launch_bounds__(128, 2)
attn_kernel(const __half* __restrict__ q,
            const __half* __restrict__ kv,
            float* __restrict__ out) {
    extern __shared__ char smem[];
    const uint32_t sb = smem_to_u32(smem);
    const int c = blockIdx.x, h = blockIdx.y, b = blockIdx.z;
    const int tid = threadIdx.x, warp = tid >> 5, lane = tid & 31;

    // ---- q: straight cp.async copies ----
    for (int idx = tid; idx < 64 * 8; idx += 128) {
        int r = idx >> 3, ch = idx & 7;
        uint32_t off = SMEM_SWIZZLE_128B((uint32_t)(r * 128 + ch * 16));
        size_t gsrc = ((size_t)b * SS + c * 64 + r) * DM + h * HD + ch * 8;
        asm volatile("cp.async.cg.shared.global [%0], [%1], 16;"
                     :: "r"(sb + AQ + off), "l"(q + gsrc));
    }
    // ---- k/v window: cp.async with zero-fill for OOB rows ----
    for (int idx = tid; idx < 192 * 8; idx += 128) {
        int j = idx >> 3, ch = idx & 7;
        int g = c * 64 - 64 + j;
        int in = (g >= 0 && g < SS);
        size_t rb = ((size_t)b * SS + (in ? g : 0)) * KVW + h * HD + ch * 8;
        uint32_t off = SMEM_SWIZZLE_128B((uint32_t)(j * 128 + ch * 16));
        int sz = in ? 16 : 0;
        asm volatile("cp.async.cg.shared.global [%0], [%1], 16, %2;"
                     :: "r"(sb + AK + off), "l"(kv + rb), "r"(sz));
        asm volatile("cp.async.cg.shared.global [%0], [%1], 16, %2;"
                     :: "r"(sb + AV + off), "l"(kv + rb + DM), "r"(sz));
    }
    asm volatile("cp.async.commit_group;" ::: "memory");
    asm volatile("cp.async.wait_group 0;" ::: "memory");
    __syncthreads();

    const int m0 = warp * 16;
    const int lrow = lane & 15;
    const int lch = lane >> 4;

    // ---- QK^T: 16 x 192 per warp, 1-term ----
    float s[24][4];
    #pragma unroll
    for (int nt = 0; nt < 24; nt++)
        #pragma unroll
        for (int u = 0; u < 4; u++) s[nt][u] = 0.f;

    #pragma unroll
    for (int ks = 0; ks < 4; ks++) {
        uint32_t aoff = SMEM_SWIZZLE_128B((uint32_t)((m0 + lrow) * 128 + ks * 32 + lch * 16));
        uint32_t ah[4];
        ldsm_x4(ah, sb + AQ + aoff);
        #pragma unroll
        for (int n6 = 0; n6 < 12; n6++) {
            uint32_t boff = SMEM_SWIZZLE_128B((uint32_t)((n6 * 16 + lrow) * 128 + ks * 32 + lch * 16));
            uint32_t bk4[4];
            ldsm_x4(bk4, sb + AK + boff);
            mma_fp16(s[2*n6],   ah, bk4[0], bk4[2]);
            mma_fp16(s[2*n6+1], ah, bk4[1], bk4[3]);
        }
    }

    const int rA = m0 + (lane >> 2);
    const int rB = rA + 8;
    const int jb = 2 * (lane & 3);
    const int gof = c * 64 - 64;
    float mA = -INFINITY, mB = -INFINITY;
    #pragma unroll
    for (int nt = 0; nt < 24; nt++) {
        int j0 = nt * 8 + jb, j1 = j0 + 1;
        int g0 = gof + j0, g1 = gof + j1;
        bool in0 = (g0 >= 0) && (g0 < SS);
        bool in1 = (g1 >= 0) && (g1 < SS);
        if (!((j0 >= rA) && (j0 <= rA + 128) && in0)) s[nt][0] = -INFINITY;
        if (!((j1 >= rA) && (j1 <= rA + 128) && in1)) s[nt][1] = -INFINITY;
        if (!((j0 >= rB) && (j0 <= rB + 128) && in0)) s[nt][2] = -INFINITY;
        if (!((j1 >= rB) && (j1 <= rB + 128) && in1)) s[nt][3] = -INFINITY;
        mA = fmaxf(mA, fmaxf(s[nt][0], s[nt][1]));
        mB = fmaxf(mB, fmaxf(s[nt][2], s[nt][3]));
    }
    mA = fmaxf(mA, __shfl_xor_sync(0xffffffffu, mA, 1));
    mA = fmaxf(mA, __shfl_xor_sync(0xffffffffu, mA, 2));
    mB = fmaxf(mB, __shfl_xor_sync(0xffffffffu, mB, 1));
    mB = fmaxf(mB, __shfl_xor_sync(0xffffffffu, mB, 2));
    float sA = 0.f, sB = 0.f;
    #pragma unroll
    for (int nt = 0; nt < 24; nt++) {
        s[nt][0] = __expf(s[nt][0] - mA);
        s[nt][1] = __expf(s[nt][1] - mA);
        s[nt][2] = __expf(s[nt][2] - mB);
        s[nt][3] = __expf(s[nt][3] - mB);
        sA += s[nt][0] + s[nt][1];
        sB += s[nt][2] + s[nt][3];
    }
    sA += __shfl_xor_sync(0xffffffffu, sA, 1);
    sA += __shfl_xor_sync(0xffffffffu, sA, 2);
    sB += __shfl_xor_sync(0xffffffffu, sB, 1);
    sB += __shfl_xor_sync(0xffffffffu, sB, 2);
    const float invA = 1.0f / sA, invB = 1.0f / sB;

    // ---- PV: P fp16 hi/lo x V single fp16 ----
    float o[8][4];
    #pragma unroll
    for (int nt = 0; nt < 8; nt++)
        #pragma unroll
        for (int u = 0; u < 4; u++) o[nt][u] = 0.f;

    #pragma unroll
    for (int t = 0; t < 12; t++) {
        uint32_t ph[4], pl[4];
        ph[0] = pack_hi16(s[2*t][0],   s[2*t][1]);
        ph[1] = pack_hi16(s[2*t][2],   s[2*t][3]);
        ph[2] = pack_hi16(s[2*t+1][0], s[2*t+1][1]);
        ph[3] = pack_hi16(s[2*t+1][2], s[2*t+1][3]);
        pl[0] = pack_lo16(s[2*t][0],   s[2*t][1]);
        pl[1] = pack_lo16(s[2*t][2],   s[2*t][3]);
        pl[2] = pack_lo16(s[2*t+1][0], s[2*t+1][1]);
        pl[3] = pack_lo16(s[2*t+1][2], s[2*t+1][3]);
        #pragma unroll
        for (int nn = 0; nn < 4; nn++) {
            uint32_t voff = SMEM_SWIZZLE_128B(
                (uint32_t)((t * 16 + (lane & 15)) * 128 + (nn * 16 + (lane >> 4) * 8) * 2));
            uint32_t vv[4];
            ldsm_x4_trans(vv, sb + AV + voff);
            mma_fp16(o[2*nn],   ph, vv[0], vv[1]);
            mma_fp16(o[2*nn+1], ph, vv[2], vv[3]);
            mma_fp16(o[2*nn],   pl, vv[0], vv[1]);
            mma_fp16(o[2*nn+1], pl, vv[2], vv[3]);
        }
    }

    const size_t rowg = (size_t)b * SS + c * 64;
    #pragma unroll
    for (int nt = 0; nt < 8; nt++) {
        int col = h * HD + nt * 8 + jb;
        float2 v0 = make_float2(o[nt][0] * invA, o[nt][1] * invA);
        float2 v1 = make_float2(o[nt][2] * invB, o[nt][3] * invB);
        *reinterpret_cast<float2*>(&out[(rowg + rA) * DM + col]) = v0;
        *reinterpret_cast<float2*>(&out[(rowg + rB) * DM + col]) = v1;
    }
}

// ============ LN1: x1 = LN(attn + x), emit ONLY fp16 ============
__global__ void __launch_bounds__(256)
add_ln_kernel(const float* __restrict__ a,
              const float* __restrict__ r,
              const float* __restrict__ g,
              const float* __restrict__ beta,
              __half* __restrict__ outH) {
    const int warp = threadIdx.x >> 5, lane = threadIdx.x & 31;
    const int row = blockIdx.x * 8 + warp;
    const float4* pa = reinterpret_cast<const float4*>(a + (size_t)row * DM);
    const float4* pr = reinterpret_cast<const float4*>(r + (size_t)row * DM);
    const float4* pg = reinterpret_cast<const float4*>(g);
    const float4* pb = reinterpret_cast<const float4*>(beta);

    float4 v[6];
    float sum = 0.f;
    #pragma unroll
    for (int ch = 0; ch < 6; ch++) {
        float4 va = pa[lane + 32 * ch];
        float4 vr = pr[lane + 32 * ch];
        v[ch] = make_float4(va.x + vr.x, va.y + vr.y, va.z + vr.z, va.w + vr.w);
        sum += v[ch].x + v[ch].y + v[ch].z + v[ch].w;
    }
    #pragma unroll
    for (int o = 16; o > 0; o >>= 1) sum += __shfl_xor_sync(0xffffffffu, sum, o);
    float mu = sum * (1.0f / DM);

    float var = 0.f;
    #pragma unroll
    for (int ch = 0; ch < 6; ch++) {
        float dx = v[ch].x - mu, dy = v[ch].y - mu, dz = v[ch].z - mu, dw = v[ch].w - mu;
        var += dx * dx + dy * dy + dz * dz + dw * dw;
    }
    #pragma unroll
    for (int o = 16; o > 0; o >>= 1) var += __shfl_xor_sync(0xffffffffu, var, o);
    float rstd = rsqrtf(var * (1.0f / DM) + 1e-5f);

    #pragma unroll
    for (int ch = 0; ch < 6; ch++) {
        float4 gg = pg[lane + 32 * ch];
        float4 bb = pb[lane + 32 * ch];
        float4 y;
        y.x = (v[ch].x - mu) * rstd * gg.x + bb.x;
        y.y = (v[ch].y - mu) * rstd * gg.y + bb.y;
        y.z = (v[ch].z - mu) * rstd * gg.z + bb.z;
        y.w = (v[ch].w - mu) * rstd * gg.w + bb.w;
        size_t o4 = (size_t)row * DM + (lane + 32 * ch) * 4;
        reinterpret_cast<__half2*>(outH + o4)[0] = __half2(__float2half(y.x), __float2half(y.y));
        reinterpret_cast<__half2*>(outH + o4)[1] = __half2(__float2half(y.z), __float2half(y.w));
    }
}

// ===== LN2: out = LN(p0+p1+p2 + bias2 + x1h) =====
__global__ void __launch_bounds__(256)
add_ln3_kernel(const __half* __restrict__ p,
               const __half* __restrict__ rH,
               const float* __restrict__ bias2,
               const float* __restrict__ g,
               const float* __restrict__ beta,
               float* __restrict__ out) {
    const int warp = threadIdx.x >> 5, lane = threadIdx.x & 31;
    const int row = blockIdx.x * 8 + warp;
    const __half2* p0 = reinterpret_cast<const __half2*>(p + (size_t)row * DM);
    const __half2* p1 = reinterpret_cast<const __half2*>(p + (size_t)row * DM + MD);
    const __half2* p2 = reinterpret_cast<const __half2*>(p + (size_t)row * DM + 2 * (size_t)MD);
    const __half2* pr = reinterpret_cast<const __half2*>(rH + (size_t)row * DM);
    const float4* pb2 = reinterpret_cast<const float4*>(bias2);
    const float4* pg = reinterpret_cast<const float4*>(g);
    const float4* pb = reinterpret_cast<const float4*>(beta);

    float4 v[6];
    float sum = 0.f;
    #pragma unroll
    for (int ch = 0; ch < 6; ch++) {
        int e2 = (lane + 32 * ch) * 2;
        float2 a0 = __half22float2(p0[e2]),  a0b = __half22float2(p0[e2 + 1]);
        float2 a1 = __half22float2(p1[e2]),  a1b = __half22float2(p1[e2 + 1]);
        float2 a2 = __half22float2(p2[e2]),  a2b = __half22float2(p2[e2 + 1]);
        float2 rr = __half22float2(pr[e2]),  rrb = __half22float2(pr[e2 + 1]);
        float4 b2 = pb2[lane + 32 * ch];
        v[ch] = make_float4(a0.x + a1.x + a2.x + b2.x + rr.x,
                            a0.y + a1.y + a2.y + b2.y + rr.y,
                            a0b.x + a1b.x + a2b.x + b2.z + rrb.x,
                            a0b.y + a1b.y + a2b.y + b2.w + rrb.y);
        sum += v[ch].x + v[ch].y + v[ch].z + v[ch].w;
    }
    #pragma unroll
    for (int o = 16; o > 0; o >>= 1) sum += __shfl_xor_sync(0xffffffffu, sum, o);
    float mu = sum * (1.0f / DM);

    float var = 0.f;
    #pragma unroll
    for (int ch = 0; ch < 6; ch++) {
        float dx = v[ch].x - mu, dy = v[ch].y - mu, dz = v[ch].z - mu, dw = v[ch].w - mu;
        var += dx * dx + dy * dy + dz * dz + dw * dw;
    }
    #pragma unroll
    for (int o = 16; o > 0; o >>= 1) var += __shfl_xor_sync(0xffffffffu, var, o);
    float rstd = rsqrtf(var * (1.0f / DM) + 1e-5f);

    float4* po = reinterpret_cast<float4*>(out + (size_t)row * DM);
    #pragma unroll
    for (int ch = 0; ch < 6; ch++) {
        float4 gg = pg[lane + 32 * ch];
        float4 bb = pb[lane + 32 * ch];
        float4 y;
        y.x = (v[ch].x - mu) * rstd * gg.x + bb.x;
        y.y = (v[ch].y - mu) * rstd * gg.y + bb.y;
        y.z = (v[ch].z - mu) * rstd * gg.z + bb.z;
        y.w = (v[ch].w - mu) * rstd * gg.w + bb.w;
        po[lane + 32 * ch] = y;
    }
}

// ================= launch =================
extern "C" void kernel_launch(void* const* d_in, const int* in_sizes, int n_in,
                              void* d_out, int out_size) {
    const float* x     = (const float*)d_in[0];
    const float* Wq    = (const float*)d_in[1];
    const float* bq    = (const float*)d_in[2];
    const float* Wk    = (const float*)d_in[3];
    const float* bk    = (const float*)d_in[4];
    const float* Wv    = (const float*)d_in[5];
    const float* bv    = (const float*)d_in[6];
    const float* ln1_g = (const float*)d_in[7];
    const float* ln1_b = (const float*)d_in[8];
    const float* W1    = (const float*)d_in[9];
    const float* b1    = (const float*)d_in[10];
    const float* W2    = (const float*)d_in[11];
    const float* b2    = (const float*)d_in[12];
    const float* ln2_g = (const float*)d_in[13];
    const float* ln2_b = (const float*)d_in[14];
    float* out = (float*)d_out;

    float *attn, *bqkv;
    __half *q, *kv, *xh, *x1h, *hid, *ffp, *wqkv, *w1, *w2;
    cudaGetSymbolAddress((void**)&attn, g_attn);
    cudaGetSymbolAddress((void**)&bqkv, g_bqkv);
    cudaGetSymbolAddress((void**)&q, g_q);
    cudaGetSymbolAddress((void**)&kv, g_kv);
    cudaGetSymbolAddress((void**)&xh, g_xh);
    cudaGetSymbolAddress((void**)&x1h, g_x1h);
    cudaGetSymbolAddress((void**)&hid, g_hid);
    cudaGetSymbolAddress((void**)&ffp, g_ffp);
    cudaGetSymbolAddress((void**)&wqkv, g_wqkv);
    cudaGetSymbolAddress((void**)&w1, g_w1);     cudaGetSymbolAddress((void**)&w2, g_w2);

    const int SMEM_F = 3 * 2 * 16384;   // 1-term, 3 stages = 96KB
    cudaFuncSetAttribute((const void*)tc_gemm<1,3>, cudaFuncAttributeMaxDynamicSharedMemorySize, SMEM_F);
    cudaFuncSetAttribute(attn_kernel, cudaFuncAttributeMaxDynamicSharedMemorySize, ATTN_SMEM);

    // ---- merged prep: weights + bias + x convert (one launch) ----
    prep_all<<<12489, 256>>>(x, Wq, Wk, Wv, W1, W2, bq, bk, bv,
                             wqkv, w1, w2, bqkv, xh);

    // ---- fused QKV projection (1-term): q single fp16 (scaled), k/v fp16 ----
    {
        dim3 grid(QKVN / 128, MROWS / 128);
        tc_gemm<1,3><<<grid, 256, SMEM_F>>>(xh, nullptr, wqkv, bqkv, (float*)kv,
                                            q, MROWS, QKVN, DM, 2);
    }

    // ---- attention ----
    {
        dim3 grid(NC, NH, BB);
        attn_kernel<<<grid, 128, ATTN_SMEM>>>(q, kv, attn);
    }

    // ---- x1 = LN(attn + x), fp16 only ----
    add_ln_kernel<<<MROWS / 8, 256>>>(attn, x, ln1_g, ln1_b, x1h);

    // ---- FFN (1-term) ----
    {
        dim3 grid1(FF / 128, MROWS / 128);
        tc_gemm<1,3><<<grid1, 256, SMEM_F>>>(x1h, nullptr, w1, b1, nullptr,
                                             hid, MROWS, FF, DM, 1);
        dim3 grid2(DM / 128, MROWS / 128, 3);   // split-K = 3, fp16 partials
        tc_gemm<1,3><<<grid2, 256, SMEM_F>>>(hid, nullptr, w2, nullptr, nullptr,
                                             ffp, MROWS, DM, FF, 3);
    }

    // ---- out = LN(p0+p1+p2 + b2 + x1) ----
    add_ln3_kernel<<<MROWS / 8, 256>>>(ffp, x1h, b2, ln2_g, ln2_b, out);
}

// round 16
// speedup vs baseline: 2.7284x; 1.0140x over previous
#include <cuda_runtime.h>
#include <cuda_bf16.h>
#include <cuda_fp16.h>
#include <math.h>
#include <cstdint>

#define BB 2
#define SS 4096
#define DM 768
#define NH 12
#define FF 3072
#define WIN 64
#define HD 64
#define NC (SS / WIN)
#define MROWS (BB * SS)    // 8192
#define QKVN (3 * DM)      // 2304
#define KVW (2 * DM)       // 1536
#define MD (MROWS * DM)

// ================= helpers =================
__device__ __forceinline__ uint32_t smem_to_u32(const void* p) {
    uint32_t a;
    asm("{ .reg .u64 t; cvta.to.shared.u64 t, %1; cvt.u32.u64 %0, t; }" : "=r"(a) : "l"(p));
    return a;
}
#define SMEM_SWIZZLE_128B(o) ((o) ^ (((o) >> 3) & 0x70))

__device__ __forceinline__ void ldsm_x4(uint32_t r[4], uint32_t addr) {
    asm volatile("ldmatrix.sync.aligned.m8n8.x4.shared.b16 {%0,%1,%2,%3}, [%4];"
        : "=r"(r[0]), "=r"(r[1]), "=r"(r[2]), "=r"(r[3]) : "r"(addr));
}
__device__ __forceinline__ void ldsm_x4_trans(uint32_t r[4], uint32_t addr) {
    asm volatile("ldmatrix.sync.aligned.m8n8.x4.trans.shared.b16 {%0,%1,%2,%3}, [%4];"
        : "=r"(r[0]), "=r"(r[1]), "=r"(r[2]), "=r"(r[3]) : "r"(addr));
}
__device__ __forceinline__ void mma_fp16(float c[4], const uint32_t a[4],
                                         uint32_t b0, uint32_t b1) {
    asm volatile("mma.sync.aligned.m16n8k16.row.col.f32.f16.f16.f32 "
        "{%0,%1,%2,%3}, {%4,%5,%6,%7}, {%8,%9}, {%0,%1,%2,%3};"
        : "+f"(c[0]), "+f"(c[1]), "+f"(c[2]), "+f"(c[3])
        : "r"(a[0]), "r"(a[1]), "r"(a[2]), "r"(a[3]), "r"(b0), "r"(b1));
}
__device__ __forceinline__ uint32_t pack_f16x2(float x, float y) {
    __half2 t(__float2half(x), __float2half(y));
    return *reinterpret_cast<uint32_t*>(&t);
}
__device__ __forceinline__ float gelu_tanh(float x) {
    const float c = 0.7978845608028654f;
    float x3 = x * x * x;
    return 0.5f * x * (1.0f + tanhf(c * (x + 0.044715f * x3)));
}

// ================= scratch =================
__device__ __half g_attn[MD];                 // attention output, fp16
__device__ float g_bqkv[QKVN];
__device__ __half g_q[MD];                    // q pre-scaled, single fp16
__device__ __half g_kv[MROWS * KVW];
__device__ __half g_xh[MD];
__device__ __half g_x1h[MD];
__device__ __half g_hid[MROWS * FF];
__device__ __half g_ffp[3 * MD];
__device__ __half g_wqkv[QKVN * DM];
__device__ __half g_w1[FF * DM];
__device__ __half g_w2[DM * FF];

// ========== merged prep: weight transpose + bias pack + x convert ==========
__global__ void prep_all(const float* __restrict__ x,
                         const float* __restrict__ Wq, const float* __restrict__ Wk,
                         const float* __restrict__ Wv, const float* __restrict__ W1,
                         const float* __restrict__ W2,
                         const float* __restrict__ bq, const float* __restrict__ bk,
                         const float* __restrict__ bv,
                         __half* __restrict__ wqkv,
                         __half* __restrict__ w1,
                         __half* __restrict__ w2,
                         float* __restrict__ bqkv,
                         __half* __restrict__ xh) {
    int id = blockIdx.x;
    if (id >= 6345) {
        int i = (id - 6345) * 256 + threadIdx.x;
        float4 v = reinterpret_cast<const float4*>(x)[i];
        reinterpret_cast<__half2*>(xh)[i*2+0] = __half2(__float2half(v.x), __float2half(v.y));
        reinterpret_cast<__half2*>(xh)[i*2+1] = __half2(__float2half(v.z), __float2half(v.w));
        return;
    }
    if (id >= 6336) {
        int i = (id - 6336) * 256 + threadIdx.x;
        if (i < QKVN)
            bqkv[i] = (i < DM) ? bq[i] : (i < 2 * DM) ? bk[i - DM] : bv[i - 2 * DM];
        return;
    }
    const float* W; __half* T; int K, N, tix;
    if (id < 576)       { W = Wq; T = wqkv;               K = DM; N = DM; tix = id; }
    else if (id < 1152) { W = Wk; T = wqkv + DM * DM;     K = DM; N = DM; tix = id - 576; }
    else if (id < 1728) { W = Wv; T = wqkv + 2 * DM * DM; K = DM; N = DM; tix = id - 1152; }
    else if (id < 4032) { W = W1; T = w1;                 K = DM; N = FF; tix = id - 1728; }
    else                { W = W2; T = w2;                 K = FF; N = DM; tix = id - 4032; }
    int nt = N / 32;
    int n0 = (tix % nt) * 32, k0 = (tix / nt) * 32;
    __shared__ float t[32][33];
    int tx = threadIdx.x & 31, ty = threadIdx.x >> 5;
    #pragma unroll
    for (int i = 0; i < 4; i++)
        t[ty + i*8][tx] = W[(size_t)(k0 + ty + i*8) * N + n0 + tx];
    __syncthreads();
    #pragma unroll
    for (int i = 0; i < 4; i++) {
        T[(size_t)(n0 + ty + i*8) * K + k0 + tx] = __float2half(t[tx][ty + i*8]);
    }
}

// ========== HMMA GEMM (templated TERMS/NSTAGES; 96KB smem, 2 CTAs/SM) ==========
template<int TERMS, int NSTAGES>
__global__ void __launch_bounds__(256, 2)
tc_gemm(const __half* __restrict__ Ah, const __half* __restrict__ Al,
        const __half* __restrict__ B,
        const float* __restrict__ bias,
        float* __restrict__ outF,
        void* __restrict__ outAux,
        int M, int N, int K, int mode) {
    constexpr uint32_t STAGE = (TERMS + 1) * 16384u;
    extern __shared__ char smem[];
    const uint32_t tiles = smem_to_u32(smem);
    const int tid = threadIdx.x;
    const int wid = tid >> 5;
    const int lane = tid & 31;
    const int warpM = wid >> 1;
    const int warpN = wid & 1;
    const int bm = blockIdx.y * 128;
    const int bn = blockIdx.x * 128;
    const int kb0 = (mode == 3) ? blockIdx.z * 16 : 0;
    const int NB  = (mode == 3) ? 16 : (K >> 6);
    __half* aux = (__half*)outAux;
    if (mode == 3) aux += (size_t)blockIdx.z * M * N;

    const __half* srcs[2] = {Ah, Al};

    auto stage = [&](int kb, int s) {
        #pragma unroll
        for (int t = 0; t < TERMS + 1; t++) {
            const __half* src = (t < TERMS) ? srcs[t] : B;
            const int rbase = (t < TERMS) ? bm : bn;
            const uint32_t sb = tiles + (uint32_t)s * STAGE + (uint32_t)t * 16384u;
            #pragma unroll
            for (int i = 0; i < 4; i++) {
                int chunk = tid + i * 256;
                int row = chunk >> 3;
                int c16 = chunk & 7;
                uint32_t off = (uint32_t)(row * 128 + c16 * 16);
                uint32_t dst = sb + SMEM_SWIZZLE_128B(off);
                const void* g = src + (size_t)(rbase + row) * K + kb * 64 + c16 * 8;
                asm volatile("cp.async.cg.shared.global [%0], [%1], 16;" :: "r"(dst), "l"(g));
            }
        }
        asm volatile("cp.async.commit_group;" ::: "memory");
    };

    float c[2][8][4] = {};

    stage(kb0, 0);
    if (NSTAGES >= 3 && NB > 1) stage(kb0 + 1, 1);

    const int lrow = lane & 15;
    const int lchunk = lane >> 4;

    for (int kb = 0; kb < NB; kb++) {
        const int s = kb % NSTAGES;
        if (NSTAGES >= 3) {
            if (kb + 1 < NB) asm volatile("cp.async.wait_group 1;" ::: "memory");
            else             asm volatile("cp.async.wait_group 0;" ::: "memory");
            __syncthreads();
            if (kb + 2 < NB) stage(kb0 + kb + 2, (kb + 2) % NSTAGES);
        } else {
            asm volatile("cp.async.wait_group 0;" ::: "memory");
            __syncthreads();
            if (kb + 1 < NB) stage(kb0 + kb + 1, (kb + 1) % NSTAGES);
        }

        const uint32_t base_s = tiles + (uint32_t)s * STAGE;
        const uint32_t baseB = base_s + (uint32_t)TERMS * 16384u;
        #pragma unroll
        for (int ks = 0; ks < 4; ks++) {
            uint32_t ah[2][4], al2[2][4];
            #pragma unroll
            for (int mt = 0; mt < 2; mt++) {
                uint32_t off = (uint32_t)((warpM * 32 + mt * 16 + lrow) * 128 + ks * 32 + lchunk * 16);
                uint32_t sw = SMEM_SWIZZLE_128B(off);
                ldsm_x4(ah[mt], base_s + sw);
                if (TERMS == 2) ldsm_x4(al2[mt], base_s + 16384u + sw);
            }
            uint32_t bb[2][4];
            {
                uint32_t off0 = (uint32_t)((warpN * 64 + lrow) * 128 + ks * 32 + lchunk * 16);
                ldsm_x4(bb[0], baseB + SMEM_SWIZZLE_128B(off0));
            }
            #pragma unroll
            for (int np = 0; np < 4; np++) {
                const int cur = np & 1;
                if (np < 3) {
                    uint32_t off = (uint32_t)((warpN * 64 + (np + 1) * 16 + lrow) * 128 + ks * 32 + lchunk * 16);
                    ldsm_x4(bb[cur ^ 1], baseB + SMEM_SWIZZLE_128B(off));
                }
                #pragma unroll
                for (int mt = 0; mt < 2; mt++) {
                    mma_fp16(c[mt][2*np],   ah[mt], bb[cur][0], bb[cur][2]);
                    mma_fp16(c[mt][2*np+1], ah[mt], bb[cur][1], bb[cur][3]);
                    if (TERMS == 2) {
                        mma_fp16(c[mt][2*np],   al2[mt], bb[cur][0], bb[cur][2]);
                        mma_fp16(c[mt][2*np+1], al2[mt], bb[cur][1], bb[cur][3]);
                    }
                }
            }
        }
        if (NSTAGES == 2) __syncthreads();
    }
    __syncthreads();

    float* sD = reinterpret_cast<float*>(smem);   // 128 x 129
    #pragma unroll
    for (int mt = 0; mt < 2; mt++) {
        #pragma unroll
        for (int nt = 0; nt < 8; nt++) {
            int r0 = warpM * 32 + mt * 16 + (lane >> 2);
            int col = warpN * 64 + nt * 8 + (lane & 3) * 2;
            sD[r0 * 129 + col]           = c[mt][nt][0];
            sD[r0 * 129 + col + 1]       = c[mt][nt][1];
            sD[(r0 + 8) * 129 + col]     = c[mt][nt][2];
            sD[(r0 + 8) * 129 + col + 1] = c[mt][nt][3];
        }
    }
    __syncthreads();

    for (int idx = tid; idx < 128 * 128; idx += 256) {
        int r = idx >> 7, cc = idx & 127;
        float v = sD[r * 129 + cc];
        size_t row = (size_t)(bm + r);
        int gc = bn + cc;
        if (mode == 3) {
            aux[row * N + gc] = __float2half(v);
            continue;
        }
        v += bias[gc];
        if (mode == 0) {
            outF[row * N + gc] = v;
        } else if (mode == 1) {
            v = gelu_tanh(v);
            aux[row * N + gc] = __float2half(v);
        } else {
            if (gc < DM) {
                aux[row * DM + gc] = __float2half(v * 0.125f);
            } else {
                ((__half*)outF)[row * KVW + (gc - DM)] = __float2half(v);
            }
        }
    }
}

// ================= HMMA sliding-window attention =================
// q/k/v single fp16; QK 1-term, PV 1-term (P single fp16); out fp16.
#define AQ  0
#define AK  8192
#define AV  32768
#define ATTN_SMEM 57344
__global__ void __launch_bounds__(128, 2)
attn_kernel(const __half* __restrict__ q,
            const __half* __restrict__ kv,
            __half* __restrict__ out) {
    extern __shared__ char smem[];
    const uint32_t sb = smem_to_u32(smem);
    const int c = blockIdx.x, h = blockIdx.y, b = blockIdx.z;
    const int tid = threadIdx.x, warp = tid >> 5, lane = tid & 31;

    for (int idx = tid; idx < 64 * 8; idx += 128) {
        int r = idx >> 3, ch = idx & 7;
        uint32_t off = SMEM_SWIZZLE_128B((uint32_t)(r * 128 + ch * 16));
        size_t gsrc = ((size_t)b * SS + c * 64 + r) * DM + h * HD + ch * 8;
        asm volatile("cp.async.cg.shared.global [%0], [%1], 16;"
                     :: "r"(sb + AQ + off), "l"(q + gsrc));
    }
    for (int idx = tid; idx < 192 * 8; idx += 128) {
        int j = idx >> 3, ch = idx & 7;
        int g = c * 64 - 64 + j;
        int in = (g >= 0 && g < SS);
        size_t rb = ((size_t)b * SS + (in ? g : 0)) * KVW + h * HD + ch * 8;
        uint32_t off = SMEM_SWIZZLE_128B((uint32_t)(j * 128 + ch * 16));
        int sz = in ? 16 : 0;
        asm volatile("cp.async.cg.shared.global [%0], [%1], 16, %2;"
                     :: "r"(sb + AK + off), "l"(kv + rb), "r"(sz));
        asm volatile("cp.async.cg.shared.global [%0], [%1], 16, %2;"
                     :: "r"(sb + AV + off), "l"(kv + rb + DM), "r"(sz));
    }
    asm volatile("cp.async.commit_group;" ::: "memory");
    asm volatile("cp.async.wait_group 0;" ::: "memory");
    __syncthreads();

    const int m0 = warp * 16;
    const int lrow = lane & 15;
    const int lch = lane >> 4;

    float s[24][4];
    #pragma unroll
    for (int nt = 0; nt < 24; nt++)
        #pragma unroll
        for (int u = 0; u < 4; u++) s[nt][u] = 0.f;

    #pragma unroll
    for (int ks = 0; ks < 4; ks++) {
        uint32_t aoff = SMEM_SWIZZLE_128B((uint32_t)((m0 + lrow) * 128 + ks * 32 + lch * 16));
        uint32_t ah[4];
        ldsm_x4(ah, sb + AQ + aoff);
        #pragma unroll
        for (int n6 = 0; n6 < 12; n6++) {
            uint32_t boff = SMEM_SWIZZLE_128B((uint32_t)((n6 * 16 + lrow) * 128 + ks * 32 + lch * 16));
            uint32_t bk4[4];
            ldsm_x4(bk4, sb + AK + boff);
            mma_fp16(s[2*n6],   ah, bk4[0], bk4[2]);
            mma_fp16(s[2*n6+1], ah, bk4[1], bk4[3]);
        }
    }

    const int rA = m0 + (lane >> 2);
    const int rB = rA + 8;
    const int jb = 2 * (lane & 3);
    const int gof = c * 64 - 64;
    float mA = -INFINITY, mB = -INFINITY;
    #pragma unroll
    for (int nt = 0; nt < 24; nt++) {
        int j0 = nt * 8 + jb, j1 = j0 + 1;
        int g0 = gof + j0, g1 = gof + j1;
        bool in0 = (g0 >= 0) && (g0 < SS);
        bool in1 = (g1 >= 0) && (g1 < SS);
        if (!((j0 >= rA) && (j0 <= rA + 128) && in0)) s[nt][0] = -INFINITY;
        if (!((j1 >= rA) && (j1 <= rA + 128) && in1)) s[nt][1] = -INFINITY;
        if (!((j0 >= rB) && (j0 <= rB + 128) && in0)) s[nt][2] = -INFINITY;
        if (!((j1 >= rB) && (j1 <= rB + 128) && in1)) s[nt][3] = -INFINITY;
        mA = fmaxf(mA, fmaxf(s[nt][0], s[nt][1]));
        mB = fmaxf(mB, fmaxf(s[nt][2], s[nt][3]));
    }
    mA = fmaxf(mA, __shfl_xor_sync(0xffffffffu, mA, 1));
    mA = fmaxf(mA, __shfl_xor_sync(0xffffffffu, mA, 2));
    mB = fmaxf(mB, __shfl_xor_sync(0xffffffffu, mB, 1));
    mB = fmaxf(mB, __shfl_xor_sync(0xffffffffu, mB, 2));
    float sA = 0.f, sB = 0.f;
    #pragma unroll
    for (int nt = 0; nt < 24; nt++) {
        s[nt][0] = __expf(s[nt][0] - mA);
        s[nt][1] = __expf(s[nt][1] - mA);
        s[nt][2] = __expf(s[nt][2] - mB);
        s[nt][3] = __expf(s[nt][3] - mB);
        sA += s[nt][0] + s[nt][1];
        sB += s[nt][2] + s[nt][3];
    }
    sA += __shfl_xor_sync(0xffffffffu, sA, 1);
    sA += __shfl_xor_sync(0xffffffffu, sA, 2);
    sB += __shfl_xor_sync(0xffffffffu, sB, 1);
    sB += __shfl_xor_sync(0xffffffffu, sB, 2);
    const float invA = 1.0f / sA, invB = 1.0f / sB;

    // ---- PV: P single fp16 x V single fp16 ----
    float o[8][4];
    #pragma unroll
    for (int nt = 0; nt < 8; nt++)
        #pragma unroll
        for (int u = 0; u < 4; u++) o[nt][u] = 0.f;

    #pragma unroll
    for (int t = 0; t < 12; t++) {
        uint32_t ph[4];
        ph[0] = pack_f16x2(s[2*t][0],   s[2*t][1]);
        ph[1] = pack_f16x2(s[2*t][2],   s[2*t][3]);
        ph[2] = pack_f16x2(s[2*t+1][0], s[2*t+1][1]);
        ph[3] = pack_f16x2(s[2*t+1][2], s[2*t+1][3]);
        #pragma unroll
        for (int nn = 0; nn < 4; nn++) {
            uint32_t voff = SMEM_SWIZZLE_128B(
                (uint32_t)((t * 16 + (lane & 15)) * 128 + (nn * 16 + (lane >> 4) * 8) * 2));
            uint32_t vv[4];
            ldsm_x4_trans(vv, sb + AV + voff);
            mma_fp16(o[2*nn],   ph, vv[0], vv[1]);
            mma_fp16(o[2*nn+1], ph, vv[2], vv[3]);
        }
    }

    const size_t rowg = (size_t)b * SS + c * 64;
    #pragma unroll
    for (int nt = 0; nt < 8; nt++) {
        int col = h * HD + nt * 8 + jb;
        uint32_t pA = pack_f16x2(o[nt][0] * invA, o[nt][1] * invA);
        uint32_t pB = pack_f16x2(o[nt][2] * invB, o[nt][3] * invB);
        *reinterpret_cast<uint32_t*>(&out[(rowg + rA) * DM + col]) = pA;
        *reinterpret_cast<uint32_t*>(&out[(rowg + rB) * DM + col]) = pB;
    }
}

// ============ LN1: x1 = LN(attn_fp16 + x), emit fp16 ============
__global__ void __launch_bounds__(256)
add_ln_kernel(const __half* __restrict__ aH,
              const float* __restrict__ r,
              const float* __restrict__ g,
              const float* __restrict__ beta,
              __half* __restrict__ outH) {
    const int warp = threadIdx.x >> 5, lane = threadIdx.x & 31;
    const int row = blockIdx.x * 8 + warp;
    const __half2* pa = reinterpret_cast<const __half2*>(aH + (size_t)row * DM);
    const float4* pr = reinterpret_cast<const float4*>(r + (size_t)row * DM);
    const float4* pg = reinterpret_cast<const float4*>(g);
    const float4* pb = reinterpret_cast<const float4*>(beta);

    float4 v[6];
    float sum = 0.f;
    #pragma unroll
    for (int ch = 0; ch < 6; ch++) {
        int e2 = (lane + 32 * ch) * 2;
        float2 a0 = __half22float2(pa[e2]);
        float2 a1 = __half22float2(pa[e2 + 1]);
        float4 vr = pr[lane + 32 * ch];
        v[ch] = make_float4(a0.x + vr.x, a0.y + vr.y, a1.x + vr.z, a1.y + vr.w);
        sum += v[ch].x + v[ch].y + v[ch].z + v[ch].w;
    }
    #pragma unroll
    for (int o = 16; o > 0; o >>= 1) sum += __shfl_xor_sync(0xffffffffu, sum, o);
    float mu = sum * (1.0f / DM);

    float var = 0.f;
    #pragma unroll
    for (int ch = 0; ch < 6; ch++) {
        float dx = v[ch].x - mu, dy = v[ch].y - mu, dz = v[ch].z - mu, dw = v[ch].w - mu;
        var += dx * dx + dy * dy + dz * dz + dw * dw;
    }
    #pragma unroll
    for (int o = 16; o > 0; o >>= 1) var += __shfl_xor_sync(0xffffffffu, var, o);
    float rstd = rsqrtf(var * (1.0f / DM) + 1e-5f);

    #pragma unroll
    for (int ch = 0; ch < 6; ch++) {
        float4 gg = pg[lane + 32 * ch];
        float4 bb = pb[lane + 32 * ch];
        float4 y;
        y.x = (v[ch].x - mu) * rstd * gg.x + bb.x;
        y.y = (v[ch].y - mu) * rstd * gg.y + bb.y;
        y.z = (v[ch].z - mu) * rstd * gg.z + bb.z;
        y.w = (v[ch].w - mu) * rstd * gg.w + bb.w;
        size_t o4 = (size_t)row * DM + (lane + 32 * ch) * 4;
        reinterpret_cast<__half2*>(outH + o4)[0] = __half2(__float2half(y.x), __float2half(y.y));
        reinterpret_cast<__half2*>(outH + o4)[1] = __half2(__float2half(y.z), __float2half(y.w));
    }
}

// ===== LN2: out = LN(p0+p1+p2 + bias2 + x1h) =====
__global__ void __launch_bounds__(256)
add_ln3_kernel(const __half* __restrict__ p,
               const __half* __restrict__ rH,
               const float* __restrict__ bias2,
               const float* __restrict__ g,
               const float* __restrict__ beta,
               float* __restrict__ out) {
    const int warp = threadIdx.x >> 5, lane = threadIdx.x & 31;
    const int row = blockIdx.x * 8 + warp;
    const __half2* p0 = reinterpret_cast<const __half2*>(p + (size_t)row * DM);
    const __half2* p1 = reinterpret_cast<const __half2*>(p + (size_t)row * DM + MD);
    const __half2* p2 = reinterpret_cast<const __half2*>(p + (size_t)row * DM + 2 * (size_t)MD);
    const __half2* pr = reinterpret_cast<const __half2*>(rH + (size_t)row * DM);
    const float4* pb2 = reinterpret_cast<const float4*>(bias2);
    const float4* pg = reinterpret_cast<const float4*>(g);
    const float4* pb = reinterpret_cast<const float4*>(beta);

    float4 v[6];
    float sum = 0.f;
    #pragma unroll
    for (int ch = 0; ch < 6; ch++) {
        int e2 = (lane + 32 * ch) * 2;
        float2 a0 = __half22float2(p0[e2]),  a0b = __half22float2(p0[e2 + 1]);
        float2 a1 = __half22float2(p1[e2]),  a1b = __half22float2(p1[e2 + 1]);
        float2 a2 = __half22float2(p2[e2]),  a2b = __half22float2(p2[e2 + 1]);
        float2 rr = __half22float2(pr[e2]),  rrb = __half22float2(pr[e2 + 1]);
        float4 b2 = pb2[lane + 32 * ch];
        v[ch] = make_float4(a0.x + a1.x + a2.x + b2.x + rr.x,
                            a0.y + a1.y + a2.y + b2.y + rr.y,
                            a0b.x + a1b.x + a2b.x + b2.z + rrb.x,
                            a0b.y + a1b.y + a2b.y + b2.w + rrb.y);
        sum += v[ch].x + v[ch].y + v[ch].z + v[ch].w;
    }
    #pragma unroll
    for (int o = 16; o > 0; o >>= 1) sum += __shfl_xor_sync(0xffffffffu, sum, o);
    float mu = sum * (1.0f / DM);

    float var = 0.f;
    #pragma unroll
    for (int ch = 0; ch < 6; ch++) {
        float dx = v[ch].x - mu, dy = v[ch].y - mu, dz = v[ch].z - mu, dw = v[ch].w - mu;
        var += dx * dx + dy * dy + dz * dz + dw * dw;
    }
    #pragma unroll
    for (int o = 16; o > 0; o >>= 1) var += __shfl_xor_sync(0xffffffffu, var, o);
    float rstd = rsqrtf(var * (1.0f / DM) + 1e-5f);

    float4* po = reinterpret_cast<float4*>(out + (size_t)row * DM);
    #pragma unroll
    for (int ch = 0; ch < 6; ch++) {
        float4 gg = pg[lane + 32 * ch];
        float4 bb = pb[lane + 32 * ch];
        float4 y;
        y.x = (v[ch].x - mu) * rstd * gg.x + bb.x;
        y.y = (v[ch].y - mu) * rstd * gg.y + bb.y;
        y.z = (v[ch].z - mu) * rstd * gg.z + bb.z;
        y.w = (v[ch].w - mu) * rstd * gg.w + bb.w;
        po[lane + 32 * ch] = y;
    }
}

// ================= launch =================
extern "C" void kernel_launch(void* const* d_in, const int* in_sizes, int n_in,
                              void* d_out, int out_size) {
    const float* x     = (const float*)d_in[0];
    const float* Wq    = (const float*)d_in[1];
    const float* bq    = (const float*)d_in[2];
    const float* Wk    = (const float*)d_in[3];
    const float* bk    = (const float*)d_in[4];
    const float* Wv    = (const float*)d_in[5];
    const float* bv    = (const float*)d_in[6];
    const float* ln1_g = (const float*)d_in[7];
    const float* ln1_b = (const float*)d_in[8];
    const float* W1    = (const float*)d_in[9];
    const float* b1    = (const float*)d_in[10];
    const float* W2    = (const float*)d_in[11];
    const float* b2    = (const float*)d_in[12];
    const float* ln2_g = (const float*)d_in[13];
    const float* ln2_b = (const float*)d_in[14];
    float* out = (float*)d_out;

    float *bqkv;
    __half *attn, *q, *kv, *xh, *x1h, *hid, *ffp, *wqkv, *w1, *w2;
    cudaGetSymbolAddress((void**)&attn, g_attn);
    cudaGetSymbolAddress((void**)&bqkv, g_bqkv);
    cudaGetSymbolAddress((void**)&q, g_q);
    cudaGetSymbolAddress((void**)&kv, g_kv);
    cudaGetSymbolAddress((void**)&xh, g_xh);
    cudaGetSymbolAddress((void**)&x1h, g_x1h);
    cudaGetSymbolAddress((void**)&hid, g_hid);
    cudaGetSymbolAddress((void**)&ffp, g_ffp);
    cudaGetSymbolAddress((void**)&wqkv, g_wqkv);
    cudaGetSymbolAddress((void**)&w1, g_w1);     cudaGetSymbolAddress((void**)&w2, g_w2);

    const int SMEM_F = 3 * 2 * 16384;   // 1-term, 3 stages = 96KB
    cudaFuncSetAttribute((const void*)tc_gemm<1,3>, cudaFuncAttributeMaxDynamicSharedMemorySize, SMEM_F);
    cudaFuncSetAttribute(attn_kernel, cudaFuncAttributeMaxDynamicSharedMemorySize, ATTN_SMEM);

    // ---- merged prep ----
    prep_all<<<12489, 256>>>(x, Wq, Wk, Wv, W1, W2, bq, bk, bv,
                             wqkv, w1, w2, bqkv, xh);

    // ---- fused QKV projection (1-term) ----
    {
        dim3 grid(QKVN / 128, MROWS / 128);
        tc_gemm<1,3><<<grid, 256, SMEM_F>>>(xh, nullptr, wqkv, bqkv, (float*)kv,
                                            q, MROWS, QKVN, DM, 2);
    }

    // ---- attention ----
    {
        dim3 grid(NC, NH, BB);
        attn_kernel<<<grid, 128, ATTN_SMEM>>>(q, kv, attn);
    }

    // ---- x1 = LN(attn + x), fp16 ----
    add_ln_kernel<<<MROWS / 8, 256>>>(attn, x, ln1_g, ln1_b, x1h);

    // ---- FFN (1-term) ----
    {
        dim3 grid1(FF / 128, MROWS / 128);
        tc_gemm<1,3><<<grid1, 256, SMEM_F>>>(x1h, nullptr, w1, b1, nullptr,
                                             hid, MROWS, FF, DM, 1);
        dim3 grid2(DM / 128, MROWS / 128, 3);   // split-K = 3, fp16 partials
        tc_gemm<1,3><<<grid2, 256, SMEM_F>>>(hid, nullptr, w2, nullptr, nullptr,
                                             ffp, MROWS, DM, FF, 3);
    }

    // ---- out = LN(p0+p1+p2 + b2 + x1) ----
    add_ln3_kernel<<<MROWS / 8, 256>>>(ffp, x1h, b2, ln2_g, ln2_b, out);
}

// round 17
// speedup vs baseline: 2.7458x; 1.0064x over previous
#include <cuda_runtime.h>
#include <cuda_bf16.h>
#include <cuda_fp16.h>
#include <math.h>
#include <cstdint>

#define BB 2
#define SS 4096
#define DM 768
#define NH 12
#define FF 3072
#define WIN 64
#define HD 64
#define NC (SS / WIN)
#define MROWS (BB * SS)    // 8192
#define QKVN (3 * DM)      // 2304
#define KVW (2 * DM)       // 1536
#define MD (MROWS * DM)

// ================= helpers =================
__device__ __forceinline__ uint32_t smem_to_u32(const void* p) {
    uint32_t a;
    asm("{ .reg .u64 t; cvta.to.shared.u64 t, %1; cvt.u32.u64 %0, t; }" : "=r"(a) : "l"(p));
    return a;
}
#define SMEM_SWIZZLE_128B(o) ((o) ^ (((o) >> 3) & 0x70))

__device__ __forceinline__ void ldsm_x4(uint32_t r[4], uint32_t addr) {
    asm volatile("ldmatrix.sync.aligned.m8n8.x4.shared.b16 {%0,%1,%2,%3}, [%4];"
        : "=r"(r[0]), "=r"(r[1]), "=r"(r[2]), "=r"(r[3]) : "r"(addr));
}
__device__ __forceinline__ void ldsm_x4_trans(uint32_t r[4], uint32_t addr) {
    asm volatile("ldmatrix.sync.aligned.m8n8.x4.trans.shared.b16 {%0,%1,%2,%3}, [%4];"
        : "=r"(r[0]), "=r"(r[1]), "=r"(r[2]), "=r"(r[3]) : "r"(addr));
}
__device__ __forceinline__ void mma_fp16(float c[4], const uint32_t a[4],
                                         uint32_t b0, uint32_t b1) {
    asm volatile("mma.sync.aligned.m16n8k16.row.col.f32.f16.f16.f32 "
        "{%0,%1,%2,%3}, {%4,%5,%6,%7}, {%8,%9}, {%0,%1,%2,%3};"
        : "+f"(c[0]), "+f"(c[1]), "+f"(c[2]), "+f"(c[3])
        : "r"(a[0]), "r"(a[1]), "r"(a[2]), "r"(a[3]), "r"(b0), "r"(b1));
}
__device__ __forceinline__ uint32_t pack_f16x2(float x, float y) {
    __half2 t(__float2half(x), __float2half(y));
    return *reinterpret_cast<uint32_t*>(&t);
}
__device__ __forceinline__ float gelu_tanh(float x) {
    const float c = 0.7978845608028654f;
    float x3 = x * x * x;
    return 0.5f * x * (1.0f + tanhf(c * (x + 0.044715f * x3)));
}

// ================= scratch =================
__device__ __half g_attn[MD];
__device__ float g_bqkv[QKVN];
__device__ __half g_q[MD];
__device__ __half g_kv[MROWS * KVW];
__device__ __half g_xh[MD];
__device__ __half g_x1h[MD];
__device__ __half g_hid[MROWS * FF];
__device__ __half g_ffp[3 * MD];
__device__ __half g_wqkv[QKVN * DM];
__device__ __half g_w1[FF * DM];
__device__ __half g_w2[DM * FF];

// ========== merged prep: weight transpose + bias pack + x convert ==========
__global__ void prep_all(const float* __restrict__ x,
                         const float* __restrict__ Wq, const float* __restrict__ Wk,
                         const float* __restrict__ Wv, const float* __restrict__ W1,
                         const float* __restrict__ W2,
                         const float* __restrict__ bq, const float* __restrict__ bk,
                         const float* __restrict__ bv,
                         __half* __restrict__ wqkv,
                         __half* __restrict__ w1,
                         __half* __restrict__ w2,
                         float* __restrict__ bqkv,
                         __half* __restrict__ xh) {
    int id = blockIdx.x;
    if (id >= 6345) {
        int i = (id - 6345) * 256 + threadIdx.x;
        float4 v = reinterpret_cast<const float4*>(x)[i];
        reinterpret_cast<__half2*>(xh)[i*2+0] = __half2(__float2half(v.x), __float2half(v.y));
        reinterpret_cast<__half2*>(xh)[i*2+1] = __half2(__float2half(v.z), __float2half(v.w));
        return;
    }
    if (id >= 6336) {
        int i = (id - 6336) * 256 + threadIdx.x;
        if (i < QKVN)
            bqkv[i] = (i < DM) ? bq[i] : (i < 2 * DM) ? bk[i - DM] : bv[i - 2 * DM];
        return;
    }
    const float* W; __half* T; int K, N, tix;
    if (id < 576)       { W = Wq; T = wqkv;               K = DM; N = DM; tix = id; }
    else if (id < 1152) { W = Wk; T = wqkv + DM * DM;     K = DM; N = DM; tix = id - 576; }
    else if (id < 1728) { W = Wv; T = wqkv + 2 * DM * DM; K = DM; N = DM; tix = id - 1152; }
    else if (id < 4032) { W = W1; T = w1;                 K = DM; N = FF; tix = id - 1728; }
    else                { W = W2; T = w2;                 K = FF; N = DM; tix = id - 4032; }
    int nt = N / 32;
    int n0 = (tix % nt) * 32, k0 = (tix / nt) * 32;
    __shared__ float t[32][33];
    int tx = threadIdx.x & 31, ty = threadIdx.x >> 5;
    #pragma unroll
    for (int i = 0; i < 4; i++)
        t[ty + i*8][tx] = W[(size_t)(k0 + ty + i*8) * N + n0 + tx];
    __syncthreads();
    #pragma unroll
    for (int i = 0; i < 4; i++) {
        T[(size_t)(n0 + ty + i*8) * K + k0 + tx] = __float2half(t[tx][ty + i*8]);
    }
}

// ========== HMMA GEMM (templated TERMS/NSTAGES; 96KB smem, 2 CTAs/SM) ==========
template<int TERMS, int NSTAGES>
__global__ void __launch_bounds__(256, 2)
tc_gemm(const __half* __restrict__ Ah, const __half* __restrict__ Al,
        const __half* __restrict__ B,
        const float* __restrict__ bias,
        float* __restrict__ outF,
        void* __restrict__ outAux,
        int M, int N, int K, int mode) {
    constexpr uint32_t STAGE = (TERMS + 1) * 16384u;
    extern __shared__ char smem[];
    const uint32_t tiles = smem_to_u32(smem);
    const int tid = threadIdx.x;
    const int wid = tid >> 5;
    const int lane = tid & 31;
    const int warpM = wid >> 1;
    const int warpN = wid & 1;
    const int bm = blockIdx.y * 128;
    const int bn = blockIdx.x * 128;
    const int kb0 = (mode == 3) ? blockIdx.z * 16 : 0;
    const int NB  = (mode == 3) ? 16 : (K >> 6);
    __half* aux = (__half*)outAux;
    if (mode == 3) aux += (size_t)blockIdx.z * M * N;

    const __half* srcs[2] = {Ah, Al};

    auto stage = [&](int kb, int s) {
        #pragma unroll
        for (int t = 0; t < TERMS + 1; t++) {
            const __half* src = (t < TERMS) ? srcs[t] : B;
            const int rbase = (t < TERMS) ? bm : bn;
            const uint32_t sb = tiles + (uint32_t)s * STAGE + (uint32_t)t * 16384u;
            #pragma unroll
            for (int i = 0; i < 4; i++) {
                int chunk = tid + i * 256;
                int row = chunk >> 3;
                int c16 = chunk & 7;
                uint32_t off = (uint32_t)(row * 128 + c16 * 16);
                uint32_t dst = sb + SMEM_SWIZZLE_128B(off);
                const void* g = src + (size_t)(rbase + row) * K + kb * 64 + c16 * 8;
                asm volatile("cp.async.cg.shared.global [%0], [%1], 16;" :: "r"(dst), "l"(g));
            }
        }
        asm volatile("cp.async.commit_group;" ::: "memory");
    };

    float c[2][8][4] = {};

    stage(kb0, 0);
    if (NSTAGES >= 3 && NB > 1) stage(kb0 + 1, 1);

    const int lrow = lane & 15;
    const int lchunk = lane >> 4;

    for (int kb = 0; kb < NB; kb++) {
        const int s = kb % NSTAGES;
        if (NSTAGES >= 3) {
            if (kb + 1 < NB) asm volatile("cp.async.wait_group 1;" ::: "memory");
            else             asm volatile("cp.async.wait_group 0;" ::: "memory");
            __syncthreads();
            if (kb + 2 < NB) stage(kb0 + kb + 2, (kb + 2) % NSTAGES);
        } else {
            asm volatile("cp.async.wait_group 0;" ::: "memory");
            __syncthreads();
            if (kb + 1 < NB) stage(kb0 + kb + 1, (kb + 1) % NSTAGES);
        }

        const uint32_t base_s = tiles + (uint32_t)s * STAGE;
        const uint32_t baseB = base_s + (uint32_t)TERMS * 16384u;
        #pragma unroll
        for (int ks = 0; ks < 4; ks++) {
            uint32_t ah[2][4], al2[2][4];
            #pragma unroll
            for (int mt = 0; mt < 2; mt++) {
                uint32_t off = (uint32_t)((warpM * 32 + mt * 16 + lrow) * 128 + ks * 32 + lchunk * 16);
                uint32_t sw = SMEM_SWIZZLE_128B(off);
                ldsm_x4(ah[mt], base_s + sw);
                if (TERMS == 2) ldsm_x4(al2[mt], base_s + 16384u + sw);
            }
            uint32_t bb[2][4];
            {
                uint32_t off0 = (uint32_t)((warpN * 64 + lrow) * 128 + ks * 32 + lchunk * 16);
                ldsm_x4(bb[0], baseB + SMEM_SWIZZLE_128B(off0));
            }
            #pragma unroll
            for (int np = 0; np < 4; np++) {
                const int cur = np & 1;
                if (np < 3) {
                    uint32_t off = (uint32_t)((warpN * 64 + (np + 1) * 16 + lrow) * 128 + ks * 32 + lchunk * 16);
                    ldsm_x4(bb[cur ^ 1], baseB + SMEM_SWIZZLE_128B(off));
                }
                #pragma unroll
                for (int mt = 0; mt < 2; mt++) {
                    mma_fp16(c[mt][2*np],   ah[mt], bb[cur][0], bb[cur][2]);
                    mma_fp16(c[mt][2*np+1], ah[mt], bb[cur][1], bb[cur][3]);
                    if (TERMS == 2) {
                        mma_fp16(c[mt][2*np],   al2[mt], bb[cur][0], bb[cur][2]);
                        mma_fp16(c[mt][2*np+1], al2[mt], bb[cur][1], bb[cur][3]);
                    }
                }
            }
        }
        if (NSTAGES == 2) __syncthreads();
    }
    __syncthreads();

    float* sD = reinterpret_cast<float*>(smem);   // 128 x 129
    #pragma unroll
    for (int mt = 0; mt < 2; mt++) {
        #pragma unroll
        for (int nt = 0; nt < 8; nt++) {
            int r0 = warpM * 32 + mt * 16 + (lane >> 2);
            int col = warpN * 64 + nt * 8 + (lane & 3) * 2;
            sD[r0 * 129 + col]           = c[mt][nt][0];
            sD[r0 * 129 + col + 1]       = c[mt][nt][1];
            sD[(r0 + 8) * 129 + col]     = c[mt][nt][2];
            sD[(r0 + 8) * 129 + col + 1] = c[mt][nt][3];
        }
    }
    __syncthreads();

    for (int idx = tid; idx < 128 * 128; idx += 256) {
        int r = idx >> 7, cc = idx & 127;
        float v = sD[r * 129 + cc];
        size_t row = (size_t)(bm + r);
        int gc = bn + cc;
        if (mode == 3) {
            aux[row * N + gc] = __float2half(v);
            continue;
        }
        v += bias[gc];
        if (mode == 0) {
            outF[row * N + gc] = v;
        } else if (mode == 1) {
            v = gelu_tanh(v);
            aux[row * N + gc] = __float2half(v);
        } else {
            if (gc < DM) {
                aux[row * DM + gc] = __float2half(v * 0.125f);
            } else {
                ((__half*)outF)[row * KVW + (gc - DM)] = __float2half(v);
            }
        }
    }
}

// ================= HMMA sliding-window attention =================
// q/k/v single fp16; QK 1-term, PV 1-term; out fp16. 3 CTAs/SM, piped loads.
#define AQ  0
#define AK  8192
#define AV  32768
#define ATTN_SMEM 57344
__global__ void __launch_bounds__(128, 3)
attn_kernel(const __half* __restrict__ q,
            const __half* __restrict__ kv,
            __half* __restrict__ out) {
    extern __shared__ char smem[];
    const uint32_t sb = smem_to_u32(smem);
    const int c = blockIdx.x, h = blockIdx.y, b = blockIdx.z;
    const int tid = threadIdx.x, warp = tid >> 5, lane = tid & 31;

    // ---- group 0: q + k ----
    for (int idx = tid; idx < 64 * 8; idx += 128) {
        int r = idx >> 3, ch = idx & 7;
        uint32_t off = SMEM_SWIZZLE_128B((uint32_t)(r * 128 + ch * 16));
        size_t gsrc = ((size_t)b * SS + c * 64 + r) * DM + h * HD + ch * 8;
        asm volatile("cp.async.cg.shared.global [%0], [%1], 16;"
                     :: "r"(sb + AQ + off), "l"(q + gsrc));
    }
    for (int idx = tid; idx < 192 * 8; idx += 128) {
        int j = idx >> 3, ch = idx & 7;
        int g = c * 64 - 64 + j;
        int in = (g >= 0 && g < SS);
        size_t rb = ((size_t)b * SS + (in ? g : 0)) * KVW + h * HD + ch * 8;
        uint32_t off = SMEM_SWIZZLE_128B((uint32_t)(j * 128 + ch * 16));
        int sz = in ? 16 : 0;
        asm volatile("cp.async.cg.shared.global [%0], [%1], 16, %2;"
                     :: "r"(sb + AK + off), "l"(kv + rb), "r"(sz));
    }
    asm volatile("cp.async.commit_group;" ::: "memory");
    // ---- group 1: v ----
    for (int idx = tid; idx < 192 * 8; idx += 128) {
        int j = idx >> 3, ch = idx & 7;
        int g = c * 64 - 64 + j;
        int in = (g >= 0 && g < SS);
        size_t rb = ((size_t)b * SS + (in ? g : 0)) * KVW + h * HD + ch * 8;
        uint32_t off = SMEM_SWIZZLE_128B((uint32_t)(j * 128 + ch * 16));
        int sz = in ? 16 : 0;
        asm volatile("cp.async.cg.shared.global [%0], [%1], 16, %2;"
                     :: "r"(sb + AV + off), "l"(kv + rb + DM), "r"(sz));
    }
    asm volatile("cp.async.commit_group;" ::: "memory");

    asm volatile("cp.async.wait_group 1;" ::: "memory");   // q + k ready
    __syncthreads();

    const int m0 = warp * 16;
    const int lrow = lane & 15;
    const int lch = lane >> 4;

    float s[24][4];
    #pragma unroll
    for (int nt = 0; nt < 24; nt++)
        #pragma unroll
        for (int u = 0; u < 4; u++) s[nt][u] = 0.f;

    #pragma unroll
    for (int ks = 0; ks < 4; ks++) {
        uint32_t aoff = SMEM_SWIZZLE_128B((uint32_t)((m0 + lrow) * 128 + ks * 32 + lch * 16));
        uint32_t ah[4];
        ldsm_x4(ah, sb + AQ + aoff);
        #pragma unroll
        for (int n6 = 0; n6 < 12; n6++) {
            uint32_t boff = SMEM_SWIZZLE_128B((uint32_t)((n6 * 16 + lrow) * 128 + ks * 32 + lch * 16));
            uint32_t bk4[4];
            ldsm_x4(bk4, sb + AK + boff);
            mma_fp16(s[2*n6],   ah, bk4[0], bk4[2]);
            mma_fp16(s[2*n6+1], ah, bk4[1], bk4[3]);
        }
    }

    asm volatile("cp.async.wait_group 0;" ::: "memory");   // v ready
    __syncthreads();

    const int rA = m0 + (lane >> 2);
    const int rB = rA + 8;
    const int jb = 2 * (lane & 3);
    const int gof = c * 64 - 64;
    float mA = -INFINITY, mB = -INFINITY;
    #pragma unroll
    for (int nt = 0; nt < 24; nt++) {
        int j0 = nt * 8 + jb, j1 = j0 + 1;
        int g0 = gof + j0, g1 = gof + j1;
        bool in0 = (g0 >= 0) && (g0 < SS);
        bool in1 = (g1 >= 0) && (g1 < SS);
        if (!((j0 >= rA) && (j0 <= rA + 128) && in0)) s[nt][0] = -INFINITY;
        if (!((j1 >= rA) && (j1 <= rA + 128) && in1)) s[nt][1] = -INFINITY;
        if (!((j0 >= rB) && (j0 <= rB + 128) && in0)) s[nt][2] = -INFINITY;
        if (!((j1 >= rB) && (j1 <= rB + 128) && in1)) s[nt][3] = -INFINITY;
        mA = fmaxf(mA, fmaxf(s[nt][0], s[nt][1]));
        mB = fmaxf(mB, fmaxf(s[nt][2], s[nt][3]));
    }
    mA = fmaxf(mA, __shfl_xor_sync(0xffffffffu, mA, 1));
    mA = fmaxf(mA, __shfl_xor_sync(0xffffffffu, mA, 2));
    mB = fmaxf(mB, __shfl_xor_sync(0xffffffffu, mB, 1));
    mB = fmaxf(mB, __shfl_xor_sync(0xffffffffu, mB, 2));
    float sA = 0.f, sB = 0.f;
    #pragma unroll
    for (int nt = 0; nt < 24; nt++) {
        s[nt][0] = __expf(s[nt][0] - mA);
        s[nt][1] = __expf(s[nt][1] - mA);
        s[nt][2] = __expf(s[nt][2] - mB);
        s[nt][3] = __expf(s[nt][3] - mB);
        sA += s[nt][0] + s[nt][1];
        sB += s[nt][2] + s[nt][3];
    }
    sA += __shfl_xor_sync(0xffffffffu, sA, 1);
    sA += __shfl_xor_sync(0xffffffffu, sA, 2);
    sB += __shfl_xor_sync(0xffffffffu, sB, 1);
    sB += __shfl_xor_sync(0xffffffffu, sB, 2);
    const float invA = 1.0f / sA, invB = 1.0f / sB;

    float o[8][4];
    #pragma unroll
    for (int nt = 0; nt < 8; nt++)
        #pragma unroll
        for (int u = 0; u < 4; u++) o[nt][u] = 0.f;

    #pragma unroll
    for (int t = 0; t < 12; t++) {
        uint32_t ph[4];
        ph[0] = pack_f16x2(s[2*t][0],   s[2*t][1]);
        ph[1] = pack_f16x2(s[2*t][2],   s[2*t][3]);
        ph[2] = pack_f16x2(s[2*t+1][0], s[2*t+1][1]);
        ph[3] = pack_f16x2(s[2*t+1][2], s[2*t+1][3]);
        #pragma unroll
        for (int nn = 0; nn < 4; nn++) {
            uint32_t voff = SMEM_SWIZZLE_128B(
                (uint32_t)((t * 16 + (lane & 15)) * 128 + (nn * 16 + (lane >> 4) * 8) * 2));
            uint32_t vv[4];
            ldsm_x4_trans(vv, sb + AV + voff);
            mma_fp16(o[2*nn],   ph, vv[0], vv[1]);
            mma_fp16(o[2*nn+1], ph, vv[2], vv[3]);
        }
    }

    const size_t rowg = (size_t)b * SS + c * 64;
    #pragma unroll
    for (int nt = 0; nt < 8; nt++) {
        int col = h * HD + nt * 8 + jb;
        uint32_t pA = pack_f16x2(o[nt][0] * invA, o[nt][1] * invA);
        uint32_t pB = pack_f16x2(o[nt][2] * invB, o[nt][3] * invB);
        *reinterpret_cast<uint32_t*>(&out[(rowg + rA) * DM + col]) = pA;
        *reinterpret_cast<uint32_t*>(&out[(rowg + rB) * DM + col]) = pB;
    }
}

// ============ LN1: x1 = LN(attn_fp16 + x_fp16), emit fp16 ============
__global__ void __launch_bounds__(256)
add_ln_kernel(const __half* __restrict__ aH,
              const __half* __restrict__ rH,
              const float* __restrict__ g,
              const float* __restrict__ beta,
              __half* __restrict__ outH) {
    const int warp = threadIdx.x >> 5, lane = threadIdx.x & 31;
    const int row = blockIdx.x * 8 + warp;
    const __half2* pa = reinterpret_cast<const __half2*>(aH + (size_t)row * DM);
    const __half2* pr = reinterpret_cast<const __half2*>(rH + (size_t)row * DM);
    const float4* pg = reinterpret_cast<const float4*>(g);
    const float4* pb = reinterpret_cast<const float4*>(beta);

    float4 v[6];
    float sum = 0.f;
    #pragma unroll
    for (int ch = 0; ch < 6; ch++) {
        int e2 = (lane + 32 * ch) * 2;
        float2 a0 = __half22float2(pa[e2]);
        float2 a1 = __half22float2(pa[e2 + 1]);
        float2 r0 = __half22float2(pr[e2]);
        float2 r1 = __half22float2(pr[e2 + 1]);
        v[ch] = make_float4(a0.x + r0.x, a0.y + r0.y, a1.x + r1.x, a1.y + r1.y);
        sum += v[ch].x + v[ch].y + v[ch].z + v[ch].w;
    }
    #pragma unroll
    for (int o = 16; o > 0; o >>= 1) sum += __shfl_xor_sync(0xffffffffu, sum, o);
    float mu = sum * (1.0f / DM);

    float var = 0.f;
    #pragma unroll
    for (int ch = 0; ch < 6; ch++) {
        float dx = v[ch].x - mu, dy = v[ch].y - mu, dz = v[ch].z - mu, dw = v[ch].w - mu;
        var += dx * dx + dy * dy + dz * dz + dw * dw;
    }
    #pragma unroll
    for (int o = 16; o > 0; o >>= 1) var += __shfl_xor_sync(0xffffffffu, var, o);
    float rstd = rsqrtf(var * (1.0f / DM) + 1e-5f);

    #pragma unroll
    for (int ch = 0; ch < 6; ch++) {
        float4 gg = pg[lane + 32 * ch];
        float4 bb = pb[lane + 32 * ch];
        float4 y;
        y.x = (v[ch].x - mu) * rstd * gg.x + bb.x;
        y.y = (v[ch].y - mu) * rstd * gg.y + bb.y;
        y.z = (v[ch].z - mu) * rstd * gg.z + bb.z;
        y.w = (v[ch].w - mu) * rstd * gg.w + bb.w;
        size_t o4 = (size_t)row * DM + (lane + 32 * ch) * 4;
        reinterpret_cast<__half2*>(outH + o4)[0] = __half2(__float2half(y.x), __float2half(y.y));
        reinterpret_cast<__half2*>(outH + o4)[1] = __half2(__float2half(y.z), __float2half(y.w));
    }
}

// ===== LN2: out = LN(p0+p1+p2 + bias2 + x1h) =====
__global__ void __launch_bounds__(256)
add_ln3_kernel(const __half* __restrict__ p,
               const __half* __restrict__ rH,
               const float* __restrict__ bias2,
               const float* __restrict__ g,
               const float* __restrict__ beta,
               float* __restrict__ out) {
    const int warp = threadIdx.x >> 5, lane = threadIdx.x & 31;
    const int row = blockIdx.x * 8 + warp;
    const __half2* p0 = reinterpret_cast<const __half2*>(p + (size_t)row * DM);
    const __half2* p1 = reinterpret_cast<const __half2*>(p + (size_t)row * DM + MD);
    const __half2* p2 = reinterpret_cast<const __half2*>(p + (size_t)row * DM + 2 * (size_t)MD);
    const __half2* pr = reinterpret_cast<const __half2*>(rH + (size_t)row * DM);
    const float4* pb2 = reinterpret_cast<const float4*>(bias2);
    const float4* pg = reinterpret_cast<const float4*>(g);
    const float4* pb = reinterpret_cast<const float4*>(beta);

    float4 v[6];
    float sum = 0.f;
    #pragma unroll
    for (int ch = 0; ch < 6; ch++) {
        int e2 = (lane + 32 * ch) * 2;
        float2 a0 = __half22float2(p0[e2]),  a0b = __half22float2(p0[e2 + 1]);
        float2 a1 = __half22float2(p1[e2]),  a1b = __half22float2(p1[e2 + 1]);
        float2 a2 = __half22float2(p2[e2]),  a2b = __half22float2(p2[e2 + 1]);
        float2 rr = __half22float2(pr[e2]),  rrb = __half22float2(pr[e2 + 1]);
        float4 b2 = pb2[lane + 32 * ch];
        v[ch] = make_float4(a0.x + a1.x + a2.x + b2.x + rr.x,
                            a0.y + a1.y + a2.y + b2.y + rr.y,
                            a0b.x + a1b.x + a2b.x + b2.z + rrb.x,
                            a0b.y + a1b.y + a2b.y + b2.w + rrb.y);
        sum += v[ch].x + v[ch].y + v[ch].z + v[ch].w;
    }
    #pragma unroll
    for (int o = 16; o > 0; o >>= 1) sum += __shfl_xor_sync(0xffffffffu, sum, o);
    float mu = sum * (1.0f / DM);

    float var = 0.f;
    #pragma unroll
    for (int ch = 0; ch < 6; ch++) {
        float dx = v[ch].x - mu, dy = v[ch].y - mu, dz = v[ch].z - mu, dw = v[ch].w - mu;
        var += dx * dx + dy * dy + dz * dz + dw * dw;
    }
    #pragma unroll
    for (int o = 16; o > 0; o >>= 1) var += __shfl_xor_sync(0xffffffffu, var, o);
    float rstd = rsqrtf(var * (1.0f / DM) + 1e-5f);

    float4* po = reinterpret_cast<float4*>(out + (size_t)row * DM);
    #pragma unroll
    for (int ch = 0; ch < 6; ch++) {
        float4 gg = pg[lane + 32 * ch];
        float4 bb = pb[lane + 32 * ch];
        float4 y;
        y.x = (v[ch].x - mu) * rstd * gg.x + bb.x;
        y.y = (v[ch].y - mu) * rstd * gg.y + bb.y;
        y.z = (v[ch].z - mu) * rstd * gg.z + bb.z;
        y.w = (v[ch].w - mu) * rstd * gg.w + bb.w;
        po[lane + 32 * ch] = y;
    }
}

// ================= launch =================
extern "C" void kernel_launch(void* const* d_in, const int* in_sizes, int n_in,
                              void* d_out, int out_size) {
    const float* x     = (const float*)d_in[0];
    const float* Wq    = (const float*)d_in[1];
    const float* bq    = (const float*)d_in[2];
    const float* Wk    = (const float*)d_in[3];
    const float* bk    = (const float*)d_in[4];
    const float* Wv    = (const float*)d_in[5];
    const float* bv    = (const float*)d_in[6];
    const float* ln1_g = (const float*)d_in[7];
    const float* ln1_b = (const float*)d_in[8];
    const float* W1    = (const float*)d_in[9];
    const float* b1    = (const float*)d_in[10];
    const float* W2    = (const float*)d_in[11];
    const float* b2    = (const float*)d_in[12];
    const float* ln2_g = (const float*)d_in[13];
    const float* ln2_b = (const float*)d_in[14];
    float* out = (float*)d_out;

    float *bqkv;
    __half *attn, *q, *kv, *xh, *x1h, *hid, *ffp, *wqkv, *w1, *w2;
    cudaGetSymbolAddress((void**)&attn, g_attn);
    cudaGetSymbolAddress((void**)&bqkv, g_bqkv);
    cudaGetSymbolAddress((void**)&q, g_q);
    cudaGetSymbolAddress((void**)&kv, g_kv);
    cudaGetSymbolAddress((void**)&xh, g_xh);
    cudaGetSymbolAddress((void**)&x1h, g_x1h);
    cudaGetSymbolAddress((void**)&hid, g_hid);
    cudaGetSymbolAddress((void**)&ffp, g_ffp);
    cudaGetSymbolAddress((void**)&wqkv, g_wqkv);
    cudaGetSymbolAddress((void**)&w1, g_w1);     cudaGetSymbolAddress((void**)&w2, g_w2);

    const int SMEM_F = 3 * 2 * 16384;   // 1-term, 3 stages = 96KB
    cudaFuncSetAttribute((const void*)tc_gemm<1,3>, cudaFuncAttributeMaxDynamicSharedMemorySize, SMEM_F);
    cudaFuncSetAttribute(attn_kernel, cudaFuncAttributeMaxDynamicSharedMemorySize, ATTN_SMEM);

    // ---- merged prep ----
    prep_all<<<12489, 256>>>(x, Wq, Wk, Wv, W1, W2, bq, bk, bv,
                             wqkv, w1, w2, bqkv, xh);

    // ---- fused QKV projection (1-term) ----
    {
        dim3 grid(QKVN / 128, MROWS / 128);
        tc_gemm<1,3><<<grid, 256, SMEM_F>>>(xh, nullptr, wqkv, bqkv, (float*)kv,
                                            q, MROWS, QKVN, DM, 2);
    }

    // ---- attention (3 CTAs/SM, pipelined loads) ----
    {
        dim3 grid(NC, NH, BB);
        attn_kernel<<<grid, 128, ATTN_SMEM>>>(q, kv, attn);
    }

    // ---- x1 = LN(attn + x_fp16), fp16 ----
    add_ln_kernel<<<MROWS / 8, 256>>>(attn, xh, ln1_g, ln1_b, x1h);

    // ---- FFN (1-term) ----
    {
        dim3 grid1(FF / 128, MROWS / 128);
        tc_gemm<1,3><<<grid1, 256, SMEM_F>>>(x1h, nullptr, w1, b1, nullptr,
                                             hid, MROWS, FF, DM, 1);
        dim3 grid2(DM / 128, MROWS / 128, 3);
        tc_gemm<1,3><<<grid2, 256, SMEM_F>>>(hid, nullptr, w2, nullptr, nullptr,
                                             ffp, MROWS, DM, FF, 3);
    }

    // ---- out = LN(p0+p1+p2 + b2 + x1) ----
    add_ln3_kernel<<<MROWS / 8, 256>>>(ffp, x1h, b2, ln2_g, ln2_b, out);
}